// round 7
// baseline (speedup 1.0000x reference)
#include <cuda_runtime.h>
#include <math.h>

#define BB 32
#define EE 512
#define HH 1024
#define VV 32000
#define TT 64
#define START_TOK 1
#define F32_TINY 1.17549435e-38f
#define KC 32
#define TILEV 128
#define KTOT 1536
#define SPLITK 4
#define KSEG (KTOT / SPLITK)     // 384
#define NCHUNK_LSTM (KSEG / KC)  // 12
#define WS_STRIDE 36
// logits config
#define LTILEV 256
#define NCHUNK_LOG (HH / KC)     // 32

// ---------------- device scratch ----------------
__device__ __align__(16) float g_hA[HH * BB];   // [k][b]
__device__ __align__(16) float g_hB[HH * BB];
__device__ __align__(16) float g_cA[HH * BB];
__device__ __align__(16) float g_cB[HH * BB];
__device__ __align__(16) float g_xh[KTOT * BB]; // [k][b]
__device__ __align__(16) float g_gpart[SPLITK * 4 * HH * BB];
__device__ unsigned long long g_best[TT * BB];
__device__ __align__(16) float g_stage[(size_t)BB * TT * VV]; // [b][t][v]

// ---------------- f32x2 packed math ----------------
__device__ __forceinline__ unsigned long long pack2(float lo, float hi) {
    unsigned long long r;
    asm("mov.b64 %0, {%1, %2};" : "=l"(r) : "f"(lo), "f"(hi));
    return r;
}
__device__ __forceinline__ void unpack2(unsigned long long v, float& lo, float& hi) {
    asm("mov.b64 {%0, %1}, %2;" : "=f"(lo), "=f"(hi) : "l"(v));
}
__device__ __forceinline__ unsigned long long fma2(unsigned long long a,
                                                   unsigned long long b,
                                                   unsigned long long c) {
    unsigned long long d;
    asm("fma.rn.f32x2 %0, %1, %2, %3;" : "=l"(d) : "l"(a), "l"(b), "l"(c));
    return d;
}

// ---------------- threefry2x32 (JAX-compatible) ----------------
__device__ __forceinline__ void threefry2x32_dev(unsigned k0, unsigned k1,
                                                 unsigned x0, unsigned x1,
                                                 unsigned& o0, unsigned& o1) {
    unsigned ks2 = k0 ^ k1 ^ 0x1BD11BDAu;
    x0 += k0; x1 += k1;
#define TF_RND(r) { x0 += x1; x1 = __funnelshift_l(x1, x1, r); x1 ^= x0; }
    TF_RND(13) TF_RND(15) TF_RND(26) TF_RND(6)  x0 += k1;  x1 += ks2 + 1u;
    TF_RND(17) TF_RND(29) TF_RND(16) TF_RND(24) x0 += ks2; x1 += k0 + 2u;
    TF_RND(13) TF_RND(15) TF_RND(26) TF_RND(6)  x0 += k0;  x1 += k1 + 3u;
    TF_RND(17) TF_RND(29) TF_RND(16) TF_RND(24) x0 += k1;  x1 += ks2 + 4u;
    TF_RND(13) TF_RND(15) TF_RND(26) TF_RND(6)  x0 += ks2; x1 += k0 + 5u;
#undef TF_RND
    o0 = x0; o1 = x1;
}

__device__ __forceinline__ unsigned ford(float f) {
    unsigned u = __float_as_uint(f);
    return (u & 0x80000000u) ? ~u : (u | 0x80000000u);
}
__device__ __forceinline__ unsigned long long u64max(unsigned long long a,
                                                     unsigned long long b) {
    return a > b ? a : b;
}
__device__ __forceinline__ int decode_tok(unsigned long long key) {
    return (int)(0xFFFFFFFFu - (unsigned)(key & 0xFFFFFFFFull));
}

// ---------------- cp.async helpers ----------------
__device__ __forceinline__ void cp_async16(unsigned dst, const void* src) {
    asm volatile("cp.async.cg.shared.global [%0], [%1], 16;"
                 :: "r"(dst), "l"(src) : "memory");
}
__device__ __forceinline__ void cp_commit() {
    asm volatile("cp.async.commit_group;" ::: "memory");
}

// ---------------- K0: h0/c0 from condition ----------------
__global__ __launch_bounds__(256) void init_kernel(
    const float* __restrict__ cond, const float* __restrict__ Wh,
    const float* __restrict__ bh,   const float* __restrict__ Wc,
    const float* __restrict__ bc,
    float* __restrict__ hout, float* __restrict__ cout) {
    int j = blockIdx.x * 8 + (threadIdx.x >> 5);
    int lane = threadIdx.x & 31;
    if (blockIdx.x < 8) {
        int idx = blockIdx.x * 256 + threadIdx.x;
        if (idx < TT * BB) g_best[idx] = 0ull;
    }
    const float* cr = cond + (size_t)lane * EE;
    const float* wh = Wh + (size_t)j * EE;
    const float* wc = Wc + (size_t)j * EE;
    float ah = bh[j], ac = bc[j];
#pragma unroll 4
    for (int k = 0; k < EE; k += 4) {
        float4 c4 = *(const float4*)(cr + k);
        float4 h4 = *(const float4*)(wh + k);
        float4 q4 = *(const float4*)(wc + k);
        ah = fmaf(c4.x, h4.x, ah); ah = fmaf(c4.y, h4.y, ah);
        ah = fmaf(c4.z, h4.z, ah); ah = fmaf(c4.w, h4.w, ah);
        ac = fmaf(c4.x, q4.x, ac); ac = fmaf(c4.y, q4.y, ac);
        ac = fmaf(c4.z, q4.z, ac); ac = fmaf(c4.w, q4.w, ac);
    }
    hout[j * BB + lane] = ah;
    cout[j * BB + lane] = ac;
}

// ---------------- K-gather: build xh[k][b] = [embed(tok); h] ----------------
__global__ __launch_bounds__(256) void gather_kernel(
    const float* __restrict__ embed, const float* __restrict__ hin, int t) {
    int idx = blockIdx.x * 256 + threadIdx.x;
    int b = idx & 31;
    int k = idx >> 5;
    float val;
    if (k < EE) {
        int tok = START_TOK;
        if (t > 0) tok = decode_tok(g_best[(t - 1) * BB + b]);
        val = embed[(size_t)tok * EE + k];
    } else {
        val = hin[(k - EE) * BB + b];
    }
    g_xh[k * BB + b] = val;
}

// ---------------- K1a: lstm gate GEMM (split-K) ----------------
__global__ __launch_bounds__(256) void lstm_gemm_kernel(
    const float* __restrict__ Wih, const float* __restrict__ Whh) {
    __shared__ __align__(16) float Ws[2][TILEV][WS_STRIDE];
    __shared__ __align__(16) float xs[2][KC][BB];
    int tid = threadIdx.x;
    int rt = tid & 31;
    int bt = tid >> 5;
    int m0 = blockIdx.x * TILEV;
    int seg = blockIdx.y;
    int k0seg = seg * KSEG;

    int srow = tid >> 1;
    int sko = (tid & 1) * 16;
    unsigned wdst0 = (unsigned)__cvta_generic_to_shared(&Ws[0][srow][sko]);
    unsigned wdst1 = (unsigned)__cvta_generic_to_shared(&Ws[1][srow][sko]);
    unsigned xdst0 = (unsigned)__cvta_generic_to_shared(&xs[0][0][0]) + tid * 16;
    unsigned xdst1 = (unsigned)__cvta_generic_to_shared(&xs[1][0][0]) + tid * 16;

    auto do_stage = [&](int buf, int c) {
        int kk = k0seg + c * KC;
        const float* wsrc;
        if (kk < EE) wsrc = Wih + (size_t)(m0 + srow) * EE + kk + sko;
        else         wsrc = Whh + (size_t)(m0 + srow) * HH + (kk - EE) + sko;
        unsigned wd = buf ? wdst1 : wdst0;
#pragma unroll
        for (int ch = 0; ch < 4; ch++)
            cp_async16(wd + ch * 16, wsrc + ch * 4);
        cp_async16(buf ? xdst1 : xdst0, g_xh + (size_t)kk * BB + tid * 4);
        cp_commit();
    };

    do_stage(0, 0);
    do_stage(1, 1);

    unsigned long long acc[4][2];
#pragma unroll
    for (int rj = 0; rj < 4; rj++) { acc[rj][0] = 0ull; acc[rj][1] = 0ull; }

    for (int c = 0; c < NCHUNK_LSTM; c++) {
        if (c == NCHUNK_LSTM - 1)
            asm volatile("cp.async.wait_group 0;" ::: "memory");
        else
            asm volatile("cp.async.wait_group 1;" ::: "memory");
        __syncthreads();
        int buf = c & 1;
#pragma unroll
        for (int k4 = 0; k4 < KC / 4; k4++) {
            unsigned long long h01[4], h23[4];
#pragma unroll
            for (int i = 0; i < 4; i++) {
                float4 h4 = *(const float4*)&xs[buf][k4 * 4 + i][bt * 4];
                h01[i] = pack2(h4.x, h4.y);
                h23[i] = pack2(h4.z, h4.w);
            }
#pragma unroll
            for (int rj = 0; rj < 4; rj++) {
                float4 w4 = *(const float4*)&Ws[buf][rt + 32 * rj][k4 * 4];
                unsigned long long w;
                w = pack2(w4.x, w4.x);
                acc[rj][0] = fma2(w, h01[0], acc[rj][0]);
                acc[rj][1] = fma2(w, h23[0], acc[rj][1]);
                w = pack2(w4.y, w4.y);
                acc[rj][0] = fma2(w, h01[1], acc[rj][0]);
                acc[rj][1] = fma2(w, h23[1], acc[rj][1]);
                w = pack2(w4.z, w4.z);
                acc[rj][0] = fma2(w, h01[2], acc[rj][0]);
                acc[rj][1] = fma2(w, h23[2], acc[rj][1]);
                w = pack2(w4.w, w4.w);
                acc[rj][0] = fma2(w, h01[3], acc[rj][0]);
                acc[rj][1] = fma2(w, h23[3], acc[rj][1]);
            }
        }
        __syncthreads();
        if (c + 2 < NCHUNK_LSTM) do_stage(buf, c + 2);
    }

    float* part = g_gpart + (size_t)seg * 4 * HH * BB;
#pragma unroll
    for (int rj = 0; rj < 4; rj++) {
        int r = m0 + rt + 32 * rj;
        float p[4];
        unpack2(acc[rj][0], p[0], p[1]);
        unpack2(acc[rj][1], p[2], p[3]);
#pragma unroll
        for (int bi = 0; bi < 4; bi++)
            part[(size_t)r * BB + bt * 4 + bi] = p[bi];
    }
}

// ---------------- K1b: combine partials + cell ----------------
__global__ __launch_bounds__(256) void cell_kernel(
    const float* __restrict__ bih, const float* __restrict__ bhh,
    const float* __restrict__ cin,
    float* __restrict__ hout, float* __restrict__ cout) {
    int idx = blockIdx.x * 256 + threadIdx.x;
    int b = idx & 31;
    int j = idx >> 5;
    float a[4] = {0.f, 0.f, 0.f, 0.f};
#pragma unroll
    for (int seg = 0; seg < SPLITK; seg++) {
        const float* part = g_gpart + (size_t)seg * 4 * HH * BB;
#pragma unroll
        for (int gate = 0; gate < 4; gate++)
            a[gate] += part[(size_t)(gate * HH + j) * BB + b];
    }
#pragma unroll
    for (int gate = 0; gate < 4; gate++) {
        int r = gate * HH + j;
        a[gate] += bih[r] + bhh[r];
    }
    float ig = 1.0f / (1.0f + expf(-a[0]));
    float fg = 1.0f / (1.0f + expf(-a[1]));
    float gg = tanhf(a[2]);
    float og = 1.0f / (1.0f + expf(-a[3]));
    float c = fg * cin[j * BB + b] + ig * gg;
    float h = og * tanhf(c);
    cout[j * BB + b] = c;
    hout[j * BB + b] = h;
}

// ---------------- K2: logits GEMM (8v x 8b tiles) + gumbel + argmax -------
// 128 threads = 4 warps. vt = lane (32 v-rows), bt = warp (8 b's each).
// Thread tile: 8 v (v = v0 + vt + 32*vj) x 8 b. h loads are warp-uniform
// (broadcast, ~free crossbar). Single wave: grid 125.
__global__ __launch_bounds__(128) void logits_kernel(
    const float* __restrict__ hT, const float* __restrict__ Wout,
    const float* __restrict__ bout, float* __restrict__ stage,
    unsigned long long* __restrict__ best, int t, unsigned key0, unsigned key1) {
    extern __shared__ __align__(16) char dsm[];
    float* Ws = (float*)dsm;                          // [2][256][36]
    float* hs = (float*)(dsm + 2 * LTILEV * WS_STRIDE * 4); // [2][32][32]
    int tid = threadIdx.x;
    int vt = tid & 31;
    int bt = tid >> 5;          // warp id -> b group (8 b's)
    int v0 = blockIdx.x * LTILEV;

    unsigned wsm = (unsigned)__cvta_generic_to_shared(Ws);
    unsigned hsm = (unsigned)__cvta_generic_to_shared(hs);

    auto do_stage = [&](int buf, int c) {
        int kc = c * KC;
        unsigned wb = wsm + buf * (LTILEV * WS_STRIDE * 4);
#pragma unroll
        for (int i = 0; i < 16; i++) {
            int gi = tid + 128 * i;         // 0..2047
            int row = gi >> 3;
            int kg = gi & 7;
            cp_async16(wb + row * (WS_STRIDE * 4) + kg * 16,
                       Wout + (size_t)(v0 + row) * HH + kc + kg * 4);
        }
        unsigned hb = hsm + buf * 4096;
        cp_async16(hb + tid * 32,      hT + (size_t)kc * BB + tid * 8);
        cp_async16(hb + tid * 32 + 16, hT + (size_t)kc * BB + tid * 8 + 4);
        cp_commit();
    };

    do_stage(0, 0);
    do_stage(1, 1);

    unsigned long long acc[8][4];
#pragma unroll
    for (int vj = 0; vj < 8; vj++)
#pragma unroll
        for (int p = 0; p < 4; p++) acc[vj][p] = 0ull;

    for (int c = 0; c < NCHUNK_LOG; c++) {
        if (c == NCHUNK_LOG - 1)
            asm volatile("cp.async.wait_group 0;" ::: "memory");
        else
            asm volatile("cp.async.wait_group 1;" ::: "memory");
        __syncthreads();
        int buf = c & 1;
        const float* wsb = Ws + buf * (LTILEV * WS_STRIDE);
        const float* hsb = hs + buf * (KC * BB);
#pragma unroll
        for (int k4 = 0; k4 < KC / 4; k4++) {
            unsigned long long hp[4][4];
#pragma unroll
            for (int k = 0; k < 4; k++) {
                float4 a = *(const float4*)&hsb[(k4 * 4 + k) * BB + bt * 8];
                float4 b2 = *(const float4*)&hsb[(k4 * 4 + k) * BB + bt * 8 + 4];
                hp[k][0] = pack2(a.x, a.y);
                hp[k][1] = pack2(a.z, a.w);
                hp[k][2] = pack2(b2.x, b2.y);
                hp[k][3] = pack2(b2.z, b2.w);
            }
#pragma unroll
            for (int vj = 0; vj < 8; vj++) {
                float4 w4 = *(const float4*)&wsb[(vt + 32 * vj) * WS_STRIDE + k4 * 4];
                unsigned long long ww;
                ww = pack2(w4.x, w4.x);
                acc[vj][0] = fma2(ww, hp[0][0], acc[vj][0]);
                acc[vj][1] = fma2(ww, hp[0][1], acc[vj][1]);
                acc[vj][2] = fma2(ww, hp[0][2], acc[vj][2]);
                acc[vj][3] = fma2(ww, hp[0][3], acc[vj][3]);
                ww = pack2(w4.y, w4.y);
                acc[vj][0] = fma2(ww, hp[1][0], acc[vj][0]);
                acc[vj][1] = fma2(ww, hp[1][1], acc[vj][1]);
                acc[vj][2] = fma2(ww, hp[1][2], acc[vj][2]);
                acc[vj][3] = fma2(ww, hp[1][3], acc[vj][3]);
                ww = pack2(w4.z, w4.z);
                acc[vj][0] = fma2(ww, hp[2][0], acc[vj][0]);
                acc[vj][1] = fma2(ww, hp[2][1], acc[vj][1]);
                acc[vj][2] = fma2(ww, hp[2][2], acc[vj][2]);
                acc[vj][3] = fma2(ww, hp[2][3], acc[vj][3]);
                ww = pack2(w4.w, w4.w);
                acc[vj][0] = fma2(ww, hp[3][0], acc[vj][0]);
                acc[vj][1] = fma2(ww, hp[3][1], acc[vj][1]);
                acc[vj][2] = fma2(ww, hp[3][2], acc[vj][2]);
                acc[vj][3] = fma2(ww, hp[3][3], acc[vj][3]);
            }
        }
        __syncthreads();
        if (c + 2 < NCHUNK_LOG) do_stage(buf, c + 2);
    }

    // epilogue: bias, stage store [b][t][v], gumbel, per-b argmax
    unsigned long long bk[8];
#pragma unroll
    for (int bi = 0; bi < 8; bi++) bk[bi] = 0ull;
#pragma unroll
    for (int vj = 0; vj < 8; vj++) {
        int v = v0 + vt + 32 * vj;
        float bo = bout[v];
        float lg[8];
        unpack2(acc[vj][0], lg[0], lg[1]);
        unpack2(acc[vj][1], lg[2], lg[3]);
        unpack2(acc[vj][2], lg[4], lg[5]);
        unpack2(acc[vj][3], lg[6], lg[7]);
#pragma unroll
        for (int bi = 0; bi < 8; bi++) {
            int b = bt * 8 + bi;
            float logit = lg[bi] + bo;
            stage[((size_t)b * TT + t) * VV + v] = logit;
            unsigned o0, o1;
            threefry2x32_dev(key0, key1, 0u, (unsigned)(b * VV + v), o0, o1);
            unsigned bits = o0 ^ o1;
            float u = __uint_as_float(0x3f800000u | (bits >> 9)) - 1.0f;
            u = fmaxf(u + F32_TINY, F32_TINY);
            float g = -logf(-logf(u));
            float val = logit + g;
            unsigned long long key =
                ((unsigned long long)ford(val) << 32) |
                (unsigned long long)(0xFFFFFFFFu - (unsigned)v);
            bk[bi] = u64max(bk[bi], key);
        }
    }
#pragma unroll
    for (int off = 1; off < 32; off <<= 1)
#pragma unroll
        for (int bi = 0; bi < 8; bi++)
            bk[bi] = u64max(bk[bi], __shfl_xor_sync(0xffffffffu, bk[bi], off));
    if (vt == 0) {
#pragma unroll
        for (int bi = 0; bi < 8; bi++)
            atomicMax(&best[t * BB + bt * 8 + bi], bk[bi]);
    }
}

// ---------------- final: captions ----------------
__global__ void caption_kernel(float* __restrict__ cap_f, int* __restrict__ cap_i) {
    int idx = blockIdx.x * 256 + threadIdx.x;
    int tt = idx & 63;
    int b = idx >> 6;
    int v = decode_tok(g_best[tt * BB + b]);
    if (cap_f) cap_f[b * TT + tt] = (float)v;
    if (cap_i) cap_i[b * TT + tt] = v;
}

// ---------------- final: transpose [b][t][v] -> [b][v][t] ----------------
__global__ __launch_bounds__(256) void transpose_kernel(
    const float* __restrict__ stage, float* __restrict__ out) {
    __shared__ float tile[128][65];
    int b = blockIdx.x / 250;
    int vc = blockIdx.x % 250;
    int v0 = vc * 128;
    const float* src = stage + (size_t)b * TT * VV + v0;
#pragma unroll
    for (int l = 0; l < 32; l++) {
        int e = threadIdx.x + l * 256;
        int tt = e >> 7;
        int vi = e & 127;
        tile[vi][tt] = src[(size_t)tt * VV + vi];
    }
    __syncthreads();
    float* dst = out + ((size_t)b * VV + v0) * TT;
#pragma unroll
    for (int l = 0; l < 32; l++) {
        int e = threadIdx.x + l * 256;
        int vi = e >> 6;
        int tt = e & 63;
        dst[(size_t)vi * TT + tt] = tile[vi][tt];
    }
}

// ---------------- host threefry ----------------
static void host_threefry(unsigned k0, unsigned k1, unsigned x0, unsigned x1,
                          unsigned& o0, unsigned& o1) {
    unsigned ks2 = k0 ^ k1 ^ 0x1BD11BDAu;
    x0 += k0; x1 += k1;
#define HTF_RND(r) { x0 += x1; x1 = (x1 << r) | (x1 >> (32 - r)); x1 ^= x0; }
    HTF_RND(13) HTF_RND(15) HTF_RND(26) HTF_RND(6)  x0 += k1;  x1 += ks2 + 1u;
    HTF_RND(17) HTF_RND(29) HTF_RND(16) HTF_RND(24) x0 += ks2; x1 += k0 + 2u;
    HTF_RND(13) HTF_RND(15) HTF_RND(26) HTF_RND(6)  x0 += k0;  x1 += k1 + 3u;
    HTF_RND(17) HTF_RND(29) HTF_RND(16) HTF_RND(24) x0 += k1;  x1 += ks2 + 4u;
    HTF_RND(13) HTF_RND(15) HTF_RND(26) HTF_RND(6)  x0 += ks2; x1 += k0 + 5u;
#undef HTF_RND
    o0 = x0; o1 = x1;
}

extern "C" void kernel_launch(void* const* d_in, const int* in_sizes, int n_in,
                              void* d_out, int out_size) {
    const float* condition = (const float*)d_in[0];
    const float* Wh    = (const float*)d_in[1];
    const float* bh    = (const float*)d_in[2];
    const float* Wc    = (const float*)d_in[3];
    const float* bc    = (const float*)d_in[4];
    const float* embed = (const float*)d_in[5];
    const float* Wih   = (const float*)d_in[6];
    const float* bih   = (const float*)d_in[7];
    const float* Whh   = (const float*)d_in[8];
    const float* bhh   = (const float*)d_in[9];
    const float* Wout  = (const float*)d_in[10];
    const float* bout  = (const float*)d_in[11];

    float *hA, *hB, *cA, *cB, *stage;
    unsigned long long* best;
    cudaGetSymbolAddress((void**)&hA, g_hA);
    cudaGetSymbolAddress((void**)&hB, g_hB);
    cudaGetSymbolAddress((void**)&cA, g_cA);
    cudaGetSymbolAddress((void**)&cB, g_cB);
    cudaGetSymbolAddress((void**)&stage, g_stage);
    cudaGetSymbolAddress((void**)&best, g_best);

    const long long n_cap = (long long)BB * TT;
    const long long n_log = (long long)BB * VV * TT;
    float* cap_f = nullptr;
    int*   cap_i = nullptr;
    float* log_out = nullptr;
    long long osz = (long long)out_size;
    if (osz == n_cap + n_log) {
        cap_f = (float*)d_out;
        log_out = (float*)d_out + n_cap;
    } else if (osz == n_log) {
        log_out = (float*)d_out;
    } else if (osz == n_cap) {
        cap_i = (int*)d_out;
    } else {
        cap_f = (float*)d_out;
        log_out = (float*)d_out + n_cap;
    }

    const int lsm = 2 * LTILEV * WS_STRIDE * 4 + 2 * KC * BB * 4; // 81920
    cudaFuncSetAttribute(logits_kernel,
                         cudaFuncAttributeMaxDynamicSharedMemorySize, lsm);

    init_kernel<<<128, 256>>>(condition, Wh, bh, Wc, bc, hA, cA);

    float *hcur = hA, *hnxt = hB, *ccur = cA, *cnxt = cB;
    for (int t = 0; t < TT; t++) {
        gather_kernel<<<192, 256>>>(embed, hcur, t);
        dim3 ggrid(HH * 4 / TILEV, SPLITK);
        lstm_gemm_kernel<<<ggrid, 256>>>(Wih, Whh);
        cell_kernel<<<128, 256>>>(bih, bhh, ccur, hnxt, cnxt);
        unsigned o0, o1;
        host_threefry(0u, 42u, 0u, (unsigned)t, o0, o1);
        logits_kernel<<<VV / LTILEV, 128, lsm>>>(hnxt, Wout, bout,
                                                 stage, best, t, o0, o1);
        float* tmp;
        tmp = hcur; hcur = hnxt; hnxt = tmp;
        tmp = ccur; ccur = cnxt; cnxt = tmp;
    }
    caption_kernel<<<8, 256>>>(cap_f, cap_i);
    if (log_out) transpose_kernel<<<8000, 256>>>(stage, log_out);
}

// round 8
// speedup vs baseline: 1.1162x; 1.1162x over previous
#include <cuda_runtime.h>
#include <math.h>

#define BB 32
#define EE 512
#define HH 1024
#define VV 32000
#define TT 64
#define START_TOK 1
#define F32_TINY 1.17549435e-38f
#define KC 32
#define TILEV 128
#define KTOT 1536
#define SPLITK 4
#define KSEG (KTOT / SPLITK)     // 384
#define NCHUNK_LSTM (KSEG / KC)  // 12
#define WS_STRIDE 36
// logits config
#define LTILEV 256
#define NCHUNK_LOG (HH / KC)     // 32
#define LW_FLOATS (LTILEV * WS_STRIDE)       // 9216 floats per buffer
#define LSMEM_W (2 * LW_FLOATS * 4)          // 73728
#define LSMEM_H (2 * KC * BB * 4)            // 8192
#define LSMEM_TOTAL (LSMEM_W + LSMEM_H + 4096) // + parts = 86016

// ---------------- device scratch ----------------
__device__ __align__(16) float g_hA[HH * BB];   // [k][b]
__device__ __align__(16) float g_hB[HH * BB];
__device__ __align__(16) float g_cA[HH * BB];
__device__ __align__(16) float g_cB[HH * BB];
__device__ __align__(16) float g_xh[KTOT * BB]; // [k][b]
__device__ __align__(16) float g_gpart[SPLITK * 4 * HH * BB];
__device__ unsigned long long g_best[TT * BB];
__device__ __align__(16) float g_stage[(size_t)BB * TT * VV]; // [b][t][v]

// ---------------- f32x2 packed math ----------------
__device__ __forceinline__ unsigned long long pack2(float lo, float hi) {
    unsigned long long r;
    asm("mov.b64 %0, {%1, %2};" : "=l"(r) : "f"(lo), "f"(hi));
    return r;
}
__device__ __forceinline__ void unpack2(unsigned long long v, float& lo, float& hi) {
    asm("mov.b64 {%0, %1}, %2;" : "=f"(lo), "=f"(hi) : "l"(v));
}
__device__ __forceinline__ unsigned long long fma2(unsigned long long a,
                                                   unsigned long long b,
                                                   unsigned long long c) {
    unsigned long long d;
    asm("fma.rn.f32x2 %0, %1, %2, %3;" : "=l"(d) : "l"(a), "l"(b), "l"(c));
    return d;
}

// ---------------- threefry2x32 (JAX-compatible) ----------------
__device__ __forceinline__ void threefry2x32_dev(unsigned k0, unsigned k1,
                                                 unsigned x0, unsigned x1,
                                                 unsigned& o0, unsigned& o1) {
    unsigned ks2 = k0 ^ k1 ^ 0x1BD11BDAu;
    x0 += k0; x1 += k1;
#define TF_RND(r) { x0 += x1; x1 = __funnelshift_l(x1, x1, r); x1 ^= x0; }
    TF_RND(13) TF_RND(15) TF_RND(26) TF_RND(6)  x0 += k1;  x1 += ks2 + 1u;
    TF_RND(17) TF_RND(29) TF_RND(16) TF_RND(24) x0 += ks2; x1 += k0 + 2u;
    TF_RND(13) TF_RND(15) TF_RND(26) TF_RND(6)  x0 += k0;  x1 += k1 + 3u;
    TF_RND(17) TF_RND(29) TF_RND(16) TF_RND(24) x0 += k1;  x1 += ks2 + 4u;
    TF_RND(13) TF_RND(15) TF_RND(26) TF_RND(6)  x0 += ks2; x1 += k0 + 5u;
#undef TF_RND
    o0 = x0; o1 = x1;
}

__device__ __forceinline__ unsigned ford(float f) {
    unsigned u = __float_as_uint(f);
    return (u & 0x80000000u) ? ~u : (u | 0x80000000u);
}
__device__ __forceinline__ unsigned long long u64max(unsigned long long a,
                                                     unsigned long long b) {
    return a > b ? a : b;
}
__device__ __forceinline__ int decode_tok(unsigned long long key) {
    return (int)(0xFFFFFFFFu - (unsigned)(key & 0xFFFFFFFFull));
}

// ---------------- cp.async helpers ----------------
__device__ __forceinline__ void cp_async16(unsigned dst, const void* src) {
    asm volatile("cp.async.cg.shared.global [%0], [%1], 16;"
                 :: "r"(dst), "l"(src) : "memory");
}
__device__ __forceinline__ void cp_commit() {
    asm volatile("cp.async.commit_group;" ::: "memory");
}

// ---------------- K0: h0/c0 from condition ----------------
__global__ __launch_bounds__(256) void init_kernel(
    const float* __restrict__ cond, const float* __restrict__ Wh,
    const float* __restrict__ bh,   const float* __restrict__ Wc,
    const float* __restrict__ bc,
    float* __restrict__ hout, float* __restrict__ cout) {
    int j = blockIdx.x * 8 + (threadIdx.x >> 5);
    int lane = threadIdx.x & 31;
    if (blockIdx.x < 8) {
        int idx = blockIdx.x * 256 + threadIdx.x;
        if (idx < TT * BB) g_best[idx] = 0ull;
    }
    const float* cr = cond + (size_t)lane * EE;
    const float* wh = Wh + (size_t)j * EE;
    const float* wc = Wc + (size_t)j * EE;
    float ah = bh[j], ac = bc[j];
#pragma unroll 4
    for (int k = 0; k < EE; k += 4) {
        float4 c4 = *(const float4*)(cr + k);
        float4 h4 = *(const float4*)(wh + k);
        float4 q4 = *(const float4*)(wc + k);
        ah = fmaf(c4.x, h4.x, ah); ah = fmaf(c4.y, h4.y, ah);
        ah = fmaf(c4.z, h4.z, ah); ah = fmaf(c4.w, h4.w, ah);
        ac = fmaf(c4.x, q4.x, ac); ac = fmaf(c4.y, q4.y, ac);
        ac = fmaf(c4.z, q4.z, ac); ac = fmaf(c4.w, q4.w, ac);
    }
    hout[j * BB + lane] = ah;
    cout[j * BB + lane] = ac;
}

// ---------------- K-gather: build xh[k][b] = [embed(tok); h] ----------------
__global__ __launch_bounds__(256) void gather_kernel(
    const float* __restrict__ embed, const float* __restrict__ hin, int t) {
    int idx = blockIdx.x * 256 + threadIdx.x;
    int b = idx & 31;
    int k = idx >> 5;
    float val;
    if (k < EE) {
        int tok = START_TOK;
        if (t > 0) tok = decode_tok(g_best[(t - 1) * BB + b]);
        val = embed[(size_t)tok * EE + k];
    } else {
        val = hin[(k - EE) * BB + b];
    }
    g_xh[k * BB + b] = val;
}

// ---------------- K1a: lstm gate GEMM (split-K) ----------------
__global__ __launch_bounds__(256) void lstm_gemm_kernel(
    const float* __restrict__ Wih, const float* __restrict__ Whh) {
    __shared__ __align__(16) float Ws[2][TILEV][WS_STRIDE];
    __shared__ __align__(16) float xs[2][KC][BB];
    int tid = threadIdx.x;
    int rt = tid & 31;
    int bt = tid >> 5;
    int m0 = blockIdx.x * TILEV;
    int seg = blockIdx.y;
    int k0seg = seg * KSEG;

    int srow = tid >> 1;
    int sko = (tid & 1) * 16;
    unsigned wdst0 = (unsigned)__cvta_generic_to_shared(&Ws[0][srow][sko]);
    unsigned wdst1 = (unsigned)__cvta_generic_to_shared(&Ws[1][srow][sko]);
    unsigned xdst0 = (unsigned)__cvta_generic_to_shared(&xs[0][0][0]) + tid * 16;
    unsigned xdst1 = (unsigned)__cvta_generic_to_shared(&xs[1][0][0]) + tid * 16;

    auto do_stage = [&](int buf, int c) {
        int kk = k0seg + c * KC;
        const float* wsrc;
        if (kk < EE) wsrc = Wih + (size_t)(m0 + srow) * EE + kk + sko;
        else         wsrc = Whh + (size_t)(m0 + srow) * HH + (kk - EE) + sko;
        unsigned wd = buf ? wdst1 : wdst0;
#pragma unroll
        for (int ch = 0; ch < 4; ch++)
            cp_async16(wd + ch * 16, wsrc + ch * 4);
        cp_async16(buf ? xdst1 : xdst0, g_xh + (size_t)kk * BB + tid * 4);
        cp_commit();
    };

    do_stage(0, 0);
    do_stage(1, 1);

    unsigned long long acc[4][2];
#pragma unroll
    for (int rj = 0; rj < 4; rj++) { acc[rj][0] = 0ull; acc[rj][1] = 0ull; }

    for (int c = 0; c < NCHUNK_LSTM; c++) {
        if (c == NCHUNK_LSTM - 1)
            asm volatile("cp.async.wait_group 0;" ::: "memory");
        else
            asm volatile("cp.async.wait_group 1;" ::: "memory");
        __syncthreads();
        int buf = c & 1;
#pragma unroll
        for (int k4 = 0; k4 < KC / 4; k4++) {
            unsigned long long h01[4], h23[4];
#pragma unroll
            for (int i = 0; i < 4; i++) {
                float4 h4 = *(const float4*)&xs[buf][k4 * 4 + i][bt * 4];
                h01[i] = pack2(h4.x, h4.y);
                h23[i] = pack2(h4.z, h4.w);
            }
#pragma unroll
            for (int rj = 0; rj < 4; rj++) {
                float4 w4 = *(const float4*)&Ws[buf][rt + 32 * rj][k4 * 4];
                unsigned long long w;
                w = pack2(w4.x, w4.x);
                acc[rj][0] = fma2(w, h01[0], acc[rj][0]);
                acc[rj][1] = fma2(w, h23[0], acc[rj][1]);
                w = pack2(w4.y, w4.y);
                acc[rj][0] = fma2(w, h01[1], acc[rj][0]);
                acc[rj][1] = fma2(w, h23[1], acc[rj][1]);
                w = pack2(w4.z, w4.z);
                acc[rj][0] = fma2(w, h01[2], acc[rj][0]);
                acc[rj][1] = fma2(w, h23[2], acc[rj][1]);
                w = pack2(w4.w, w4.w);
                acc[rj][0] = fma2(w, h01[3], acc[rj][0]);
                acc[rj][1] = fma2(w, h23[3], acc[rj][1]);
            }
        }
        __syncthreads();
        if (c + 2 < NCHUNK_LSTM) do_stage(buf, c + 2);
    }

    float* part = g_gpart + (size_t)seg * 4 * HH * BB;
#pragma unroll
    for (int rj = 0; rj < 4; rj++) {
        int r = m0 + rt + 32 * rj;
        float p[4];
        unpack2(acc[rj][0], p[0], p[1]);
        unpack2(acc[rj][1], p[2], p[3]);
#pragma unroll
        for (int bi = 0; bi < 4; bi++)
            part[(size_t)r * BB + bt * 4 + bi] = p[bi];
    }
}

// ---------------- K1b: combine partials + cell ----------------
__global__ __launch_bounds__(256) void cell_kernel(
    const float* __restrict__ bih, const float* __restrict__ bhh,
    const float* __restrict__ cin,
    float* __restrict__ hout, float* __restrict__ cout) {
    int idx = blockIdx.x * 256 + threadIdx.x;
    int b = idx & 31;
    int j = idx >> 5;
    float a[4] = {0.f, 0.f, 0.f, 0.f};
#pragma unroll
    for (int seg = 0; seg < SPLITK; seg++) {
        const float* part = g_gpart + (size_t)seg * 4 * HH * BB;
#pragma unroll
        for (int gate = 0; gate < 4; gate++)
            a[gate] += part[(size_t)(gate * HH + j) * BB + b];
    }
#pragma unroll
    for (int gate = 0; gate < 4; gate++) {
        int r = gate * HH + j;
        a[gate] += bih[r] + bhh[r];
    }
    float ig = 1.0f / (1.0f + expf(-a[0]));
    float fg = 1.0f / (1.0f + expf(-a[1]));
    float gg = tanhf(a[2]);
    float og = 1.0f / (1.0f + expf(-a[3]));
    float c = fg * cin[j * BB + b] + ig * gg;
    float h = og * tanhf(c);
    cout[j * BB + b] = c;
    hout[j * BB + b] = h;
}

// ---------------- K2: logits GEMM, warp-owns-v layout ----------------
// 512 threads = 16 warps. Warp w owns v-rows [v0+w*16, +16). Lane = vp*4+bg:
// vp in 0..7 -> v-pair (vp*2, vp*2+1); bg in 0..3 -> 8 b's (bg*8..).
// Thread tile 2v x 8b (8 fma2 acc streams). W read once per block (4-lane
// dup is broadcast); h 4-way dup'd float4s. Grid 125 = one uniform wave.
__global__ __launch_bounds__(512) void logits_kernel(
    const float* __restrict__ hT, const float* __restrict__ Wout,
    const float* __restrict__ bout, float* __restrict__ stage,
    unsigned long long* __restrict__ best, int t, unsigned key0, unsigned key1) {
    extern __shared__ __align__(16) char dsm[];
    float* Ws = (float*)dsm;                        // [2][256][36]
    float* hs = (float*)(dsm + LSMEM_W);            // [2][32][32]
    unsigned long long* parts =
        (unsigned long long*)(dsm + LSMEM_W + LSMEM_H);  // [16][32]
    int tid = threadIdx.x;
    int lane = tid & 31;
    int w = tid >> 5;           // warp -> v group
    int bg = lane & 3;          // b group (8 b)
    int vp = lane >> 2;         // v pair within warp
    int v0 = blockIdx.x * LTILEV;

    unsigned wsm = (unsigned)__cvta_generic_to_shared(Ws);
    unsigned hsm = (unsigned)__cvta_generic_to_shared(hs);

    auto do_stage = [&](int buf, int c) {
        int kc = c * KC;
        unsigned wb = wsm + buf * (LW_FLOATS * 4);
#pragma unroll
        for (int i = 0; i < 4; i++) {
            int gi = tid + 512 * i;         // 0..2047
            int row = gi >> 3;
            int kg = gi & 7;
            cp_async16(wb + row * (WS_STRIDE * 4) + kg * 16,
                       Wout + (size_t)(v0 + row) * HH + kc + kg * 4);
        }
        if (tid < 256) {
            unsigned hb = hsm + buf * 4096;
            cp_async16(hb + tid * 16, hT + (size_t)kc * BB + tid * 4);
        }
        cp_commit();
    };

    do_stage(0, 0);
    do_stage(1, 1);

    unsigned long long acc[2][4];
#pragma unroll
    for (int i = 0; i < 2; i++)
#pragma unroll
        for (int p = 0; p < 4; p++) acc[i][p] = 0ull;

    int wrow0 = w * 16 + vp * 2;

    for (int c = 0; c < NCHUNK_LOG; c++) {
        if (c == NCHUNK_LOG - 1)
            asm volatile("cp.async.wait_group 0;" ::: "memory");
        else
            asm volatile("cp.async.wait_group 1;" ::: "memory");
        __syncthreads();
        int buf = c & 1;
        const float* wsb = Ws + buf * LW_FLOATS;
        const float* hsb = hs + buf * (KC * BB);
#pragma unroll
        for (int k4 = 0; k4 < KC / 4; k4++) {
            float4 wA = *(const float4*)&wsb[wrow0 * WS_STRIDE + k4 * 4];
            float4 wB = *(const float4*)&wsb[(wrow0 + 1) * WS_STRIDE + k4 * 4];
            float wa[4] = {wA.x, wA.y, wA.z, wA.w};
            float wbv[4] = {wB.x, wB.y, wB.z, wB.w};
#pragma unroll
            for (int k = 0; k < 4; k++) {
                float4 h0 = *(const float4*)&hsb[(k4 * 4 + k) * BB + bg * 8];
                float4 h1 = *(const float4*)&hsb[(k4 * 4 + k) * BB + bg * 8 + 4];
                unsigned long long hp0 = pack2(h0.x, h0.y);
                unsigned long long hp1 = pack2(h0.z, h0.w);
                unsigned long long hp2 = pack2(h1.x, h1.y);
                unsigned long long hp3 = pack2(h1.z, h1.w);
                unsigned long long ww;
                ww = pack2(wa[k], wa[k]);
                acc[0][0] = fma2(ww, hp0, acc[0][0]);
                acc[0][1] = fma2(ww, hp1, acc[0][1]);
                acc[0][2] = fma2(ww, hp2, acc[0][2]);
                acc[0][3] = fma2(ww, hp3, acc[0][3]);
                ww = pack2(wbv[k], wbv[k]);
                acc[1][0] = fma2(ww, hp0, acc[1][0]);
                acc[1][1] = fma2(ww, hp1, acc[1][1]);
                acc[1][2] = fma2(ww, hp2, acc[1][2]);
                acc[1][3] = fma2(ww, hp3, acc[1][3]);
            }
        }
        __syncthreads();
        if (c + 2 < NCHUNK_LOG) do_stage(buf, c + 2);
    }

    // epilogue: bias, stage store (float2 along v), gumbel, argmax
    int vA = v0 + wrow0;
    float lg[2][8];
#pragma unroll
    for (int i = 0; i < 2; i++) {
        float bo = bout[vA + i];
        unpack2(acc[i][0], lg[i][0], lg[i][1]);
        unpack2(acc[i][1], lg[i][2], lg[i][3]);
        unpack2(acc[i][2], lg[i][4], lg[i][5]);
        unpack2(acc[i][3], lg[i][6], lg[i][7]);
#pragma unroll
        for (int bi = 0; bi < 8; bi++) lg[i][bi] += bo;
    }
    unsigned long long bk[8];
#pragma unroll
    for (int bi = 0; bi < 8; bi++) {
        int b = bg * 8 + bi;
        float2 val = make_float2(lg[0][bi], lg[1][bi]);
        *(float2*)&stage[((size_t)b * TT + t) * VV + vA] = val;
        bk[bi] = 0ull;
#pragma unroll
        for (int i = 0; i < 2; i++) {
            int v = vA + i;
            unsigned o0, o1;
            threefry2x32_dev(key0, key1, 0u, (unsigned)(b * VV + v), o0, o1);
            unsigned bits = o0 ^ o1;
            float u = __uint_as_float(0x3f800000u | (bits >> 9)) - 1.0f;
            u = fmaxf(u + F32_TINY, F32_TINY);
            float g = -logf(-logf(u));
            float val2 = lg[i][bi] + g;
            unsigned long long key =
                ((unsigned long long)ford(val2) << 32) |
                (unsigned long long)(0xFFFFFFFFu - (unsigned)v);
            bk[bi] = u64max(bk[bi], key);
        }
    }
    // reduce over vp lanes (lane bits 2..4), elementwise on 8 keys
#pragma unroll
    for (int off = 4; off < 32; off <<= 1)
#pragma unroll
        for (int bi = 0; bi < 8; bi++)
            bk[bi] = u64max(bk[bi], __shfl_xor_sync(0xffffffffu, bk[bi], off));
    // lane (vp,bg) writes key for b = bg*8 + vp
    parts[w * 32 + bg * 8 + vp] = bk[vp];
    __syncthreads();
    if (tid < 32) {
        unsigned long long m = 0ull;
#pragma unroll
        for (int wi = 0; wi < 16; wi++) m = u64max(m, parts[wi * 32 + tid]);
        atomicMax(&best[t * BB + tid], m);
    }
}

// ---------------- final: captions ----------------
__global__ void caption_kernel(float* __restrict__ cap_f, int* __restrict__ cap_i) {
    int idx = blockIdx.x * 256 + threadIdx.x;
    int tt = idx & 63;
    int b = idx >> 6;
    int v = decode_tok(g_best[tt * BB + b]);
    if (cap_f) cap_f[b * TT + tt] = (float)v;
    if (cap_i) cap_i[b * TT + tt] = v;
}

// ---------------- final: transpose [b][t][v] -> [b][v][t] ----------------
__global__ __launch_bounds__(256) void transpose_kernel(
    const float* __restrict__ stage, float* __restrict__ out) {
    __shared__ float tile[128][65];
    int b = blockIdx.x / 250;
    int vc = blockIdx.x % 250;
    int v0 = vc * 128;
    const float* src = stage + (size_t)b * TT * VV + v0;
#pragma unroll
    for (int l = 0; l < 32; l++) {
        int e = threadIdx.x + l * 256;
        int tt = e >> 7;
        int vi = e & 127;
        tile[vi][tt] = src[(size_t)tt * VV + vi];
    }
    __syncthreads();
    float* dst = out + ((size_t)b * VV + v0) * TT;
#pragma unroll
    for (int l = 0; l < 32; l++) {
        int e = threadIdx.x + l * 256;
        int vi = e >> 6;
        int tt = e & 63;
        dst[(size_t)vi * TT + tt] = tile[vi][tt];
    }
}

// ---------------- host threefry ----------------
static void host_threefry(unsigned k0, unsigned k1, unsigned x0, unsigned x1,
                          unsigned& o0, unsigned& o1) {
    unsigned ks2 = k0 ^ k1 ^ 0x1BD11BDAu;
    x0 += k0; x1 += k1;
#define HTF_RND(r) { x0 += x1; x1 = (x1 << r) | (x1 >> (32 - r)); x1 ^= x0; }
    HTF_RND(13) HTF_RND(15) HTF_RND(26) HTF_RND(6)  x0 += k1;  x1 += ks2 + 1u;
    HTF_RND(17) HTF_RND(29) HTF_RND(16) HTF_RND(24) x0 += ks2; x1 += k0 + 2u;
    HTF_RND(13) HTF_RND(15) HTF_RND(26) HTF_RND(6)  x0 += k0;  x1 += k1 + 3u;
    HTF_RND(17) HTF_RND(29) HTF_RND(16) HTF_RND(24) x0 += k1;  x1 += ks2 + 4u;
    HTF_RND(13) HTF_RND(15) HTF_RND(26) HTF_RND(6)  x0 += ks2; x1 += k0 + 5u;
#undef HTF_RND
    o0 = x0; o1 = x1;
}

extern "C" void kernel_launch(void* const* d_in, const int* in_sizes, int n_in,
                              void* d_out, int out_size) {
    const float* condition = (const float*)d_in[0];
    const float* Wh    = (const float*)d_in[1];
    const float* bh    = (const float*)d_in[2];
    const float* Wc    = (const float*)d_in[3];
    const float* bc    = (const float*)d_in[4];
    const float* embed = (const float*)d_in[5];
    const float* Wih   = (const float*)d_in[6];
    const float* bih   = (const float*)d_in[7];
    const float* Whh   = (const float*)d_in[8];
    const float* bhh   = (const float*)d_in[9];
    const float* Wout  = (const float*)d_in[10];
    const float* bout  = (const float*)d_in[11];

    float *hA, *hB, *cA, *cB, *stage;
    unsigned long long* best;
    cudaGetSymbolAddress((void**)&hA, g_hA);
    cudaGetSymbolAddress((void**)&hB, g_hB);
    cudaGetSymbolAddress((void**)&cA, g_cA);
    cudaGetSymbolAddress((void**)&cB, g_cB);
    cudaGetSymbolAddress((void**)&stage, g_stage);
    cudaGetSymbolAddress((void**)&best, g_best);

    const long long n_cap = (long long)BB * TT;
    const long long n_log = (long long)BB * VV * TT;
    float* cap_f = nullptr;
    int*   cap_i = nullptr;
    float* log_out = nullptr;
    long long osz = (long long)out_size;
    if (osz == n_cap + n_log) {
        cap_f = (float*)d_out;
        log_out = (float*)d_out + n_cap;
    } else if (osz == n_log) {
        log_out = (float*)d_out;
    } else if (osz == n_cap) {
        cap_i = (int*)d_out;
    } else {
        cap_f = (float*)d_out;
        log_out = (float*)d_out + n_cap;
    }

    cudaFuncSetAttribute(logits_kernel,
                         cudaFuncAttributeMaxDynamicSharedMemorySize, LSMEM_TOTAL);

    init_kernel<<<128, 256>>>(condition, Wh, bh, Wc, bc, hA, cA);

    float *hcur = hA, *hnxt = hB, *ccur = cA, *cnxt = cB;
    for (int t = 0; t < TT; t++) {
        gather_kernel<<<192, 256>>>(embed, hcur, t);
        dim3 ggrid(HH * 4 / TILEV, SPLITK);
        lstm_gemm_kernel<<<ggrid, 256>>>(Wih, Whh);
        cell_kernel<<<128, 256>>>(bih, bhh, ccur, hnxt, cnxt);
        unsigned o0, o1;
        host_threefry(0u, 42u, 0u, (unsigned)t, o0, o1);
        logits_kernel<<<VV / LTILEV, 512, LSMEM_TOTAL>>>(hnxt, Wout, bout,
                                                         stage, best, t, o0, o1);
        float* tmp;
        tmp = hcur; hcur = hnxt; hnxt = tmp;
        tmp = ccur; ccur = cnxt; cnxt = tmp;
    }
    caption_kernel<<<8, 256>>>(cap_f, cap_i);
    if (log_out) transpose_kernel<<<8000, 256>>>(stage, log_out);
}

// round 9
// speedup vs baseline: 1.2546x; 1.1240x over previous
#include <cuda_runtime.h>
#include <math.h>

#define BB 32
#define EE 512
#define HH 1024
#define VV 32000
#define TT 64
#define START_TOK 1
#define F32_TINY 1.17549435e-38f
#define KC 32
#define TILEV 128
#define KTOT 1536
#define SPLITK 4
#define KSEG (KTOT / SPLITK)     // 384
#define NCHUNK_LSTM (KSEG / KC)  // 12
#define WS_STRIDE 36
// logits config: 64 v-rows per block, 500 blocks
#define LTV 64
#define NBLK_LOG (VV / LTV)      // 500
#define NCHUNK_LOG (HH / KC)     // 32

// ---------------- device scratch ----------------
__device__ __align__(16) float g_hA[HH * BB];   // [k][b]
__device__ __align__(16) float g_hB[HH * BB];
__device__ __align__(16) float g_cA[HH * BB];
__device__ __align__(16) float g_cB[HH * BB];
__device__ __align__(16) float g_xh[KTOT * BB]; // [k][b]
__device__ __align__(16) float g_gpart[SPLITK * 4 * HH * BB];
__device__ unsigned long long g_best[TT * BB];
__device__ __align__(16) float g_stage[(size_t)BB * TT * VV]; // [b][t][v]

// ---------------- f32x2 packed math ----------------
__device__ __forceinline__ unsigned long long pack2(float lo, float hi) {
    unsigned long long r;
    asm("mov.b64 %0, {%1, %2};" : "=l"(r) : "f"(lo), "f"(hi));
    return r;
}
__device__ __forceinline__ void unpack2(unsigned long long v, float& lo, float& hi) {
    asm("mov.b64 {%0, %1}, %2;" : "=f"(lo), "=f"(hi) : "l"(v));
}
__device__ __forceinline__ unsigned long long fma2(unsigned long long a,
                                                   unsigned long long b,
                                                   unsigned long long c) {
    unsigned long long d;
    asm("fma.rn.f32x2 %0, %1, %2, %3;" : "=l"(d) : "l"(a), "l"(b), "l"(c));
    return d;
}

// ---------------- threefry2x32 (JAX-compatible) ----------------
__device__ __forceinline__ void threefry2x32_dev(unsigned k0, unsigned k1,
                                                 unsigned x0, unsigned x1,
                                                 unsigned& o0, unsigned& o1) {
    unsigned ks2 = k0 ^ k1 ^ 0x1BD11BDAu;
    x0 += k0; x1 += k1;
#define TF_RND(r) { x0 += x1; x1 = __funnelshift_l(x1, x1, r); x1 ^= x0; }
    TF_RND(13) TF_RND(15) TF_RND(26) TF_RND(6)  x0 += k1;  x1 += ks2 + 1u;
    TF_RND(17) TF_RND(29) TF_RND(16) TF_RND(24) x0 += ks2; x1 += k0 + 2u;
    TF_RND(13) TF_RND(15) TF_RND(26) TF_RND(6)  x0 += k0;  x1 += k1 + 3u;
    TF_RND(17) TF_RND(29) TF_RND(16) TF_RND(24) x0 += k1;  x1 += ks2 + 4u;
    TF_RND(13) TF_RND(15) TF_RND(26) TF_RND(6)  x0 += ks2; x1 += k0 + 5u;
#undef TF_RND
    o0 = x0; o1 = x1;
}

__device__ __forceinline__ unsigned ford(float f) {
    unsigned u = __float_as_uint(f);
    return (u & 0x80000000u) ? ~u : (u | 0x80000000u);
}
__device__ __forceinline__ unsigned long long u64max(unsigned long long a,
                                                     unsigned long long b) {
    return a > b ? a : b;
}
__device__ __forceinline__ int decode_tok(unsigned long long key) {
    return (int)(0xFFFFFFFFu - (unsigned)(key & 0xFFFFFFFFull));
}

// ---------------- cp.async helpers ----------------
__device__ __forceinline__ void cp_async16(unsigned dst, const void* src) {
    asm volatile("cp.async.cg.shared.global [%0], [%1], 16;"
                 :: "r"(dst), "l"(src) : "memory");
}
__device__ __forceinline__ void cp_commit() {
    asm volatile("cp.async.commit_group;" ::: "memory");
}

// ---------------- K0: h0/c0 from condition ----------------
__global__ __launch_bounds__(256) void init_kernel(
    const float* __restrict__ cond, const float* __restrict__ Wh,
    const float* __restrict__ bh,   const float* __restrict__ Wc,
    const float* __restrict__ bc,
    float* __restrict__ hout, float* __restrict__ cout) {
    int j = blockIdx.x * 8 + (threadIdx.x >> 5);
    int lane = threadIdx.x & 31;
    if (blockIdx.x < 8) {
        int idx = blockIdx.x * 256 + threadIdx.x;
        if (idx < TT * BB) g_best[idx] = 0ull;
    }
    const float* cr = cond + (size_t)lane * EE;
    const float* wh = Wh + (size_t)j * EE;
    const float* wc = Wc + (size_t)j * EE;
    float ah = bh[j], ac = bc[j];
#pragma unroll 4
    for (int k = 0; k < EE; k += 4) {
        float4 c4 = *(const float4*)(cr + k);
        float4 h4 = *(const float4*)(wh + k);
        float4 q4 = *(const float4*)(wc + k);
        ah = fmaf(c4.x, h4.x, ah); ah = fmaf(c4.y, h4.y, ah);
        ah = fmaf(c4.z, h4.z, ah); ah = fmaf(c4.w, h4.w, ah);
        ac = fmaf(c4.x, q4.x, ac); ac = fmaf(c4.y, q4.y, ac);
        ac = fmaf(c4.z, q4.z, ac); ac = fmaf(c4.w, q4.w, ac);
    }
    hout[j * BB + lane] = ah;
    cout[j * BB + lane] = ac;
}

// ---------------- K-gather: build xh[k][b] = [embed(tok); h] ----------------
__global__ __launch_bounds__(256) void gather_kernel(
    const float* __restrict__ embed, const float* __restrict__ hin, int t) {
    int idx = blockIdx.x * 256 + threadIdx.x;
    int b = idx & 31;
    int k = idx >> 5;
    float val;
    if (k < EE) {
        int tok = START_TOK;
        if (t > 0) tok = decode_tok(g_best[(t - 1) * BB + b]);
        val = embed[(size_t)tok * EE + k];
    } else {
        val = hin[(k - EE) * BB + b];
    }
    g_xh[k * BB + b] = val;
}

// ---------------- K1a: lstm gate GEMM (split-K) ----------------
__global__ __launch_bounds__(256) void lstm_gemm_kernel(
    const float* __restrict__ Wih, const float* __restrict__ Whh) {
    __shared__ __align__(16) float Ws[2][TILEV][WS_STRIDE];
    __shared__ __align__(16) float xs[2][KC][BB];
    int tid = threadIdx.x;
    int rt = tid & 31;
    int bt = tid >> 5;
    int m0 = blockIdx.x * TILEV;
    int seg = blockIdx.y;
    int k0seg = seg * KSEG;

    int srow = tid >> 1;
    int sko = (tid & 1) * 16;
    unsigned wdst0 = (unsigned)__cvta_generic_to_shared(&Ws[0][srow][sko]);
    unsigned wdst1 = (unsigned)__cvta_generic_to_shared(&Ws[1][srow][sko]);
    unsigned xdst0 = (unsigned)__cvta_generic_to_shared(&xs[0][0][0]) + tid * 16;
    unsigned xdst1 = (unsigned)__cvta_generic_to_shared(&xs[1][0][0]) + tid * 16;

    auto do_stage = [&](int buf, int c) {
        int kk = k0seg + c * KC;
        const float* wsrc;
        if (kk < EE) wsrc = Wih + (size_t)(m0 + srow) * EE + kk + sko;
        else         wsrc = Whh + (size_t)(m0 + srow) * HH + (kk - EE) + sko;
        unsigned wd = buf ? wdst1 : wdst0;
#pragma unroll
        for (int ch = 0; ch < 4; ch++)
            cp_async16(wd + ch * 16, wsrc + ch * 4);
        cp_async16(buf ? xdst1 : xdst0, g_xh + (size_t)kk * BB + tid * 4);
        cp_commit();
    };

    do_stage(0, 0);
    do_stage(1, 1);

    unsigned long long acc[4][2];
#pragma unroll
    for (int rj = 0; rj < 4; rj++) { acc[rj][0] = 0ull; acc[rj][1] = 0ull; }

    for (int c = 0; c < NCHUNK_LSTM; c++) {
        if (c == NCHUNK_LSTM - 1)
            asm volatile("cp.async.wait_group 0;" ::: "memory");
        else
            asm volatile("cp.async.wait_group 1;" ::: "memory");
        __syncthreads();
        int buf = c & 1;
#pragma unroll
        for (int k4 = 0; k4 < KC / 4; k4++) {
            unsigned long long h01[4], h23[4];
#pragma unroll
            for (int i = 0; i < 4; i++) {
                float4 h4 = *(const float4*)&xs[buf][k4 * 4 + i][bt * 4];
                h01[i] = pack2(h4.x, h4.y);
                h23[i] = pack2(h4.z, h4.w);
            }
#pragma unroll
            for (int rj = 0; rj < 4; rj++) {
                float4 w4 = *(const float4*)&Ws[buf][rt + 32 * rj][k4 * 4];
                unsigned long long w;
                w = pack2(w4.x, w4.x);
                acc[rj][0] = fma2(w, h01[0], acc[rj][0]);
                acc[rj][1] = fma2(w, h23[0], acc[rj][1]);
                w = pack2(w4.y, w4.y);
                acc[rj][0] = fma2(w, h01[1], acc[rj][0]);
                acc[rj][1] = fma2(w, h23[1], acc[rj][1]);
                w = pack2(w4.z, w4.z);
                acc[rj][0] = fma2(w, h01[2], acc[rj][0]);
                acc[rj][1] = fma2(w, h23[2], acc[rj][1]);
                w = pack2(w4.w, w4.w);
                acc[rj][0] = fma2(w, h01[3], acc[rj][0]);
                acc[rj][1] = fma2(w, h23[3], acc[rj][1]);
            }
        }
        __syncthreads();
        if (c + 2 < NCHUNK_LSTM) do_stage(buf, c + 2);
    }

    float* part = g_gpart + (size_t)seg * 4 * HH * BB;
#pragma unroll
    for (int rj = 0; rj < 4; rj++) {
        int r = m0 + rt + 32 * rj;
        float p[4];
        unpack2(acc[rj][0], p[0], p[1]);
        unpack2(acc[rj][1], p[2], p[3]);
#pragma unroll
        for (int bi = 0; bi < 4; bi++)
            part[(size_t)r * BB + bt * 4 + bi] = p[bi];
    }
}

// ---------------- K1b: combine partials + cell ----------------
__global__ __launch_bounds__(128) void cell_kernel(
    const float* __restrict__ bih, const float* __restrict__ bhh,
    const float* __restrict__ cin,
    float* __restrict__ hout, float* __restrict__ cout) {
    int idx = blockIdx.x * 128 + threadIdx.x;
    int b = idx & 31;
    int j = idx >> 5;
    float a[4] = {0.f, 0.f, 0.f, 0.f};
#pragma unroll
    for (int seg = 0; seg < SPLITK; seg++) {
        const float* part = g_gpart + (size_t)seg * 4 * HH * BB;
#pragma unroll
        for (int gate = 0; gate < 4; gate++)
            a[gate] += part[(size_t)(gate * HH + j) * BB + b];
    }
#pragma unroll
    for (int gate = 0; gate < 4; gate++) {
        int r = gate * HH + j;
        a[gate] += bih[r] + bhh[r];
    }
    float ig = 1.0f / (1.0f + expf(-a[0]));
    float fg = 1.0f / (1.0f + expf(-a[1]));
    float gg = tanhf(a[2]);
    float og = 1.0f / (1.0f + expf(-a[3]));
    float c = fg * cin[j * BB + b] + ig * gg;
    float h = og * tanhf(c);
    cout[j * BB + b] = c;
    hout[j * BB + b] = h;
}

// ---------------- K2: logits GEMM (64-row tiles, 500 blocks) --------------
// Same structure/k-order as the 6573us build, TILEV halved for occupancy.
// 256 threads: vt=tid&31, bt=tid>>5; thread tile 2v x 4b.
// Zig-zag block->v0 mapping by t parity for L2 reuse of Wout.
__global__ __launch_bounds__(256) void logits_kernel(
    const float* __restrict__ hT, const float* __restrict__ Wout,
    const float* __restrict__ bout, float* __restrict__ stage,
    unsigned long long* __restrict__ best, int t, unsigned key0, unsigned key1) {
    __shared__ __align__(16) float Ws[2][LTV][WS_STRIDE];
    __shared__ __align__(16) float hs[2][KC][BB];
    int tid = threadIdx.x;
    int vt = tid & 31;
    int bt = tid >> 5;
    int bid = blockIdx.x;
    if (t & 1) bid = NBLK_LOG - 1 - bid;    // zig-zag for L2 reuse
    int v0 = bid * LTV;

    int srow = tid >> 2;              // 0..63
    int skg = tid & 3;                // k-group of 8 floats
    unsigned wdst0 = (unsigned)__cvta_generic_to_shared(&Ws[0][srow][skg * 8]);
    unsigned wdst1 = (unsigned)__cvta_generic_to_shared(&Ws[1][srow][skg * 8]);
    unsigned hdst0 = (unsigned)__cvta_generic_to_shared(&hs[0][0][0]) + tid * 16;
    unsigned hdst1 = (unsigned)__cvta_generic_to_shared(&hs[1][0][0]) + tid * 16;

    auto do_stage = [&](int buf, int c) {
        int kc = c * KC;
        const float* wsrc = Wout + (size_t)(v0 + srow) * HH + kc + skg * 8;
        unsigned wd = buf ? wdst1 : wdst0;
        cp_async16(wd, wsrc);
        cp_async16(wd + 16, wsrc + 4);
        if (tid < 64) {
            cp_async16((buf ? hdst1 : hdst0) + 192 * 16,
                       hT + (size_t)kc * BB + (tid + 192) * 4);
        }
        cp_async16(buf ? hdst1 : hdst0, hT + (size_t)kc * BB + tid * 4);
        cp_commit();
    };
    // note: hs chunk is 1024 floats = 256 cp16; the above issues 256 (tid<64
    // adds the tail 64). Layout identical to before.

    do_stage(0, 0);
    do_stage(1, 1);

    unsigned long long acc[2][2];
#pragma unroll
    for (int vj = 0; vj < 2; vj++) { acc[vj][0] = 0ull; acc[vj][1] = 0ull; }

    for (int c = 0; c < NCHUNK_LOG; c++) {
        if (c == NCHUNK_LOG - 1)
            asm volatile("cp.async.wait_group 0;" ::: "memory");
        else
            asm volatile("cp.async.wait_group 1;" ::: "memory");
        __syncthreads();
        int buf = c & 1;
#pragma unroll
        for (int k4 = 0; k4 < KC / 4; k4++) {
            unsigned long long h01[4], h23[4];
#pragma unroll
            for (int i = 0; i < 4; i++) {
                float4 h4 = *(const float4*)&hs[buf][k4 * 4 + i][bt * 4];
                h01[i] = pack2(h4.x, h4.y);
                h23[i] = pack2(h4.z, h4.w);
            }
#pragma unroll
            for (int vj = 0; vj < 2; vj++) {
                float4 w4 = *(const float4*)&Ws[buf][vt + 32 * vj][k4 * 4];
                unsigned long long w;
                w = pack2(w4.x, w4.x);
                acc[vj][0] = fma2(w, h01[0], acc[vj][0]);
                acc[vj][1] = fma2(w, h23[0], acc[vj][1]);
                w = pack2(w4.y, w4.y);
                acc[vj][0] = fma2(w, h01[1], acc[vj][0]);
                acc[vj][1] = fma2(w, h23[1], acc[vj][1]);
                w = pack2(w4.z, w4.z);
                acc[vj][0] = fma2(w, h01[2], acc[vj][0]);
                acc[vj][1] = fma2(w, h23[2], acc[vj][1]);
                w = pack2(w4.w, w4.w);
                acc[vj][0] = fma2(w, h01[3], acc[vj][0]);
                acc[vj][1] = fma2(w, h23[3], acc[vj][1]);
            }
        }
        __syncthreads();
        if (c + 2 < NCHUNK_LOG) do_stage(buf, c + 2);
    }

    // epilogue: bias, store to staging [b][t][v], gumbel, argmax
    float lg[2][4];
#pragma unroll
    for (int vj = 0; vj < 2; vj++) {
        unpack2(acc[vj][0], lg[vj][0], lg[vj][1]);
        unpack2(acc[vj][1], lg[vj][2], lg[vj][3]);
        float bo = bout[v0 + vt + 32 * vj];
#pragma unroll
        for (int bi = 0; bi < 4; bi++) lg[vj][bi] += bo;
    }
#pragma unroll
    for (int bi = 0; bi < 4; bi++) {
        int b = bt * 4 + bi;
        float* sp = stage + ((size_t)b * TT + t) * VV + v0 + vt;
        unsigned long long bk = 0ull;
#pragma unroll
        for (int vj = 0; vj < 2; vj++) {
            int v = v0 + vt + 32 * vj;
            float logit = lg[vj][bi];
            sp[32 * vj] = logit;
            unsigned i = (unsigned)(b * VV + v);
            unsigned o0, o1;
            threefry2x32_dev(key0, key1, 0u, i, o0, o1);
            unsigned bits = o0 ^ o1;
            float u = __uint_as_float(0x3f800000u | (bits >> 9)) - 1.0f;
            u = fmaxf(u + F32_TINY, F32_TINY);
            float g = -logf(-logf(u));
            float val = logit + g;
            unsigned long long key =
                ((unsigned long long)ford(val) << 32) |
                (unsigned long long)(0xFFFFFFFFu - (unsigned)v);
            bk = u64max(bk, key);
        }
#pragma unroll
        for (int off = 1; off < 32; off <<= 1) {
            unsigned long long o = __shfl_xor_sync(0xffffffffu, bk, off);
            bk = u64max(bk, o);
        }
        if (vt == 0) atomicMax(&best[t * BB + b], bk);
    }
}

// ---------------- final: captions ----------------
__global__ void caption_kernel(float* __restrict__ cap_f, int* __restrict__ cap_i) {
    int idx = blockIdx.x * 256 + threadIdx.x;
    int tt = idx & 63;
    int b = idx >> 6;
    int v = decode_tok(g_best[tt * BB + b]);
    if (cap_f) cap_f[b * TT + tt] = (float)v;
    if (cap_i) cap_i[b * TT + tt] = v;
}

// ---------------- final: transpose [b][t][v] -> [b][v][t] ----------------
__global__ __launch_bounds__(256) void transpose_kernel(
    const float* __restrict__ stage, float* __restrict__ out) {
    __shared__ float tile[128][65];
    int b = blockIdx.x / 250;
    int vc = blockIdx.x % 250;
    int v0 = vc * 128;
    const float* src = stage + (size_t)b * TT * VV + v0;
#pragma unroll
    for (int l = 0; l < 32; l++) {
        int e = threadIdx.x + l * 256;
        int tt = e >> 7;
        int vi = e & 127;
        tile[vi][tt] = src[(size_t)tt * VV + vi];
    }
    __syncthreads();
    float* dst = out + ((size_t)b * VV + v0) * TT;
#pragma unroll
    for (int l = 0; l < 32; l++) {
        int e = threadIdx.x + l * 256;
        int vi = e >> 6;
        int tt = e & 63;
        dst[(size_t)vi * TT + tt] = tile[vi][tt];
    }
}

// ---------------- host threefry ----------------
static void host_threefry(unsigned k0, unsigned k1, unsigned x0, unsigned x1,
                          unsigned& o0, unsigned& o1) {
    unsigned ks2 = k0 ^ k1 ^ 0x1BD11BDAu;
    x0 += k0; x1 += k1;
#define HTF_RND(r) { x0 += x1; x1 = (x1 << r) | (x1 >> (32 - r)); x1 ^= x0; }
    HTF_RND(13) HTF_RND(15) HTF_RND(26) HTF_RND(6)  x0 += k1;  x1 += ks2 + 1u;
    HTF_RND(17) HTF_RND(29) HTF_RND(16) HTF_RND(24) x0 += ks2; x1 += k0 + 2u;
    HTF_RND(13) HTF_RND(15) HTF_RND(26) HTF_RND(6)  x0 += k0;  x1 += k1 + 3u;
    HTF_RND(17) HTF_RND(29) HTF_RND(16) HTF_RND(24) x0 += k1;  x1 += ks2 + 4u;
    HTF_RND(13) HTF_RND(15) HTF_RND(26) HTF_RND(6)  x0 += ks2; x1 += k0 + 5u;
#undef HTF_RND
    o0 = x0; o1 = x1;
}

extern "C" void kernel_launch(void* const* d_in, const int* in_sizes, int n_in,
                              void* d_out, int out_size) {
    const float* condition = (const float*)d_in[0];
    const float* Wh    = (const float*)d_in[1];
    const float* bh    = (const float*)d_in[2];
    const float* Wc    = (const float*)d_in[3];
    const float* bc    = (const float*)d_in[4];
    const float* embed = (const float*)d_in[5];
    const float* Wih   = (const float*)d_in[6];
    const float* bih   = (const float*)d_in[7];
    const float* Whh   = (const float*)d_in[8];
    const float* bhh   = (const float*)d_in[9];
    const float* Wout  = (const float*)d_in[10];
    const float* bout  = (const float*)d_in[11];

    float *hA, *hB, *cA, *cB, *stage;
    unsigned long long* best;
    cudaGetSymbolAddress((void**)&hA, g_hA);
    cudaGetSymbolAddress((void**)&hB, g_hB);
    cudaGetSymbolAddress((void**)&cA, g_cA);
    cudaGetSymbolAddress((void**)&cB, g_cB);
    cudaGetSymbolAddress((void**)&stage, g_stage);
    cudaGetSymbolAddress((void**)&best, g_best);

    const long long n_cap = (long long)BB * TT;
    const long long n_log = (long long)BB * VV * TT;
    float* cap_f = nullptr;
    int*   cap_i = nullptr;
    float* log_out = nullptr;
    long long osz = (long long)out_size;
    if (osz == n_cap + n_log) {
        cap_f = (float*)d_out;
        log_out = (float*)d_out + n_cap;
    } else if (osz == n_log) {
        log_out = (float*)d_out;
    } else if (osz == n_cap) {
        cap_i = (int*)d_out;
    } else {
        cap_f = (float*)d_out;
        log_out = (float*)d_out + n_cap;
    }

    init_kernel<<<128, 256>>>(condition, Wh, bh, Wc, bc, hA, cA);

    float *hcur = hA, *hnxt = hB, *ccur = cA, *cnxt = cB;
    for (int t = 0; t < TT; t++) {
        gather_kernel<<<192, 256>>>(embed, hcur, t);
        dim3 ggrid(HH * 4 / TILEV, SPLITK);
        lstm_gemm_kernel<<<ggrid, 256>>>(Wih, Whh);
        cell_kernel<<<256, 128>>>(bih, bhh, ccur, hnxt, cnxt);
        unsigned o0, o1;
        host_threefry(0u, 42u, 0u, (unsigned)t, o0, o1);
        logits_kernel<<<NBLK_LOG, 256>>>(hnxt, Wout, bout,
                                         stage, best, t, o0, o1);
        float* tmp;
        tmp = hcur; hcur = hnxt; hnxt = tmp;
        tmp = ccur; ccur = cnxt; cnxt = tmp;
    }
    caption_kernel<<<8, 256>>>(cap_f, cap_i);
    if (log_out) transpose_kernel<<<8000, 256>>>(stage, log_out);
}

// round 11
// speedup vs baseline: 1.4599x; 1.1636x over previous
#include <cuda_runtime.h>
#include <cuda_bf16.h>
#include <math.h>

#define BB 32
#define EE 512
#define HH 1024
#define VV 32000
#define TT 64
#define START_TOK 1
#define F32_TINY 1.17549435e-38f
#define KC 32
#define TILEV 128
#define KTOT 1536
#define SPLITK 4
#define KSEG (KTOT / SPLITK)     // 384
#define NCHUNK_LSTM (KSEG / KC)  // 12
#define WS_STRIDE 36
// logits MMA config
#define LKC 32
#define NCHUNK (HH / LKC)        // 32
#define WPAD 40                  // bf16 row stride (80B, 16B-aligned, bank-clean)
#define SM_WHI 0                 // 4 stages x 128 rows x 80B = 40960
#define SM_WLO 40960
#define SM_HHI 81920             // 4 x 32 x 80B = 10240
#define SM_HLO 92160
#define SM_PARTS 102400          // 4 warps x 32 x 8B = 1024
#define SMEM_LOG 103424

// ---------------- device scratch ----------------
__device__ __align__(16) float g_hA[HH * BB];   // [k][b]
__device__ __align__(16) float g_hB[HH * BB];
__device__ __align__(16) float g_cA[HH * BB];
__device__ __align__(16) float g_cB[HH * BB];
__device__ __align__(16) float g_xh[KTOT * BB]; // [k][b]
__device__ __align__(16) float g_gpart[SPLITK * 4 * HH * BB];
__device__ unsigned long long g_best[TT * BB];
__device__ __align__(16) float g_stage[(size_t)BB * TT * VV]; // [b][t][v]
__device__ __align__(16) __nv_bfloat16 g_whi[(size_t)VV * HH]; // [v][k]
__device__ __align__(16) __nv_bfloat16 g_wlo[(size_t)VV * HH];
__device__ __align__(16) __nv_bfloat16 g_hbf_hi[BB * HH];      // [b][k]
__device__ __align__(16) __nv_bfloat16 g_hbf_lo[BB * HH];

// ---------------- f32x2 packed math ----------------
__device__ __forceinline__ unsigned long long pack2(float lo, float hi) {
    unsigned long long r;
    asm("mov.b64 %0, {%1, %2};" : "=l"(r) : "f"(lo), "f"(hi));
    return r;
}
__device__ __forceinline__ void unpack2(unsigned long long v, float& lo, float& hi) {
    asm("mov.b64 {%0, %1}, %2;" : "=f"(lo), "=f"(hi) : "l"(v));
}
__device__ __forceinline__ unsigned long long fma2(unsigned long long a,
                                                   unsigned long long b,
                                                   unsigned long long c) {
    unsigned long long d;
    asm("fma.rn.f32x2 %0, %1, %2, %3;" : "=l"(d) : "l"(a), "l"(b), "l"(c));
    return d;
}

// ---------------- threefry2x32 (JAX-compatible) ----------------
__device__ __forceinline__ void threefry2x32_dev(unsigned k0, unsigned k1,
                                                 unsigned x0, unsigned x1,
                                                 unsigned& o0, unsigned& o1) {
    unsigned ks2 = k0 ^ k1 ^ 0x1BD11BDAu;
    x0 += k0; x1 += k1;
#define TF_RND(r) { x0 += x1; x1 = __funnelshift_l(x1, x1, r); x1 ^= x0; }
    TF_RND(13) TF_RND(15) TF_RND(26) TF_RND(6)  x0 += k1;  x1 += ks2 + 1u;
    TF_RND(17) TF_RND(29) TF_RND(16) TF_RND(24) x0 += ks2; x1 += k0 + 2u;
    TF_RND(13) TF_RND(15) TF_RND(26) TF_RND(6)  x0 += k0;  x1 += k1 + 3u;
    TF_RND(17) TF_RND(29) TF_RND(16) TF_RND(24) x0 += k1;  x1 += ks2 + 4u;
    TF_RND(13) TF_RND(15) TF_RND(26) TF_RND(6)  x0 += ks2; x1 += k0 + 5u;
#undef TF_RND
    o0 = x0; o1 = x1;
}

__device__ __forceinline__ unsigned ford(float f) {
    unsigned u = __float_as_uint(f);
    return (u & 0x80000000u) ? ~u : (u | 0x80000000u);
}
__device__ __forceinline__ unsigned long long u64max(unsigned long long a,
                                                     unsigned long long b) {
    return a > b ? a : b;
}
__device__ __forceinline__ int decode_tok(unsigned long long key) {
    return (int)(0xFFFFFFFFu - (unsigned)(key & 0xFFFFFFFFull));
}

// ---------------- cp.async / lds helpers ----------------
__device__ __forceinline__ void cp_async16(unsigned dst, const void* src) {
    asm volatile("cp.async.cg.shared.global [%0], [%1], 16;"
                 :: "r"(dst), "l"(src) : "memory");
}
__device__ __forceinline__ void cp_commit() {
    asm volatile("cp.async.commit_group;" ::: "memory");
}
__device__ __forceinline__ unsigned lds32(unsigned a) {
    unsigned r;
    asm volatile("ld.shared.b32 %0, [%1];" : "=r"(r) : "r"(a));
    return r;
}
#define MMA_BF16(c, a, b) \
    asm volatile("mma.sync.aligned.m16n8k16.row.col.f32.bf16.bf16.f32 " \
        "{%0,%1,%2,%3}, {%4,%5,%6,%7}, {%8,%9}, {%0,%1,%2,%3};" \
        : "+f"((c)[0]), "+f"((c)[1]), "+f"((c)[2]), "+f"((c)[3]) \
        : "r"((a)[0]), "r"((a)[1]), "r"((a)[2]), "r"((a)[3]), \
          "r"((b)[0]), "r"((b)[1]))

// ---------------- K-once: split Wout into bf16 hi/lo ----------------
__global__ __launch_bounds__(256) void convert_kernel(const float* __restrict__ W) {
    size_t i = ((size_t)blockIdx.x * 256 + threadIdx.x) * 4;
    float4 w = *(const float4*)(W + i);
    __nv_bfloat16 h0 = __float2bfloat16(w.x);
    __nv_bfloat16 h1 = __float2bfloat16(w.y);
    __nv_bfloat16 h2 = __float2bfloat16(w.z);
    __nv_bfloat16 h3 = __float2bfloat16(w.w);
    __nv_bfloat162 a, b, c, d;
    a.x = h0; a.y = h1; b.x = h2; b.y = h3;
    c.x = __float2bfloat16(w.x - __bfloat162float(h0));
    c.y = __float2bfloat16(w.y - __bfloat162float(h1));
    d.x = __float2bfloat16(w.z - __bfloat162float(h2));
    d.y = __float2bfloat16(w.w - __bfloat162float(h3));
    *(__nv_bfloat162*)(g_whi + i) = a;
    *(__nv_bfloat162*)(g_whi + i + 2) = b;
    *(__nv_bfloat162*)(g_wlo + i) = c;
    *(__nv_bfloat162*)(g_wlo + i + 2) = d;
}

// ---------------- K0: h0/c0 from condition ----------------
__global__ __launch_bounds__(256) void init_kernel(
    const float* __restrict__ cond, const float* __restrict__ Wh,
    const float* __restrict__ bh,   const float* __restrict__ Wc,
    const float* __restrict__ bc,
    float* __restrict__ hout, float* __restrict__ cout) {
    int j = blockIdx.x * 8 + (threadIdx.x >> 5);
    int lane = threadIdx.x & 31;
    if (blockIdx.x < 8) {
        int idx = blockIdx.x * 256 + threadIdx.x;
        if (idx < TT * BB) g_best[idx] = 0ull;
    }
    const float* cr = cond + (size_t)lane * EE;
    const float* wh = Wh + (size_t)j * EE;
    const float* wc = Wc + (size_t)j * EE;
    float ah = bh[j], ac = bc[j];
#pragma unroll 4
    for (int k = 0; k < EE; k += 4) {
        float4 c4 = *(const float4*)(cr + k);
        float4 h4 = *(const float4*)(wh + k);
        float4 q4 = *(const float4*)(wc + k);
        ah = fmaf(c4.x, h4.x, ah); ah = fmaf(c4.y, h4.y, ah);
        ah = fmaf(c4.z, h4.z, ah); ah = fmaf(c4.w, h4.w, ah);
        ac = fmaf(c4.x, q4.x, ac); ac = fmaf(c4.y, q4.y, ac);
        ac = fmaf(c4.z, q4.z, ac); ac = fmaf(c4.w, q4.w, ac);
    }
    hout[j * BB + lane] = ah;
    cout[j * BB + lane] = ac;
}

// ---------------- K-gather: build xh[k][b] = [embed(tok); h] ----------------
__global__ __launch_bounds__(256) void gather_kernel(
    const float* __restrict__ embed, const float* __restrict__ hin, int t) {
    int idx = blockIdx.x * 256 + threadIdx.x;
    int b = idx & 31;
    int k = idx >> 5;
    float val;
    if (k < EE) {
        int tok = START_TOK;
        if (t > 0) tok = decode_tok(g_best[(t - 1) * BB + b]);
        val = embed[(size_t)tok * EE + k];
    } else {
        val = hin[(k - EE) * BB + b];
    }
    g_xh[k * BB + b] = val;
}

// ---------------- K1a: lstm gate GEMM (split-K) ----------------
__global__ __launch_bounds__(256) void lstm_gemm_kernel(
    const float* __restrict__ Wih, const float* __restrict__ Whh) {
    __shared__ __align__(16) float Ws[2][TILEV][WS_STRIDE];
    __shared__ __align__(16) float xs[2][KC][BB];
    int tid = threadIdx.x;
    int rt = tid & 31;
    int bt = tid >> 5;
    int m0 = blockIdx.x * TILEV;
    int seg = blockIdx.y;
    int k0seg = seg * KSEG;

    int srow = tid >> 1;
    int sko = (tid & 1) * 16;
    unsigned wdst0 = (unsigned)__cvta_generic_to_shared(&Ws[0][srow][sko]);
    unsigned wdst1 = (unsigned)__cvta_generic_to_shared(&Ws[1][srow][sko]);
    unsigned xdst0 = (unsigned)__cvta_generic_to_shared(&xs[0][0][0]) + tid * 16;
    unsigned xdst1 = (unsigned)__cvta_generic_to_shared(&xs[1][0][0]) + tid * 16;

    auto do_stage = [&](int buf, int c) {
        int kk = k0seg + c * KC;
        const float* wsrc;
        if (kk < EE) wsrc = Wih + (size_t)(m0 + srow) * EE + kk + sko;
        else         wsrc = Whh + (size_t)(m0 + srow) * HH + (kk - EE) + sko;
        unsigned wd = buf ? wdst1 : wdst0;
#pragma unroll
        for (int ch = 0; ch < 4; ch++)
            cp_async16(wd + ch * 16, wsrc + ch * 4);
        cp_async16(buf ? xdst1 : xdst0, g_xh + (size_t)kk * BB + tid * 4);
        cp_commit();
    };

    do_stage(0, 0);
    do_stage(1, 1);

    unsigned long long acc[4][2];
#pragma unroll
    for (int rj = 0; rj < 4; rj++) { acc[rj][0] = 0ull; acc[rj][1] = 0ull; }

    for (int c = 0; c < NCHUNK_LSTM; c++) {
        if (c == NCHUNK_LSTM - 1)
            asm volatile("cp.async.wait_group 0;" ::: "memory");
        else
            asm volatile("cp.async.wait_group 1;" ::: "memory");
        __syncthreads();
        int buf = c & 1;
#pragma unroll
        for (int k4 = 0; k4 < KC / 4; k4++) {
            unsigned long long h01[4], h23[4];
#pragma unroll
            for (int i = 0; i < 4; i++) {
                float4 h4 = *(const float4*)&xs[buf][k4 * 4 + i][bt * 4];
                h01[i] = pack2(h4.x, h4.y);
                h23[i] = pack2(h4.z, h4.w);
            }
#pragma unroll
            for (int rj = 0; rj < 4; rj++) {
                float4 w4 = *(const float4*)&Ws[buf][rt + 32 * rj][k4 * 4];
                unsigned long long w;
                w = pack2(w4.x, w4.x);
                acc[rj][0] = fma2(w, h01[0], acc[rj][0]);
                acc[rj][1] = fma2(w, h23[0], acc[rj][1]);
                w = pack2(w4.y, w4.y);
                acc[rj][0] = fma2(w, h01[1], acc[rj][0]);
                acc[rj][1] = fma2(w, h23[1], acc[rj][1]);
                w = pack2(w4.z, w4.z);
                acc[rj][0] = fma2(w, h01[2], acc[rj][0]);
                acc[rj][1] = fma2(w, h23[2], acc[rj][1]);
                w = pack2(w4.w, w4.w);
                acc[rj][0] = fma2(w, h01[3], acc[rj][0]);
                acc[rj][1] = fma2(w, h23[3], acc[rj][1]);
            }
        }
        __syncthreads();
        if (c + 2 < NCHUNK_LSTM) do_stage(buf, c + 2);
    }

    float* part = g_gpart + (size_t)seg * 4 * HH * BB;
#pragma unroll
    for (int rj = 0; rj < 4; rj++) {
        int r = m0 + rt + 32 * rj;
        float p[4];
        unpack2(acc[rj][0], p[0], p[1]);
        unpack2(acc[rj][1], p[2], p[3]);
#pragma unroll
        for (int bi = 0; bi < 4; bi++)
            part[(size_t)r * BB + bt * 4 + bi] = p[bi];
    }
}

// ---------------- K1b: combine partials + cell + h bf16 split ---------------
__global__ __launch_bounds__(256) void cell_kernel(
    const float* __restrict__ bih, const float* __restrict__ bhh,
    const float* __restrict__ cin,
    float* __restrict__ hout, float* __restrict__ cout) {
    int idx = blockIdx.x * 256 + threadIdx.x;
    int b = idx & 31;
    int j = idx >> 5;
    float a[4] = {0.f, 0.f, 0.f, 0.f};
#pragma unroll
    for (int seg = 0; seg < SPLITK; seg++) {
        const float* part = g_gpart + (size_t)seg * 4 * HH * BB;
#pragma unroll
        for (int gate = 0; gate < 4; gate++)
            a[gate] += part[(size_t)(gate * HH + j) * BB + b];
    }
#pragma unroll
    for (int gate = 0; gate < 4; gate++) {
        int r = gate * HH + j;
        a[gate] += bih[r] + bhh[r];
    }
    float ig = 1.0f / (1.0f + expf(-a[0]));
    float fg = 1.0f / (1.0f + expf(-a[1]));
    float gg = tanhf(a[2]);
    float og = 1.0f / (1.0f + expf(-a[3]));
    float c = fg * cin[j * BB + b] + ig * gg;
    float h = og * tanhf(c);
    cout[j * BB + b] = c;
    hout[j * BB + b] = h;
    __nv_bfloat16 hi = __float2bfloat16(h);
    g_hbf_hi[b * HH + j] = hi;
    g_hbf_lo[b * HH + j] = __float2bfloat16(h - __bfloat162float(hi));
}

// ---------------- K2: logits via mma.sync bf16 hi/lo ----------------
// 128 threads = 4 warps. Warp w owns v-rows [v0+w*32, +32) as 2 m16 tiles.
// B = h [b][k] (col-major for mma). 4 products per (vt,bt) per k16.
__global__ __launch_bounds__(128) void logits_kernel(
    const float* __restrict__ bout, float* __restrict__ stage,
    unsigned long long* __restrict__ best, int t, unsigned key0, unsigned key1) {
    extern __shared__ __align__(16) char dsm[];
    unsigned sb = (unsigned)__cvta_generic_to_shared(dsm);
    int tid = threadIdx.x;
    int l = tid & 31;
    int w = tid >> 5;
    int v0 = blockIdx.x * 128;

    auto stage_chunk = [&](int c) {
        int s = c & 3;
        int kc = c * LKC;
        const __nv_bfloat16* shi = g_whi + (size_t)(v0 + tid) * HH + kc;
        const __nv_bfloat16* slo = g_wlo + (size_t)(v0 + tid) * HH + kc;
        unsigned dhi = sb + SM_WHI + s * 10240 + tid * 80;
        unsigned dlo = sb + SM_WLO + s * 10240 + tid * 80;
#pragma unroll
        for (int i = 0; i < 4; i++) {
            cp_async16(dhi + i * 16, shi + i * 8);
            cp_async16(dlo + i * 16, slo + i * 8);
        }
        int hr = tid >> 2, hi_ = tid & 3;
        cp_async16(sb + SM_HHI + s * 2560 + hr * 80 + hi_ * 16,
                   g_hbf_hi + hr * HH + kc + hi_ * 8);
        cp_async16(sb + SM_HLO + s * 2560 + hr * 80 + hi_ * 16,
                   g_hbf_lo + hr * HH + kc + hi_ * 8);
        cp_commit();
    };

    stage_chunk(0); stage_chunk(1); stage_chunk(2);

    float acc[2][4][4];
#pragma unroll
    for (int vt = 0; vt < 2; vt++)
#pragma unroll
        for (int bt = 0; bt < 4; bt++)
#pragma unroll
            for (int i = 0; i < 4; i++) acc[vt][bt][i] = 0.f;

    int arow = w * 32 + (l >> 2);          // + vt*16, +8
    int acolb = (l & 3) * 4;               // byte offset in k (2 bf16)
    int brow = (l >> 2);                   // + bt*8

    for (int cc = 0; cc < NCHUNK; cc++) {
        if (cc < NCHUNK - 2)
            asm volatile("cp.async.wait_group 2;" ::: "memory");
        else if (cc == NCHUNK - 2)
            asm volatile("cp.async.wait_group 1;" ::: "memory");
        else
            asm volatile("cp.async.wait_group 0;" ::: "memory");
        __syncthreads();
        int s = cc & 3;
        unsigned whib = sb + SM_WHI + s * 10240;
        unsigned wlob = sb + SM_WLO + s * 10240;
        unsigned hhib = sb + SM_HHI + s * 2560;
        unsigned hlob = sb + SM_HLO + s * 2560;
#pragma unroll
        for (int k16 = 0; k16 < 2; k16++) {
            int kb = k16 * 32;
            unsigned ahi[2][4], alo[2][4], bhi[4][2], blo[4][2];
#pragma unroll
            for (int vt = 0; vt < 2; vt++) {
                unsigned base = (arow + vt * 16) * 80 + kb + acolb;
                ahi[vt][0] = lds32(whib + base);
                ahi[vt][1] = lds32(whib + base + 640);
                ahi[vt][2] = lds32(whib + base + 16);
                ahi[vt][3] = lds32(whib + base + 656);
                alo[vt][0] = lds32(wlob + base);
                alo[vt][1] = lds32(wlob + base + 640);
                alo[vt][2] = lds32(wlob + base + 16);
                alo[vt][3] = lds32(wlob + base + 656);
            }
#pragma unroll
            for (int bt = 0; bt < 4; bt++) {
                unsigned base = (brow + bt * 8) * 80 + kb + acolb;
                bhi[bt][0] = lds32(hhib + base);
                bhi[bt][1] = lds32(hhib + base + 16);
                blo[bt][0] = lds32(hlob + base);
                blo[bt][1] = lds32(hlob + base + 16);
            }
#pragma unroll
            for (int vt = 0; vt < 2; vt++)
#pragma unroll
                for (int bt = 0; bt < 4; bt++) {
                    MMA_BF16(acc[vt][bt], ahi[vt], bhi[bt]);
                    MMA_BF16(acc[vt][bt], ahi[vt], blo[bt]);
                    MMA_BF16(acc[vt][bt], alo[vt], bhi[bt]);
                    MMA_BF16(acc[vt][bt], alo[vt], blo[bt]);
                }
        }
        __syncthreads();
        if (cc + 3 < NCHUNK) stage_chunk(cc + 3);
    }

    // epilogue: bias, stage store, gumbel, argmax
    auto gkey = [&](float logit, int b, int v) -> unsigned long long {
        unsigned o0, o1;
        threefry2x32_dev(key0, key1, 0u, (unsigned)(b * VV + v), o0, o1);
        unsigned bits = o0 ^ o1;
        float u = __uint_as_float(0x3f800000u | (bits >> 9)) - 1.0f;
        u = fmaxf(u + F32_TINY, F32_TINY);
        float g = -logf(-logf(u));
        float val = logit + g;
        return ((unsigned long long)ford(val) << 32) |
               (unsigned long long)(0xFFFFFFFFu - (unsigned)v);
    };

    unsigned long long bk[8];
#pragma unroll
    for (int i = 0; i < 8; i++) bk[i] = 0ull;

#pragma unroll
    for (int vt = 0; vt < 2; vt++) {
        int vlo = v0 + w * 32 + vt * 16 + (l >> 2);
        int vhi = vlo + 8;
        float bolo = bout[vlo];
        float bohi = bout[vhi];
#pragma unroll
        for (int bt = 0; bt < 4; bt++) {
            int be = bt * 8 + (l & 3) * 2;
            int bo = be + 1;
            float x0 = acc[vt][bt][0] + bolo;
            float x1 = acc[vt][bt][1] + bolo;
            float x2 = acc[vt][bt][2] + bohi;
            float x3 = acc[vt][bt][3] + bohi;
            stage[((size_t)be * TT + t) * VV + vlo] = x0;
            stage[((size_t)bo * TT + t) * VV + vlo] = x1;
            stage[((size_t)be * TT + t) * VV + vhi] = x2;
            stage[((size_t)bo * TT + t) * VV + vhi] = x3;
            bk[bt * 2]     = u64max(bk[bt * 2],     u64max(gkey(x0, be, vlo), gkey(x2, be, vhi)));
            bk[bt * 2 + 1] = u64max(bk[bt * 2 + 1], u64max(gkey(x1, bo, vlo), gkey(x3, bo, vhi)));
        }
    }
#pragma unroll
    for (int off = 4; off < 32; off <<= 1)
#pragma unroll
        for (int i = 0; i < 8; i++)
            bk[i] = u64max(bk[i], __shfl_xor_sync(0xffffffffu, bk[i], off));

    unsigned long long* parts = (unsigned long long*)(dsm + SM_PARTS);
    if (l < 4) {
#pragma unroll
        for (int bt = 0; bt < 4; bt++) {
            parts[w * 32 + bt * 8 + l * 2]     = bk[bt * 2];
            parts[w * 32 + bt * 8 + l * 2 + 1] = bk[bt * 2 + 1];
        }
    }
    __syncthreads();
    if (tid < 32) {
        unsigned long long m = 0ull;
#pragma unroll
        for (int wi = 0; wi < 4; wi++) m = u64max(m, parts[wi * 32 + tid]);
        atomicMax(&best[t * BB + tid], m);
    }
}

// ---------------- final: captions ----------------
__global__ void caption_kernel(float* __restrict__ cap_f, int* __restrict__ cap_i) {
    int idx = blockIdx.x * 256 + threadIdx.x;
    int tt = idx & 63;
    int b = idx >> 6;
    int v = decode_tok(g_best[tt * BB + b]);
    if (cap_f) cap_f[b * TT + tt] = (float)v;
    if (cap_i) cap_i[b * TT + tt] = v;
}

// ---------------- final: transpose [b][t][v] -> [b][v][t] ----------------
__global__ __launch_bounds__(256) void transpose_kernel(
    const float* __restrict__ stage, float* __restrict__ out) {
    __shared__ float tile[128][65];
    int b = blockIdx.x / 250;
    int vc = blockIdx.x % 250;
    int v0 = vc * 128;
    const float* src = stage + (size_t)b * TT * VV + v0;
#pragma unroll
    for (int l = 0; l < 32; l++) {
        int e = threadIdx.x + l * 256;
        int tt = e >> 7;
        int vi = e & 127;
        tile[vi][tt] = src[(size_t)tt * VV + vi];
    }
    __syncthreads();
    float* dst = out + ((size_t)b * VV + v0) * TT;
#pragma unroll
    for (int l = 0; l < 32; l++) {
        int e = threadIdx.x + l * 256;
        int vi = e >> 6;
        int tt = e & 63;
        dst[(size_t)vi * TT + tt] = tile[vi][tt];
    }
}

// ---------------- host threefry ----------------
static void host_threefry(unsigned k0, unsigned k1, unsigned x0, unsigned x1,
                          unsigned& o0, unsigned& o1) {
    unsigned ks2 = k0 ^ k1 ^ 0x1BD11BDAu;
    x0 += k0; x1 += k1;
#define HTF_RND(r) { x0 += x1; x1 = (x1 << r) | (x1 >> (32 - r)); x1 ^= x0; }
    HTF_RND(13) HTF_RND(15) HTF_RND(26) HTF_RND(6)  x0 += k1;  x1 += ks2 + 1u;
    HTF_RND(17) HTF_RND(29) HTF_RND(16) HTF_RND(24) x0 += ks2; x1 += k0 + 2u;
    HTF_RND(13) HTF_RND(15) HTF_RND(26) HTF_RND(6)  x0 += k0;  x1 += k1 + 3u;
    HTF_RND(17) HTF_RND(29) HTF_RND(16) HTF_RND(24) x0 += k1;  x1 += ks2 + 4u;
    HTF_RND(13) HTF_RND(15) HTF_RND(26) HTF_RND(6)  x0 += ks2; x1 += k0 + 5u;
#undef HTF_RND
    o0 = x0; o1 = x1;
}

extern "C" void kernel_launch(void* const* d_in, const int* in_sizes, int n_in,
                              void* d_out, int out_size) {
    const float* condition = (const float*)d_in[0];
    const float* Wh    = (const float*)d_in[1];
    const float* bh    = (const float*)d_in[2];
    const float* Wc    = (const float*)d_in[3];
    const float* bc    = (const float*)d_in[4];
    const float* embed = (const float*)d_in[5];
    const float* Wih   = (const float*)d_in[6];
    const float* bih   = (const float*)d_in[7];
    const float* Whh   = (const float*)d_in[8];
    const float* bhh   = (const float*)d_in[9];
    const float* Wout  = (const float*)d_in[10];
    const float* bout  = (const float*)d_in[11];

    float *hA, *hB, *cA, *cB, *stage;
    unsigned long long* best;
    cudaGetSymbolAddress((void**)&hA, g_hA);
    cudaGetSymbolAddress((void**)&hB, g_hB);
    cudaGetSymbolAddress((void**)&cA, g_cA);
    cudaGetSymbolAddress((void**)&cB, g_cB);
    cudaGetSymbolAddress((void**)&stage, g_stage);
    cudaGetSymbolAddress((void**)&best, g_best);

    const long long n_cap = (long long)BB * TT;
    const long long n_log = (long long)BB * VV * TT;
    float* cap_f = nullptr;
    int*   cap_i = nullptr;
    float* log_out = nullptr;
    long long osz = (long long)out_size;
    if (osz == n_cap + n_log) {
        cap_f = (float*)d_out;
        log_out = (float*)d_out + n_cap;
    } else if (osz == n_log) {
        log_out = (float*)d_out;
    } else if (osz == n_cap) {
        cap_i = (int*)d_out;
    } else {
        cap_f = (float*)d_out;
        log_out = (float*)d_out + n_cap;
    }

    cudaFuncSetAttribute(logits_kernel,
                         cudaFuncAttributeMaxDynamicSharedMemorySize, SMEM_LOG);

    convert_kernel<<<VV * HH / 1024, 256>>>(Wout);
    init_kernel<<<128, 256>>>(condition, Wh, bh, Wc, bc, hA, cA);

    // Correct ordering: step t = gather -> lstm -> cell (h_t + bf16 split)
    // -> logits(t) on h_t.
    float *hcur = hA, *hnxt = hB, *ccur = cA, *cnxt = cB;
    for (int t = 0; t < TT; t++) {
        gather_kernel<<<192, 256>>>(embed, hcur, t);
        dim3 ggrid(HH * 4 / TILEV, SPLITK);
        lstm_gemm_kernel<<<ggrid, 256>>>(Wih, Whh);
        cell_kernel<<<128, 256>>>(bih, bhh, ccur, hnxt, cnxt);
        unsigned o0, o1;
        host_threefry(0u, 42u, 0u, (unsigned)t, o0, o1);
        logits_kernel<<<250, 128, SMEM_LOG>>>(bout, stage, best, t, o0, o1);
        float* tmp;
        tmp = hcur; hcur = hnxt; hnxt = tmp;
        tmp = ccur; ccur = cnxt; cnxt = tmp;
    }
    caption_kernel<<<8, 256>>>(cap_f, cap_i);
    if (log_out) transpose_kernel<<<8000, 256>>>(stage, log_out);
}

// round 12
// speedup vs baseline: 1.7277x; 1.1835x over previous
#include <cuda_runtime.h>
#include <cuda_bf16.h>
#include <math.h>

#define BB 32
#define EE 512
#define HH 1024
#define VV 32000
#define TT 64
#define START_TOK 1
#define F32_TINY 1.17549435e-38f
#define KC 32
#define TILEV 128
#define KTOT 1536
#define SPLITK 8
#define KSEG (KTOT / SPLITK)     // 192
#define NCHUNK_LSTM (KSEG / KC)  // 6
#define WS_STRIDE 36
// logits MMA config
#define LKC 32
#define NCHUNK (HH / LKC)        // 32
#define SM_WHI 0                 // 4 stages x 128 rows x 80B = 40960
#define SM_WLO 40960
#define SM_HHI 81920             // 4 x 32 x 80B = 10240
#define SM_HLO 92160
#define SM_PARTS 102400          // 8 warps x 32 x 8B = 2048
#define SMEM_LOG 104448

// ---------------- device scratch ----------------
__device__ __align__(16) float g_hA[HH * BB];   // [k][b]
__device__ __align__(16) float g_hB[HH * BB];
__device__ __align__(16) float g_cA[HH * BB];
__device__ __align__(16) float g_cB[HH * BB];
__device__ __align__(16) float g_xh[KTOT * BB]; // [k][b]
__device__ __align__(16) float g_gpart[SPLITK * 4 * HH * BB];
__device__ unsigned long long g_best[TT * BB];
__device__ __align__(16) float g_stage[(size_t)BB * TT * VV]; // [b][t][v]
__device__ __align__(16) __nv_bfloat16 g_whi[(size_t)VV * HH]; // [v][k]
__device__ __align__(16) __nv_bfloat16 g_wlo[(size_t)VV * HH];
__device__ __align__(16) __nv_bfloat16 g_hbf_hi[BB * HH];      // [b][k]
__device__ __align__(16) __nv_bfloat16 g_hbf_lo[BB * HH];

// ---------------- f32x2 packed math ----------------
__device__ __forceinline__ unsigned long long pack2(float lo, float hi) {
    unsigned long long r;
    asm("mov.b64 %0, {%1, %2};" : "=l"(r) : "f"(lo), "f"(hi));
    return r;
}
__device__ __forceinline__ void unpack2(unsigned long long v, float& lo, float& hi) {
    asm("mov.b64 {%0, %1}, %2;" : "=f"(lo), "=f"(hi) : "l"(v));
}
__device__ __forceinline__ unsigned long long fma2(unsigned long long a,
                                                   unsigned long long b,
                                                   unsigned long long c) {
    unsigned long long d;
    asm("fma.rn.f32x2 %0, %1, %2, %3;" : "=l"(d) : "l"(a), "l"(b), "l"(c));
    return d;
}

// ---------------- threefry2x32 (JAX-compatible) ----------------
__device__ __forceinline__ void threefry2x32_dev(unsigned k0, unsigned k1,
                                                 unsigned x0, unsigned x1,
                                                 unsigned& o0, unsigned& o1) {
    unsigned ks2 = k0 ^ k1 ^ 0x1BD11BDAu;
    x0 += k0; x1 += k1;
#define TF_RND(r) { x0 += x1; x1 = __funnelshift_l(x1, x1, r); x1 ^= x0; }
    TF_RND(13) TF_RND(15) TF_RND(26) TF_RND(6)  x0 += k1;  x1 += ks2 + 1u;
    TF_RND(17) TF_RND(29) TF_RND(16) TF_RND(24) x0 += ks2; x1 += k0 + 2u;
    TF_RND(13) TF_RND(15) TF_RND(26) TF_RND(6)  x0 += k0;  x1 += k1 + 3u;
    TF_RND(17) TF_RND(29) TF_RND(16) TF_RND(24) x0 += k1;  x1 += ks2 + 4u;
    TF_RND(13) TF_RND(15) TF_RND(26) TF_RND(6)  x0 += ks2; x1 += k0 + 5u;
#undef TF_RND
    o0 = x0; o1 = x1;
}

__device__ __forceinline__ unsigned ford(float f) {
    unsigned u = __float_as_uint(f);
    return (u & 0x80000000u) ? ~u : (u | 0x80000000u);
}
__device__ __forceinline__ unsigned long long u64max(unsigned long long a,
                                                     unsigned long long b) {
    return a > b ? a : b;
}
__device__ __forceinline__ int decode_tok(unsigned long long key) {
    return (int)(0xFFFFFFFFu - (unsigned)(key & 0xFFFFFFFFull));
}

// ---------------- cp.async / lds helpers ----------------
__device__ __forceinline__ void cp_async16(unsigned dst, const void* src) {
    asm volatile("cp.async.cg.shared.global [%0], [%1], 16;"
                 :: "r"(dst), "l"(src) : "memory");
}
__device__ __forceinline__ void cp_commit() {
    asm volatile("cp.async.commit_group;" ::: "memory");
}
__device__ __forceinline__ unsigned lds32(unsigned a) {
    unsigned r;
    asm volatile("ld.shared.b32 %0, [%1];" : "=r"(r) : "r"(a));
    return r;
}
#define MMA_BF16(c, a, b) \
    asm volatile("mma.sync.aligned.m16n8k16.row.col.f32.bf16.bf16.f32 " \
        "{%0,%1,%2,%3}, {%4,%5,%6,%7}, {%8,%9}, {%0,%1,%2,%3};" \
        : "+f"((c)[0]), "+f"((c)[1]), "+f"((c)[2]), "+f"((c)[3]) \
        : "r"((a)[0]), "r"((a)[1]), "r"((a)[2]), "r"((a)[3]), \
          "r"((b)[0]), "r"((b)[1]))

// ---------------- K-once: split Wout into bf16 hi/lo ----------------
__global__ __launch_bounds__(256) void convert_kernel(const float* __restrict__ W) {
    size_t i = ((size_t)blockIdx.x * 256 + threadIdx.x) * 4;
    float4 w = *(const float4*)(W + i);
    __nv_bfloat16 h0 = __float2bfloat16(w.x);
    __nv_bfloat16 h1 = __float2bfloat16(w.y);
    __nv_bfloat16 h2 = __float2bfloat16(w.z);
    __nv_bfloat16 h3 = __float2bfloat16(w.w);
    __nv_bfloat162 a, b, c, d;
    a.x = h0; a.y = h1; b.x = h2; b.y = h3;
    c.x = __float2bfloat16(w.x - __bfloat162float(h0));
    c.y = __float2bfloat16(w.y - __bfloat162float(h1));
    d.x = __float2bfloat16(w.z - __bfloat162float(h2));
    d.y = __float2bfloat16(w.w - __bfloat162float(h3));
    *(__nv_bfloat162*)(g_whi + i) = a;
    *(__nv_bfloat162*)(g_whi + i + 2) = b;
    *(__nv_bfloat162*)(g_wlo + i) = c;
    *(__nv_bfloat162*)(g_wlo + i + 2) = d;
}

// ---------------- K0: h0/c0 from condition ----------------
__global__ __launch_bounds__(256) void init_kernel(
    const float* __restrict__ cond, const float* __restrict__ Wh,
    const float* __restrict__ bh,   const float* __restrict__ Wc,
    const float* __restrict__ bc,
    float* __restrict__ hout, float* __restrict__ cout) {
    int j = blockIdx.x * 8 + (threadIdx.x >> 5);
    int lane = threadIdx.x & 31;
    if (blockIdx.x < 8) {
        int idx = blockIdx.x * 256 + threadIdx.x;
        if (idx < TT * BB) g_best[idx] = 0ull;
    }
    const float* cr = cond + (size_t)lane * EE;
    const float* wh = Wh + (size_t)j * EE;
    const float* wc = Wc + (size_t)j * EE;
    float ah = bh[j], ac = bc[j];
#pragma unroll 4
    for (int k = 0; k < EE; k += 4) {
        float4 c4 = *(const float4*)(cr + k);
        float4 h4 = *(const float4*)(wh + k);
        float4 q4 = *(const float4*)(wc + k);
        ah = fmaf(c4.x, h4.x, ah); ah = fmaf(c4.y, h4.y, ah);
        ah = fmaf(c4.z, h4.z, ah); ah = fmaf(c4.w, h4.w, ah);
        ac = fmaf(c4.x, q4.x, ac); ac = fmaf(c4.y, q4.y, ac);
        ac = fmaf(c4.z, q4.z, ac); ac = fmaf(c4.w, q4.w, ac);
    }
    hout[j * BB + lane] = ah;
    cout[j * BB + lane] = ac;
}

// ---------------- K-gather: build xh[k][b] = [embed(tok); h] ----------------
__global__ __launch_bounds__(256) void gather_kernel(
    const float* __restrict__ embed, const float* __restrict__ hin, int t) {
    int idx = blockIdx.x * 256 + threadIdx.x;
    int b = idx & 31;
    int k = idx >> 5;
    float val;
    if (k < EE) {
        int tok = START_TOK;
        if (t > 0) tok = decode_tok(g_best[(t - 1) * BB + b]);
        val = embed[(size_t)tok * EE + k];
    } else {
        val = hin[(k - EE) * BB + b];
    }
    g_xh[k * BB + b] = val;
}

// ---------------- K1a: lstm gate GEMM (split-K 8) ----------------
__global__ __launch_bounds__(256) void lstm_gemm_kernel(
    const float* __restrict__ Wih, const float* __restrict__ Whh) {
    __shared__ __align__(16) float Ws[2][TILEV][WS_STRIDE];
    __shared__ __align__(16) float xs[2][KC][BB];
    int tid = threadIdx.x;
    int rt = tid & 31;
    int bt = tid >> 5;
    int m0 = blockIdx.x * TILEV;
    int seg = blockIdx.y;
    int k0seg = seg * KSEG;

    int srow = tid >> 1;
    int sko = (tid & 1) * 16;
    unsigned wdst0 = (unsigned)__cvta_generic_to_shared(&Ws[0][srow][sko]);
    unsigned wdst1 = (unsigned)__cvta_generic_to_shared(&Ws[1][srow][sko]);
    unsigned xdst0 = (unsigned)__cvta_generic_to_shared(&xs[0][0][0]) + tid * 16;
    unsigned xdst1 = (unsigned)__cvta_generic_to_shared(&xs[1][0][0]) + tid * 16;

    auto do_stage = [&](int buf, int c) {
        int kk = k0seg + c * KC;
        const float* wsrc;
        if (kk < EE) wsrc = Wih + (size_t)(m0 + srow) * EE + kk + sko;
        else         wsrc = Whh + (size_t)(m0 + srow) * HH + (kk - EE) + sko;
        unsigned wd = buf ? wdst1 : wdst0;
#pragma unroll
        for (int ch = 0; ch < 4; ch++)
            cp_async16(wd + ch * 16, wsrc + ch * 4);
        cp_async16(buf ? xdst1 : xdst0, g_xh + (size_t)kk * BB + tid * 4);
        cp_commit();
    };

    do_stage(0, 0);
    do_stage(1, 1);

    unsigned long long acc[4][2];
#pragma unroll
    for (int rj = 0; rj < 4; rj++) { acc[rj][0] = 0ull; acc[rj][1] = 0ull; }

    for (int c = 0; c < NCHUNK_LSTM; c++) {
        if (c == NCHUNK_LSTM - 1)
            asm volatile("cp.async.wait_group 0;" ::: "memory");
        else
            asm volatile("cp.async.wait_group 1;" ::: "memory");
        __syncthreads();
        int buf = c & 1;
#pragma unroll
        for (int k4 = 0; k4 < KC / 4; k4++) {
            unsigned long long h01[4], h23[4];
#pragma unroll
            for (int i = 0; i < 4; i++) {
                float4 h4 = *(const float4*)&xs[buf][k4 * 4 + i][bt * 4];
                h01[i] = pack2(h4.x, h4.y);
                h23[i] = pack2(h4.z, h4.w);
            }
#pragma unroll
            for (int rj = 0; rj < 4; rj++) {
                float4 w4 = *(const float4*)&Ws[buf][rt + 32 * rj][k4 * 4];
                unsigned long long w;
                w = pack2(w4.x, w4.x);
                acc[rj][0] = fma2(w, h01[0], acc[rj][0]);
                acc[rj][1] = fma2(w, h23[0], acc[rj][1]);
                w = pack2(w4.y, w4.y);
                acc[rj][0] = fma2(w, h01[1], acc[rj][0]);
                acc[rj][1] = fma2(w, h23[1], acc[rj][1]);
                w = pack2(w4.z, w4.z);
                acc[rj][0] = fma2(w, h01[2], acc[rj][0]);
                acc[rj][1] = fma2(w, h23[2], acc[rj][1]);
                w = pack2(w4.w, w4.w);
                acc[rj][0] = fma2(w, h01[3], acc[rj][0]);
                acc[rj][1] = fma2(w, h23[3], acc[rj][1]);
            }
        }
        __syncthreads();
        if (c + 2 < NCHUNK_LSTM) do_stage(buf, c + 2);
    }

    float* part = g_gpart + (size_t)seg * 4 * HH * BB;
#pragma unroll
    for (int rj = 0; rj < 4; rj++) {
        int r = m0 + rt + 32 * rj;
        float p[4];
        unpack2(acc[rj][0], p[0], p[1]);
        unpack2(acc[rj][1], p[2], p[3]);
#pragma unroll
        for (int bi = 0; bi < 4; bi++)
            part[(size_t)r * BB + bt * 4 + bi] = p[bi];
    }
}

// ---------------- K1b: combine partials + cell + h bf16 split ---------------
__global__ __launch_bounds__(256) void cell_kernel(
    const float* __restrict__ bih, const float* __restrict__ bhh,
    const float* __restrict__ cin,
    float* __restrict__ hout, float* __restrict__ cout) {
    int idx = blockIdx.x * 256 + threadIdx.x;
    int b = idx & 31;
    int j = idx >> 5;
    float a[4] = {0.f, 0.f, 0.f, 0.f};
#pragma unroll
    for (int seg = 0; seg < SPLITK; seg++) {
        const float* part = g_gpart + (size_t)seg * 4 * HH * BB;
#pragma unroll
        for (int gate = 0; gate < 4; gate++)
            a[gate] += part[(size_t)(gate * HH + j) * BB + b];
    }
#pragma unroll
    for (int gate = 0; gate < 4; gate++) {
        int r = gate * HH + j;
        a[gate] += bih[r] + bhh[r];
    }
    float ig = 1.0f / (1.0f + expf(-a[0]));
    float fg = 1.0f / (1.0f + expf(-a[1]));
    float gg = tanhf(a[2]);
    float og = 1.0f / (1.0f + expf(-a[3]));
    float c = fg * cin[j * BB + b] + ig * gg;
    float h = og * tanhf(c);
    cout[j * BB + b] = c;
    hout[j * BB + b] = h;
    __nv_bfloat16 hi = __float2bfloat16(h);
    g_hbf_hi[b * HH + j] = hi;
    g_hbf_lo[b * HH + j] = __float2bfloat16(h - __bfloat162float(hi));
}

// ---------------- K2: logits via mma.sync bf16 hi/lo (256 thr, 8 warps) ----
// Warp w owns v-rows [v0+w*16, +16) = one m16 tile. B = h [b][k] col-major.
__global__ __launch_bounds__(256) void logits_kernel(
    const float* __restrict__ bout, float* __restrict__ stage,
    unsigned long long* __restrict__ best, int t, unsigned key0, unsigned key1) {
    extern __shared__ __align__(16) char dsm[];
    unsigned sb = (unsigned)__cvta_generic_to_shared(dsm);
    int tid = threadIdx.x;
    int l = tid & 31;
    int w = tid >> 5;
    int v0 = blockIdx.x * 128;

    auto stage_chunk = [&](int c) {
        int s = c & 3;
        int kc = c * LKC;
        int srow = tid >> 1;                 // 0..127 (W row)
        int shalf = (tid & 1) * 32;          // byte half of the 64B row-chunk
        const __nv_bfloat16* shi = g_whi + (size_t)(v0 + srow) * HH + kc + (tid & 1) * 16;
        const __nv_bfloat16* slo = g_wlo + (size_t)(v0 + srow) * HH + kc + (tid & 1) * 16;
        unsigned dhi = sb + SM_WHI + s * 10240 + srow * 80 + shalf;
        unsigned dlo = sb + SM_WLO + s * 10240 + srow * 80 + shalf;
        cp_async16(dhi, shi);
        cp_async16(dhi + 16, shi + 8);
        cp_async16(dlo, slo);
        cp_async16(dlo + 16, slo + 8);
        if (tid < 128) {
            int hr = tid >> 2, hi_ = tid & 3;
            cp_async16(sb + SM_HHI + s * 2560 + hr * 80 + hi_ * 16,
                       g_hbf_hi + hr * HH + kc + hi_ * 8);
            cp_async16(sb + SM_HLO + s * 2560 + hr * 80 + hi_ * 16,
                       g_hbf_lo + hr * HH + kc + hi_ * 8);
        }
        cp_commit();
    };

    stage_chunk(0); stage_chunk(1); stage_chunk(2);

    float acc[4][4];
#pragma unroll
    for (int bt = 0; bt < 4; bt++)
#pragma unroll
        for (int i = 0; i < 4; i++) acc[bt][i] = 0.f;

    int arow = w * 16 + (l >> 2);          // warp's m16 tile, +8 second half
    int acolb = (l & 3) * 4;               // byte offset in k (2 bf16)
    int brow = (l >> 2);                   // + bt*8

    for (int cc = 0; cc < NCHUNK; cc++) {
        if (cc < NCHUNK - 2)
            asm volatile("cp.async.wait_group 2;" ::: "memory");
        else if (cc == NCHUNK - 2)
            asm volatile("cp.async.wait_group 1;" ::: "memory");
        else
            asm volatile("cp.async.wait_group 0;" ::: "memory");
        __syncthreads();
        int s = cc & 3;
        unsigned whib = sb + SM_WHI + s * 10240;
        unsigned wlob = sb + SM_WLO + s * 10240;
        unsigned hhib = sb + SM_HHI + s * 2560;
        unsigned hlob = sb + SM_HLO + s * 2560;
#pragma unroll
        for (int k16 = 0; k16 < 2; k16++) {
            int kb = k16 * 32;
            unsigned ahi[4], alo[4], bhi[4][2], blo[4][2];
            {
                unsigned base = arow * 80 + kb + acolb;
                ahi[0] = lds32(whib + base);
                ahi[1] = lds32(whib + base + 640);
                ahi[2] = lds32(whib + base + 16);
                ahi[3] = lds32(whib + base + 656);
                alo[0] = lds32(wlob + base);
                alo[1] = lds32(wlob + base + 640);
                alo[2] = lds32(wlob + base + 16);
                alo[3] = lds32(wlob + base + 656);
            }
#pragma unroll
            for (int bt = 0; bt < 4; bt++) {
                unsigned base = (brow + bt * 8) * 80 + kb + acolb;
                bhi[bt][0] = lds32(hhib + base);
                bhi[bt][1] = lds32(hhib + base + 16);
                blo[bt][0] = lds32(hlob + base);
                blo[bt][1] = lds32(hlob + base + 16);
            }
#pragma unroll
            for (int bt = 0; bt < 4; bt++) {
                MMA_BF16(acc[bt], ahi, bhi[bt]);
                MMA_BF16(acc[bt], ahi, blo[bt]);
                MMA_BF16(acc[bt], alo, bhi[bt]);
                MMA_BF16(acc[bt], alo, blo[bt]);
            }
        }
        __syncthreads();
        if (cc + 3 < NCHUNK) stage_chunk(cc + 3);
    }

    // epilogue: bias, stage store, gumbel, argmax
    auto gkey = [&](float logit, int b, int v) -> unsigned long long {
        unsigned o0, o1;
        threefry2x32_dev(key0, key1, 0u, (unsigned)(b * VV + v), o0, o1);
        unsigned bits = o0 ^ o1;
        float u = __uint_as_float(0x3f800000u | (bits >> 9)) - 1.0f;
        u = fmaxf(u + F32_TINY, F32_TINY);
        float g = -logf(-logf(u));
        float val = logit + g;
        return ((unsigned long long)ford(val) << 32) |
               (unsigned long long)(0xFFFFFFFFu - (unsigned)v);
    };

    unsigned long long bk[8];
#pragma unroll
    for (int i = 0; i < 8; i++) bk[i] = 0ull;

    {
        int vlo = v0 + w * 16 + (l >> 2);
        int vhi = vlo + 8;
        float bolo = bout[vlo];
        float bohi = bout[vhi];
#pragma unroll
        for (int bt = 0; bt < 4; bt++) {
            int be = bt * 8 + (l & 3) * 2;
            int bo = be + 1;
            float x0 = acc[bt][0] + bolo;
            float x1 = acc[bt][1] + bolo;
            float x2 = acc[bt][2] + bohi;
            float x3 = acc[bt][3] + bohi;
            stage[((size_t)be * TT + t) * VV + vlo] = x0;
            stage[((size_t)bo * TT + t) * VV + vlo] = x1;
            stage[((size_t)be * TT + t) * VV + vhi] = x2;
            stage[((size_t)bo * TT + t) * VV + vhi] = x3;
            bk[bt * 2]     = u64max(bk[bt * 2],     u64max(gkey(x0, be, vlo), gkey(x2, be, vhi)));
            bk[bt * 2 + 1] = u64max(bk[bt * 2 + 1], u64max(gkey(x1, bo, vlo), gkey(x3, bo, vhi)));
        }
    }
#pragma unroll
    for (int off = 4; off < 32; off <<= 1)
#pragma unroll
        for (int i = 0; i < 8; i++)
            bk[i] = u64max(bk[i], __shfl_xor_sync(0xffffffffu, bk[i], off));

    unsigned long long* parts = (unsigned long long*)(dsm + SM_PARTS);
    if (l < 4) {
#pragma unroll
        for (int bt = 0; bt < 4; bt++) {
            parts[w * 32 + bt * 8 + l * 2]     = bk[bt * 2];
            parts[w * 32 + bt * 8 + l * 2 + 1] = bk[bt * 2 + 1];
        }
    }
    __syncthreads();
    if (tid < 32) {
        unsigned long long m = 0ull;
#pragma unroll
        for (int wi = 0; wi < 8; wi++) m = u64max(m, parts[wi * 32 + tid]);
        atomicMax(&best[t * BB + tid], m);
    }
}

// ---------------- final: captions ----------------
__global__ void caption_kernel(float* __restrict__ cap_f, int* __restrict__ cap_i) {
    int idx = blockIdx.x * 256 + threadIdx.x;
    int tt = idx & 63;
    int b = idx >> 6;
    int v = decode_tok(g_best[tt * BB + b]);
    if (cap_f) cap_f[b * TT + tt] = (float)v;
    if (cap_i) cap_i[b * TT + tt] = v;
}

// ---------------- final: transpose [b][t][v] -> [b][v][t] ----------------
__global__ __launch_bounds__(256) void transpose_kernel(
    const float* __restrict__ stage, float* __restrict__ out) {
    __shared__ float tile[128][65];
    int b = blockIdx.x / 250;
    int vc = blockIdx.x % 250;
    int v0 = vc * 128;
    const float* src = stage + (size_t)b * TT * VV + v0;
#pragma unroll
    for (int l = 0; l < 32; l++) {
        int e = threadIdx.x + l * 256;
        int tt = e >> 7;
        int vi = e & 127;
        tile[vi][tt] = src[(size_t)tt * VV + vi];
    }
    __syncthreads();
    float* dst = out + ((size_t)b * VV + v0) * TT;
#pragma unroll
    for (int l = 0; l < 32; l++) {
        int e = threadIdx.x + l * 256;
        int vi = e >> 6;
        int tt = e & 63;
        dst[(size_t)vi * TT + tt] = tile[vi][tt];
    }
}

// ---------------- host threefry ----------------
static void host_threefry(unsigned k0, unsigned k1, unsigned x0, unsigned x1,
                          unsigned& o0, unsigned& o1) {
    unsigned ks2 = k0 ^ k1 ^ 0x1BD11BDAu;
    x0 += k0; x1 += k1;
#define HTF_RND(r) { x0 += x1; x1 = (x1 << r) | (x1 >> (32 - r)); x1 ^= x0; }
    HTF_RND(13) HTF_RND(15) HTF_RND(26) HTF_RND(6)  x0 += k1;  x1 += ks2 + 1u;
    HTF_RND(17) HTF_RND(29) HTF_RND(16) HTF_RND(24) x0 += ks2; x1 += k0 + 2u;
    HTF_RND(13) HTF_RND(15) HTF_RND(26) HTF_RND(6)  x0 += k0;  x1 += k1 + 3u;
    HTF_RND(17) HTF_RND(29) HTF_RND(16) HTF_RND(24) x0 += k1;  x1 += ks2 + 4u;
    HTF_RND(13) HTF_RND(15) HTF_RND(26) HTF_RND(6)  x0 += ks2; x1 += k0 + 5u;
#undef HTF_RND
    o0 = x0; o1 = x1;
}

extern "C" void kernel_launch(void* const* d_in, const int* in_sizes, int n_in,
                              void* d_out, int out_size) {
    const float* condition = (const float*)d_in[0];
    const float* Wh    = (const float*)d_in[1];
    const float* bh    = (const float*)d_in[2];
    const float* Wc    = (const float*)d_in[3];
    const float* bc    = (const float*)d_in[4];
    const float* embed = (const float*)d_in[5];
    const float* Wih   = (const float*)d_in[6];
    const float* bih   = (const float*)d_in[7];
    const float* Whh   = (const float*)d_in[8];
    const float* bhh   = (const float*)d_in[9];
    const float* Wout  = (const float*)d_in[10];
    const float* bout  = (const float*)d_in[11];

    float *hA, *hB, *cA, *cB, *stage;
    unsigned long long* best;
    cudaGetSymbolAddress((void**)&hA, g_hA);
    cudaGetSymbolAddress((void**)&hB, g_hB);
    cudaGetSymbolAddress((void**)&cA, g_cA);
    cudaGetSymbolAddress((void**)&cB, g_cB);
    cudaGetSymbolAddress((void**)&stage, g_stage);
    cudaGetSymbolAddress((void**)&best, g_best);

    const long long n_cap = (long long)BB * TT;
    const long long n_log = (long long)BB * VV * TT;
    float* cap_f = nullptr;
    int*   cap_i = nullptr;
    float* log_out = nullptr;
    long long osz = (long long)out_size;
    if (osz == n_cap + n_log) {
        cap_f = (float*)d_out;
        log_out = (float*)d_out + n_cap;
    } else if (osz == n_log) {
        log_out = (float*)d_out;
    } else if (osz == n_cap) {
        cap_i = (int*)d_out;
    } else {
        cap_f = (float*)d_out;
        log_out = (float*)d_out + n_cap;
    }

    cudaFuncSetAttribute(logits_kernel,
                         cudaFuncAttributeMaxDynamicSharedMemorySize, SMEM_LOG);

    convert_kernel<<<VV * HH / 1024, 256>>>(Wout);
    init_kernel<<<128, 256>>>(condition, Wh, bh, Wc, bc, hA, cA);

    float *hcur = hA, *hnxt = hB, *ccur = cA, *cnxt = cB;
    for (int t = 0; t < TT; t++) {
        gather_kernel<<<192, 256>>>(embed, hcur, t);
        dim3 ggrid(HH * 4 / TILEV, SPLITK);
        lstm_gemm_kernel<<<ggrid, 256>>>(Wih, Whh);
        cell_kernel<<<128, 256>>>(bih, bhh, ccur, hnxt, cnxt);
        unsigned o0, o1;
        host_threefry(0u, 42u, 0u, (unsigned)t, o0, o1);
        logits_kernel<<<250, 256, SMEM_LOG>>>(bout, stage, best, t, o0, o1);
        float* tmp;
        tmp = hcur; hcur = hnxt; hnxt = tmp;
        tmp = ccur; ccur = cnxt; cnxt = tmp;
    }
    caption_kernel<<<8, 256>>>(cap_f, cap_i);
    if (log_out) transpose_kernel<<<8000, 256>>>(stage, log_out);
}

// round 13
// speedup vs baseline: 1.7417x; 1.0081x over previous
#include <cuda_runtime.h>
#include <cuda_bf16.h>
#include <math.h>

#define BB 32
#define EE 512
#define HH 1024
#define VV 32000
#define TT 64
#define START_TOK 1
#define F32_TINY 1.17549435e-38f
#define KC 32
#define TILEV 128
#define KTOT 1536
#define SPLITK 8
#define KSEG (KTOT / SPLITK)     // 192
#define NCHUNK_LSTM (KSEG / KC)  // 6
#define WS_STRIDE 36
// logits MMA config
#define LKC 32
#define NCHUNK (HH / LKC)        // 32
#define NBLK_LOG 250
#define SM_WHI 0                 // 4 stages x 128 rows x 80B = 40960
#define SM_WLO 40960
#define SM_HHI 81920             // 4 x 32 x 80B = 10240
#define SM_HLO 92160
#define SM_PARTS 102400          // 8 warps x 32 x 8B = 2048
#define SMEM_LOG 104448

// ---------------- device scratch ----------------
__device__ __align__(16) float g_hA[HH * BB];   // [k][b]
__device__ __align__(16) float g_hB[HH * BB];
__device__ __align__(16) float g_cA[HH * BB];
__device__ __align__(16) float g_cB[HH * BB];
__device__ __align__(16) float g_xh[KTOT * BB]; // [k][b]
__device__ __align__(16) float g_gpart[SPLITK * 4 * HH * BB];
__device__ unsigned long long g_best[TT * BB];
__device__ __align__(16) float g_stage[(size_t)BB * TT * VV]; // [b][t][v]
__device__ __align__(16) __nv_bfloat16 g_whi[(size_t)VV * HH]; // [v][k]
__device__ __align__(16) __nv_bfloat16 g_wlo[(size_t)VV * HH];
__device__ __align__(16) __nv_bfloat16 g_hbf_hi[BB * HH];      // [b][k]
__device__ __align__(16) __nv_bfloat16 g_hbf_lo[BB * HH];

// ---------------- f32x2 packed math ----------------
__device__ __forceinline__ unsigned long long pack2(float lo, float hi) {
    unsigned long long r;
    asm("mov.b64 %0, {%1, %2};" : "=l"(r) : "f"(lo), "f"(hi));
    return r;
}
__device__ __forceinline__ void unpack2(unsigned long long v, float& lo, float& hi) {
    asm("mov.b64 {%0, %1}, %2;" : "=f"(lo), "=f"(hi) : "l"(v));
}
__device__ __forceinline__ unsigned long long fma2(unsigned long long a,
                                                   unsigned long long b,
                                                   unsigned long long c) {
    unsigned long long d;
    asm("fma.rn.f32x2 %0, %1, %2, %3;" : "=l"(d) : "l"(a), "l"(b), "l"(c));
    return d;
}

// ---------------- threefry2x32 (JAX-compatible) ----------------
__device__ __forceinline__ void threefry2x32_dev(unsigned k0, unsigned k1,
                                                 unsigned x0, unsigned x1,
                                                 unsigned& o0, unsigned& o1) {
    unsigned ks2 = k0 ^ k1 ^ 0x1BD11BDAu;
    x0 += k0; x1 += k1;
#define TF_RND(r) { x0 += x1; x1 = __funnelshift_l(x1, x1, r); x1 ^= x0; }
    TF_RND(13) TF_RND(15) TF_RND(26) TF_RND(6)  x0 += k1;  x1 += ks2 + 1u;
    TF_RND(17) TF_RND(29) TF_RND(16) TF_RND(24) x0 += ks2; x1 += k0 + 2u;
    TF_RND(13) TF_RND(15) TF_RND(26) TF_RND(6)  x0 += k0;  x1 += k1 + 3u;
    TF_RND(17) TF_RND(29) TF_RND(16) TF_RND(24) x0 += k1;  x1 += ks2 + 4u;
    TF_RND(13) TF_RND(15) TF_RND(26) TF_RND(6)  x0 += ks2; x1 += k0 + 5u;
#undef TF_RND
    o0 = x0; o1 = x1;
}

__device__ __forceinline__ unsigned ford(float f) {
    unsigned u = __float_as_uint(f);
    return (u & 0x80000000u) ? ~u : (u | 0x80000000u);
}
__device__ __forceinline__ unsigned long long u64max(unsigned long long a,
                                                     unsigned long long b) {
    return a > b ? a : b;
}
__device__ __forceinline__ int decode_tok(unsigned long long key) {
    return (int)(0xFFFFFFFFu - (unsigned)(key & 0xFFFFFFFFull));
}

// ---------------- cp.async / lds / streaming-store helpers ----------------
__device__ __forceinline__ void cp_async16(unsigned dst, const void* src) {
    asm volatile("cp.async.cg.shared.global [%0], [%1], 16;"
                 :: "r"(dst), "l"(src) : "memory");
}
__device__ __forceinline__ void cp_commit() {
    asm volatile("cp.async.commit_group;" ::: "memory");
}
__device__ __forceinline__ unsigned lds32(unsigned a) {
    unsigned r;
    asm volatile("ld.shared.b32 %0, [%1];" : "=r"(r) : "r"(a));
    return r;
}
__device__ __forceinline__ void stcs(float* p, float v) {
    asm volatile("st.global.cs.f32 [%0], %1;" :: "l"(p), "f"(v) : "memory");
}
#define MMA_BF16(c, a, b) \
    asm volatile("mma.sync.aligned.m16n8k16.row.col.f32.bf16.bf16.f32 " \
        "{%0,%1,%2,%3}, {%4,%5,%6,%7}, {%8,%9}, {%0,%1,%2,%3};" \
        : "+f"((c)[0]), "+f"((c)[1]), "+f"((c)[2]), "+f"((c)[3]) \
        : "r"((a)[0]), "r"((a)[1]), "r"((a)[2]), "r"((a)[3]), \
          "r"((b)[0]), "r"((b)[1]))

// ---------------- K-once: split Wout into bf16 hi/lo ----------------
__global__ __launch_bounds__(256) void convert_kernel(const float* __restrict__ W) {
    size_t i = ((size_t)blockIdx.x * 256 + threadIdx.x) * 4;
    float4 w = *(const float4*)(W + i);
    __nv_bfloat16 h0 = __float2bfloat16(w.x);
    __nv_bfloat16 h1 = __float2bfloat16(w.y);
    __nv_bfloat16 h2 = __float2bfloat16(w.z);
    __nv_bfloat16 h3 = __float2bfloat16(w.w);
    __nv_bfloat162 a, b, c, d;
    a.x = h0; a.y = h1; b.x = h2; b.y = h3;
    c.x = __float2bfloat16(w.x - __bfloat162float(h0));
    c.y = __float2bfloat16(w.y - __bfloat162float(h1));
    d.x = __float2bfloat16(w.z - __bfloat162float(h2));
    d.y = __float2bfloat16(w.w - __bfloat162float(h3));
    *(__nv_bfloat162*)(g_whi + i) = a;
    *(__nv_bfloat162*)(g_whi + i + 2) = b;
    *(__nv_bfloat162*)(g_wlo + i) = c;
    *(__nv_bfloat162*)(g_wlo + i + 2) = d;
}

// ---------------- K0: h0/c0 from condition ----------------
__global__ __launch_bounds__(256) void init_kernel(
    const float* __restrict__ cond, const float* __restrict__ Wh,
    const float* __restrict__ bh,   const float* __restrict__ Wc,
    const float* __restrict__ bc,
    float* __restrict__ hout, float* __restrict__ cout) {
    int j = blockIdx.x * 8 + (threadIdx.x >> 5);
    int lane = threadIdx.x & 31;
    if (blockIdx.x < 8) {
        int idx = blockIdx.x * 256 + threadIdx.x;
        if (idx < TT * BB) g_best[idx] = 0ull;
    }
    const float* cr = cond + (size_t)lane * EE;
    const float* wh = Wh + (size_t)j * EE;
    const float* wc = Wc + (size_t)j * EE;
    float ah = bh[j], ac = bc[j];
#pragma unroll 4
    for (int k = 0; k < EE; k += 4) {
        float4 c4 = *(const float4*)(cr + k);
        float4 h4 = *(const float4*)(wh + k);
        float4 q4 = *(const float4*)(wc + k);
        ah = fmaf(c4.x, h4.x, ah); ah = fmaf(c4.y, h4.y, ah);
        ah = fmaf(c4.z, h4.z, ah); ah = fmaf(c4.w, h4.w, ah);
        ac = fmaf(c4.x, q4.x, ac); ac = fmaf(c4.y, q4.y, ac);
        ac = fmaf(c4.z, q4.z, ac); ac = fmaf(c4.w, q4.w, ac);
    }
    hout[j * BB + lane] = ah;
    cout[j * BB + lane] = ac;
}

// ---------------- K-gather: build xh[k][b] = [embed(tok); h] ----------------
__global__ __launch_bounds__(256) void gather_kernel(
    const float* __restrict__ embed, const float* __restrict__ hin, int t) {
    int idx = blockIdx.x * 256 + threadIdx.x;
    int b = idx & 31;
    int k = idx >> 5;
    float val;
    if (k < EE) {
        int tok = START_TOK;
        if (t > 0) tok = decode_tok(g_best[(t - 1) * BB + b]);
        val = embed[(size_t)tok * EE + k];
    } else {
        val = hin[(k - EE) * BB + b];
    }
    g_xh[k * BB + b] = val;
}

// ---------------- K1a: lstm gate GEMM (split-K 8) ----------------
__global__ __launch_bounds__(256) void lstm_gemm_kernel(
    const float* __restrict__ Wih, const float* __restrict__ Whh) {
    __shared__ __align__(16) float Ws[2][TILEV][WS_STRIDE];
    __shared__ __align__(16) float xs[2][KC][BB];
    int tid = threadIdx.x;
    int rt = tid & 31;
    int bt = tid >> 5;
    int m0 = blockIdx.x * TILEV;
    int seg = blockIdx.y;
    int k0seg = seg * KSEG;

    int srow = tid >> 1;
    int sko = (tid & 1) * 16;
    unsigned wdst0 = (unsigned)__cvta_generic_to_shared(&Ws[0][srow][sko]);
    unsigned wdst1 = (unsigned)__cvta_generic_to_shared(&Ws[1][srow][sko]);
    unsigned xdst0 = (unsigned)__cvta_generic_to_shared(&xs[0][0][0]) + tid * 16;
    unsigned xdst1 = (unsigned)__cvta_generic_to_shared(&xs[1][0][0]) + tid * 16;

    auto do_stage = [&](int buf, int c) {
        int kk = k0seg + c * KC;
        const float* wsrc;
        if (kk < EE) wsrc = Wih + (size_t)(m0 + srow) * EE + kk + sko;
        else         wsrc = Whh + (size_t)(m0 + srow) * HH + (kk - EE) + sko;
        unsigned wd = buf ? wdst1 : wdst0;
#pragma unroll
        for (int ch = 0; ch < 4; ch++)
            cp_async16(wd + ch * 16, wsrc + ch * 4);
        cp_async16(buf ? xdst1 : xdst0, g_xh + (size_t)kk * BB + tid * 4);
        cp_commit();
    };

    do_stage(0, 0);
    do_stage(1, 1);

    unsigned long long acc[4][2];
#pragma unroll
    for (int rj = 0; rj < 4; rj++) { acc[rj][0] = 0ull; acc[rj][1] = 0ull; }

    for (int c = 0; c < NCHUNK_LSTM; c++) {
        if (c == NCHUNK_LSTM - 1)
            asm volatile("cp.async.wait_group 0;" ::: "memory");
        else
            asm volatile("cp.async.wait_group 1;" ::: "memory");
        __syncthreads();
        int buf = c & 1;
#pragma unroll
        for (int k4 = 0; k4 < KC / 4; k4++) {
            unsigned long long h01[4], h23[4];
#pragma unroll
            for (int i = 0; i < 4; i++) {
                float4 h4 = *(const float4*)&xs[buf][k4 * 4 + i][bt * 4];
                h01[i] = pack2(h4.x, h4.y);
                h23[i] = pack2(h4.z, h4.w);
            }
#pragma unroll
            for (int rj = 0; rj < 4; rj++) {
                float4 w4 = *(const float4*)&Ws[buf][rt + 32 * rj][k4 * 4];
                unsigned long long w;
                w = pack2(w4.x, w4.x);
                acc[rj][0] = fma2(w, h01[0], acc[rj][0]);
                acc[rj][1] = fma2(w, h23[0], acc[rj][1]);
                w = pack2(w4.y, w4.y);
                acc[rj][0] = fma2(w, h01[1], acc[rj][0]);
                acc[rj][1] = fma2(w, h23[1], acc[rj][1]);
                w = pack2(w4.z, w4.z);
                acc[rj][0] = fma2(w, h01[2], acc[rj][0]);
                acc[rj][1] = fma2(w, h23[2], acc[rj][1]);
                w = pack2(w4.w, w4.w);
                acc[rj][0] = fma2(w, h01[3], acc[rj][0]);
                acc[rj][1] = fma2(w, h23[3], acc[rj][1]);
            }
        }
        __syncthreads();
        if (c + 2 < NCHUNK_LSTM) do_stage(buf, c + 2);
    }

    float* part = g_gpart + (size_t)seg * 4 * HH * BB;
#pragma unroll
    for (int rj = 0; rj < 4; rj++) {
        int r = m0 + rt + 32 * rj;
        float p[4];
        unpack2(acc[rj][0], p[0], p[1]);
        unpack2(acc[rj][1], p[2], p[3]);
#pragma unroll
        for (int bi = 0; bi < 4; bi++)
            part[(size_t)r * BB + bt * 4 + bi] = p[bi];
    }
}

// ---------------- K1b: combine partials + cell + h bf16 split ---------------
__global__ __launch_bounds__(256) void cell_kernel(
    const float* __restrict__ bih, const float* __restrict__ bhh,
    const float* __restrict__ cin,
    float* __restrict__ hout, float* __restrict__ cout) {
    int idx = blockIdx.x * 256 + threadIdx.x;
    int b = idx & 31;
    int j = idx >> 5;
    float a[4] = {0.f, 0.f, 0.f, 0.f};
#pragma unroll
    for (int seg = 0; seg < SPLITK; seg++) {
        const float* part = g_gpart + (size_t)seg * 4 * HH * BB;
#pragma unroll
        for (int gate = 0; gate < 4; gate++)
            a[gate] += part[(size_t)(gate * HH + j) * BB + b];
    }
#pragma unroll
    for (int gate = 0; gate < 4; gate++) {
        int r = gate * HH + j;
        a[gate] += bih[r] + bhh[r];
    }
    float ig = 1.0f / (1.0f + expf(-a[0]));
    float fg = 1.0f / (1.0f + expf(-a[1]));
    float gg = tanhf(a[2]);
    float og = 1.0f / (1.0f + expf(-a[3]));
    float c = fg * cin[j * BB + b] + ig * gg;
    float h = og * tanhf(c);
    cout[j * BB + b] = c;
    hout[j * BB + b] = h;
    __nv_bfloat16 hi = __float2bfloat16(h);
    g_hbf_hi[b * HH + j] = hi;
    g_hbf_lo[b * HH + j] = __float2bfloat16(h - __bfloat162float(hi));
}

// ---------------- K2: logits via mma.sync bf16 hi/lo (256 thr, 8 warps) ----
// Zig-zag block->v mapping by t parity: W streamed forward/backward on
// alternate steps so ~L2-sized tail stays resident (131MB vs 126MB L2).
__global__ __launch_bounds__(256) void logits_kernel(
    const float* __restrict__ bout, float* __restrict__ stage,
    unsigned long long* __restrict__ best, int t, unsigned key0, unsigned key1) {
    extern __shared__ __align__(16) char dsm[];
    unsigned sb = (unsigned)__cvta_generic_to_shared(dsm);
    int tid = threadIdx.x;
    int l = tid & 31;
    int w = tid >> 5;
    int bid = blockIdx.x;
    if (t & 1) bid = NBLK_LOG - 1 - bid;
    int v0 = bid * 128;

    auto stage_chunk = [&](int c) {
        int s = c & 3;
        // zig-zag within the block too: on odd steps walk k backwards
        int cc2 = (t & 1) ? (NCHUNK - 1 - c) : c;
        int kc = cc2 * LKC;
        int srow = tid >> 1;
        int shalf = (tid & 1) * 32;
        const __nv_bfloat16* shi = g_whi + (size_t)(v0 + srow) * HH + kc + (tid & 1) * 16;
        const __nv_bfloat16* slo = g_wlo + (size_t)(v0 + srow) * HH + kc + (tid & 1) * 16;
        unsigned dhi = sb + SM_WHI + s * 10240 + srow * 80 + shalf;
        unsigned dlo = sb + SM_WLO + s * 10240 + srow * 80 + shalf;
        cp_async16(dhi, shi);
        cp_async16(dhi + 16, shi + 8);
        cp_async16(dlo, slo);
        cp_async16(dlo + 16, slo + 8);
        if (tid < 128) {
            int hr = tid >> 2, hi_ = tid & 3;
            cp_async16(sb + SM_HHI + s * 2560 + hr * 80 + hi_ * 16,
                       g_hbf_hi + hr * HH + kc + hi_ * 8);
            cp_async16(sb + SM_HLO + s * 2560 + hr * 80 + hi_ * 16,
                       g_hbf_lo + hr * HH + kc + hi_ * 8);
        }
        cp_commit();
    };

    stage_chunk(0); stage_chunk(1); stage_chunk(2);

    float acc[4][4];
#pragma unroll
    for (int bt = 0; bt < 4; bt++)
#pragma unroll
        for (int i = 0; i < 4; i++) acc[bt][i] = 0.f;

    int arow = w * 16 + (l >> 2);
    int acolb = (l & 3) * 4;
    int brow = (l >> 2);

    for (int cc = 0; cc < NCHUNK; cc++) {
        if (cc < NCHUNK - 2)
            asm volatile("cp.async.wait_group 2;" ::: "memory");
        else if (cc == NCHUNK - 2)
            asm volatile("cp.async.wait_group 1;" ::: "memory");
        else
            asm volatile("cp.async.wait_group 0;" ::: "memory");
        __syncthreads();
        int s = cc & 3;
        unsigned whib = sb + SM_WHI + s * 10240;
        unsigned wlob = sb + SM_WLO + s * 10240;
        unsigned hhib = sb + SM_HHI + s * 2560;
        unsigned hlob = sb + SM_HLO + s * 2560;
#pragma unroll
        for (int k16 = 0; k16 < 2; k16++) {
            int kb = k16 * 32;
            unsigned ahi[4], alo[4], bhi[4][2], blo[4][2];
            {
                unsigned base = arow * 80 + kb + acolb;
                ahi[0] = lds32(whib + base);
                ahi[1] = lds32(whib + base + 640);
                ahi[2] = lds32(whib + base + 16);
                ahi[3] = lds32(whib + base + 656);
                alo[0] = lds32(wlob + base);
                alo[1] = lds32(wlob + base + 640);
                alo[2] = lds32(wlob + base + 16);
                alo[3] = lds32(wlob + base + 656);
            }
#pragma unroll
            for (int bt = 0; bt < 4; bt++) {
                unsigned base = (brow + bt * 8) * 80 + kb + acolb;
                bhi[bt][0] = lds32(hhib + base);
                bhi[bt][1] = lds32(hhib + base + 16);
                blo[bt][0] = lds32(hlob + base);
                blo[bt][1] = lds32(hlob + base + 16);
            }
#pragma unroll
            for (int bt = 0; bt < 4; bt++) {
                MMA_BF16(acc[bt], ahi, bhi[bt]);
                MMA_BF16(acc[bt], ahi, blo[bt]);
                MMA_BF16(acc[bt], alo, bhi[bt]);
                MMA_BF16(acc[bt], alo, blo[bt]);
            }
        }
        __syncthreads();
        if (cc + 3 < NCHUNK) stage_chunk(cc + 3);
    }

    // epilogue: bias, streaming stage store, gumbel, argmax
    auto gkey = [&](float logit, int b, int v) -> unsigned long long {
        unsigned o0, o1;
        threefry2x32_dev(key0, key1, 0u, (unsigned)(b * VV + v), o0, o1);
        unsigned bits = o0 ^ o1;
        float u = __uint_as_float(0x3f800000u | (bits >> 9)) - 1.0f;
        u = fmaxf(u + F32_TINY, F32_TINY);
        float g = -logf(-logf(u));
        float val = logit + g;
        return ((unsigned long long)ford(val) << 32) |
               (unsigned long long)(0xFFFFFFFFu - (unsigned)v);
    };

    unsigned long long bk[8];
#pragma unroll
    for (int i = 0; i < 8; i++) bk[i] = 0ull;

    {
        int vlo = v0 + w * 16 + (l >> 2);
        int vhi = vlo + 8;
        float bolo = bout[vlo];
        float bohi = bout[vhi];
#pragma unroll
        for (int bt = 0; bt < 4; bt++) {
            int be = bt * 8 + (l & 3) * 2;
            int bo = be + 1;
            float x0 = acc[bt][0] + bolo;
            float x1 = acc[bt][1] + bolo;
            float x2 = acc[bt][2] + bohi;
            float x3 = acc[bt][3] + bohi;
            stcs(&stage[((size_t)be * TT + t) * VV + vlo], x0);
            stcs(&stage[((size_t)bo * TT + t) * VV + vlo], x1);
            stcs(&stage[((size_t)be * TT + t) * VV + vhi], x2);
            stcs(&stage[((size_t)bo * TT + t) * VV + vhi], x3);
            bk[bt * 2]     = u64max(bk[bt * 2],     u64max(gkey(x0, be, vlo), gkey(x2, be, vhi)));
            bk[bt * 2 + 1] = u64max(bk[bt * 2 + 1], u64max(gkey(x1, bo, vlo), gkey(x3, bo, vhi)));
        }
    }
#pragma unroll
    for (int off = 4; off < 32; off <<= 1)
#pragma unroll
        for (int i = 0; i < 8; i++)
            bk[i] = u64max(bk[i], __shfl_xor_sync(0xffffffffu, bk[i], off));

    unsigned long long* parts = (unsigned long long*)(dsm + SM_PARTS);
    if (l < 4) {
#pragma unroll
        for (int bt = 0; bt < 4; bt++) {
            parts[w * 32 + bt * 8 + l * 2]     = bk[bt * 2];
            parts[w * 32 + bt * 8 + l * 2 + 1] = bk[bt * 2 + 1];
        }
    }
    __syncthreads();
    if (tid < 32) {
        unsigned long long m = 0ull;
#pragma unroll
        for (int wi = 0; wi < 8; wi++) m = u64max(m, parts[wi * 32 + tid]);
        atomicMax(&best[t * BB + tid], m);
    }
}

// ---------------- final: captions ----------------
__global__ void caption_kernel(float* __restrict__ cap_f, int* __restrict__ cap_i) {
    int idx = blockIdx.x * 256 + threadIdx.x;
    int tt = idx & 63;
    int b = idx >> 6;
    int v = decode_tok(g_best[tt * BB + b]);
    if (cap_f) cap_f[b * TT + tt] = (float)v;
    if (cap_i) cap_i[b * TT + tt] = v;
}

// ---------------- final: transpose [b][t][v] -> [b][v][t] ----------------
__global__ __launch_bounds__(256) void transpose_kernel(
    const float* __restrict__ stage, float* __restrict__ out) {
    __shared__ float tile[128][65];
    int b = blockIdx.x / 250;
    int vc = blockIdx.x % 250;
    int v0 = vc * 128;
    const float* src = stage + (size_t)b * TT * VV + v0;
#pragma unroll
    for (int l = 0; l < 32; l++) {
        int e = threadIdx.x + l * 256;
        int tt = e >> 7;
        int vi = e & 127;
        tile[vi][tt] = src[(size_t)tt * VV + vi];
    }
    __syncthreads();
    float* dst = out + ((size_t)b * VV + v0) * TT;
#pragma unroll
    for (int l = 0; l < 32; l++) {
        int e = threadIdx.x + l * 256;
        int vi = e >> 6;
        int tt = e & 63;
        dst[(size_t)vi * TT + tt] = tile[vi][tt];
    }
}

// ---------------- host threefry ----------------
static void host_threefry(unsigned k0, unsigned k1, unsigned x0, unsigned x1,
                          unsigned& o0, unsigned& o1) {
    unsigned ks2 = k0 ^ k1 ^ 0x1BD11BDAu;
    x0 += k0; x1 += k1;
#define HTF_RND(r) { x0 += x1; x1 = (x1 << r) | (x1 >> (32 - r)); x1 ^= x0; }
    HTF_RND(13) HTF_RND(15) HTF_RND(26) HTF_RND(6)  x0 += k1;  x1 += ks2 + 1u;
    HTF_RND(17) HTF_RND(29) HTF_RND(16) HTF_RND(24) x0 += ks2; x1 += k0 + 2u;
    HTF_RND(13) HTF_RND(15) HTF_RND(26) HTF_RND(6)  x0 += k0;  x1 += k1 + 3u;
    HTF_RND(17) HTF_RND(29) HTF_RND(16) HTF_RND(24) x0 += k1;  x1 += ks2 + 4u;
    HTF_RND(13) HTF_RND(15) HTF_RND(26) HTF_RND(6)  x0 += ks2; x1 += k0 + 5u;
#undef HTF_RND
    o0 = x0; o1 = x1;
}

extern "C" void kernel_launch(void* const* d_in, const int* in_sizes, int n_in,
                              void* d_out, int out_size) {
    const float* condition = (const float*)d_in[0];
    const float* Wh    = (const float*)d_in[1];
    const float* bh    = (const float*)d_in[2];
    const float* Wc    = (const float*)d_in[3];
    const float* bc    = (const float*)d_in[4];
    const float* embed = (const float*)d_in[5];
    const float* Wih   = (const float*)d_in[6];
    const float* bih   = (const float*)d_in[7];
    const float* Whh   = (const float*)d_in[8];
    const float* bhh   = (const float*)d_in[9];
    const float* Wout  = (const float*)d_in[10];
    const float* bout  = (const float*)d_in[11];

    float *hA, *hB, *cA, *cB, *stage;
    unsigned long long* best;
    cudaGetSymbolAddress((void**)&hA, g_hA);
    cudaGetSymbolAddress((void**)&hB, g_hB);
    cudaGetSymbolAddress((void**)&cA, g_cA);
    cudaGetSymbolAddress((void**)&cB, g_cB);
    cudaGetSymbolAddress((void**)&stage, g_stage);
    cudaGetSymbolAddress((void**)&best, g_best);

    const long long n_cap = (long long)BB * TT;
    const long long n_log = (long long)BB * VV * TT;
    float* cap_f = nullptr;
    int*   cap_i = nullptr;
    float* log_out = nullptr;
    long long osz = (long long)out_size;
    if (osz == n_cap + n_log) {
        cap_f = (float*)d_out;
        log_out = (float*)d_out + n_cap;
    } else if (osz == n_log) {
        log_out = (float*)d_out;
    } else if (osz == n_cap) {
        cap_i = (int*)d_out;
    } else {
        cap_f = (float*)d_out;
        log_out = (float*)d_out + n_cap;
    }

    cudaFuncSetAttribute(logits_kernel,
                         cudaFuncAttributeMaxDynamicSharedMemorySize, SMEM_LOG);

    convert_kernel<<<VV * HH / 1024, 256>>>(Wout);
    init_kernel<<<128, 256>>>(condition, Wh, bh, Wc, bc, hA, cA);

    float *hcur = hA, *hnxt = hB, *ccur = cA, *cnxt = cB;
    for (int t = 0; t < TT; t++) {
        gather_kernel<<<192, 256>>>(embed, hcur, t);
        dim3 ggrid(HH * 4 / TILEV, SPLITK);
        lstm_gemm_kernel<<<ggrid, 256>>>(Wih, Whh);
        cell_kernel<<<128, 256>>>(bih, bhh, ccur, hnxt, cnxt);
        unsigned o0, o1;
        host_threefry(0u, 42u, 0u, (unsigned)t, o0, o1);
        logits_kernel<<<NBLK_LOG, 256, SMEM_LOG>>>(bout, stage, best, t, o0, o1);
        float* tmp;
        tmp = hcur; hcur = hnxt; hnxt = tmp;
        tmp = ccur; ccur = cnxt; cnxt = tmp;
    }
    caption_kernel<<<8, 256>>>(cap_f, cap_i);
    if (log_out) transpose_kernel<<<8000, 256>>>(stage, log_out);
}

// round 14
// speedup vs baseline: 1.9146x; 1.0993x over previous
#include <cuda_runtime.h>
#include <cuda_bf16.h>
#include <math.h>

#define BB 32
#define EE 512
#define HH 1024
#define VV 32000
#define TT 64
#define START_TOK 1
#define F32_TINY 1.17549435e-38f
#define KC 32
#define TILEV 128
#define KTOT 1536
#define SPLITK 8
#define KSEG (KTOT / SPLITK)     // 192
#define NCHUNK_LSTM (KSEG / KC)  // 6
#define WS_STRIDE 36
// logits MMA config
#define LKC 32
#define NCHUNK (HH / LKC)        // 32
#define NBLK_LOG 250
#define SM_WHI 0                 // 4 stages x 128 rows x 80B = 40960
#define SM_WLO 40960
#define SM_HHI 81920             // 4 x 32 x 80B = 10240
#define SM_HLO 92160
#define SM_PARTS 102400          // 8 warps x 32 x 8B = 2048
#define SMEM_LOG 104448

// ---------------- device scratch ----------------
__device__ __align__(16) float g_hA[HH * BB];   // [k][b]
__device__ __align__(16) float g_hB[HH * BB];
__device__ __align__(16) float g_cA[HH * BB];
__device__ __align__(16) float g_cB[HH * BB];
__device__ __align__(16) float g_xh[KTOT * BB]; // [k][b]
__device__ __align__(16) float g_gpart[SPLITK * 4 * HH * BB];
__device__ unsigned long long g_best[TT * BB];
__device__ __align__(16) float g_stage[(size_t)BB * TT * VV]; // [b][t][v]
__device__ __align__(16) __nv_bfloat16 g_whi[(size_t)VV * HH]; // [v][k]
__device__ __align__(16) __nv_bfloat16 g_wlo[(size_t)VV * HH];
__device__ __align__(16) __nv_bfloat16 g_hbf_hi[BB * HH];      // [b][k]
__device__ __align__(16) __nv_bfloat16 g_hbf_lo[BB * HH];

// ---------------- f32x2 packed math ----------------
__device__ __forceinline__ unsigned long long pack2(float lo, float hi) {
    unsigned long long r;
    asm("mov.b64 %0, {%1, %2};" : "=l"(r) : "f"(lo), "f"(hi));
    return r;
}
__device__ __forceinline__ void unpack2(unsigned long long v, float& lo, float& hi) {
    asm("mov.b64 {%0, %1}, %2;" : "=f"(lo), "=f"(hi) : "l"(v));
}
__device__ __forceinline__ unsigned long long fma2(unsigned long long a,
                                                   unsigned long long b,
                                                   unsigned long long c) {
    unsigned long long d;
    asm("fma.rn.f32x2 %0, %1, %2, %3;" : "=l"(d) : "l"(a), "l"(b), "l"(c));
    return d;
}

// ---------------- threefry2x32 (JAX-compatible) ----------------
__device__ __forceinline__ void threefry2x32_dev(unsigned k0, unsigned k1,
                                                 unsigned x0, unsigned x1,
                                                 unsigned& o0, unsigned& o1) {
    unsigned ks2 = k0 ^ k1 ^ 0x1BD11BDAu;
    x0 += k0; x1 += k1;
#define TF_RND(r) { x0 += x1; x1 = __funnelshift_l(x1, x1, r); x1 ^= x0; }
    TF_RND(13) TF_RND(15) TF_RND(26) TF_RND(6)  x0 += k1;  x1 += ks2 + 1u;
    TF_RND(17) TF_RND(29) TF_RND(16) TF_RND(24) x0 += ks2; x1 += k0 + 2u;
    TF_RND(13) TF_RND(15) TF_RND(26) TF_RND(6)  x0 += k0;  x1 += k1 + 3u;
    TF_RND(17) TF_RND(29) TF_RND(16) TF_RND(24) x0 += k1;  x1 += ks2 + 4u;
    TF_RND(13) TF_RND(15) TF_RND(26) TF_RND(6)  x0 += ks2; x1 += k0 + 5u;
#undef TF_RND
    o0 = x0; o1 = x1;
}

__device__ __forceinline__ unsigned ford(float f) {
    unsigned u = __float_as_uint(f);
    return (u & 0x80000000u) ? ~u : (u | 0x80000000u);
}
__device__ __forceinline__ unsigned long long u64max(unsigned long long a,
                                                     unsigned long long b) {
    return a > b ? a : b;
}
__device__ __forceinline__ int decode_tok(unsigned long long key) {
    return (int)(0xFFFFFFFFu - (unsigned)(key & 0xFFFFFFFFull));
}

// ---------------- cp.async / ldsm / streaming-store helpers ----------------
__device__ __forceinline__ void cp_async16(unsigned dst, const void* src) {
    asm volatile("cp.async.cg.shared.global [%0], [%1], 16;"
                 :: "r"(dst), "l"(src) : "memory");
}
__device__ __forceinline__ void cp_commit() {
    asm volatile("cp.async.commit_group;" ::: "memory");
}
__device__ __forceinline__ void ldsm_x4(unsigned addr, unsigned* r) {
    asm volatile("ldmatrix.sync.aligned.m8n8.x4.shared.b16 {%0,%1,%2,%3}, [%4];"
                 : "=r"(r[0]), "=r"(r[1]), "=r"(r[2]), "=r"(r[3]) : "r"(addr));
}
__device__ __forceinline__ void stcs(float* p, float v) {
    asm volatile("st.global.cs.f32 [%0], %1;" :: "l"(p), "f"(v) : "memory");
}
#define MMA_BF16(c, a, b) \
    asm volatile("mma.sync.aligned.m16n8k16.row.col.f32.bf16.bf16.f32 " \
        "{%0,%1,%2,%3}, {%4,%5,%6,%7}, {%8,%9}, {%0,%1,%2,%3};" \
        : "+f"((c)[0]), "+f"((c)[1]), "+f"((c)[2]), "+f"((c)[3]) \
        : "r"((a)[0]), "r"((a)[1]), "r"((a)[2]), "r"((a)[3]), \
          "r"((b)[0]), "r"((b)[1]))

// ---------------- K-once: split Wout into bf16 hi/lo ----------------
__global__ __launch_bounds__(256) void convert_kernel(const float* __restrict__ W) {
    size_t i = ((size_t)blockIdx.x * 256 + threadIdx.x) * 4;
    float4 w = *(const float4*)(W + i);
    __nv_bfloat16 h0 = __float2bfloat16(w.x);
    __nv_bfloat16 h1 = __float2bfloat16(w.y);
    __nv_bfloat16 h2 = __float2bfloat16(w.z);
    __nv_bfloat16 h3 = __float2bfloat16(w.w);
    __nv_bfloat162 a, b, c, d;
    a.x = h0; a.y = h1; b.x = h2; b.y = h3;
    c.x = __float2bfloat16(w.x - __bfloat162float(h0));
    c.y = __float2bfloat16(w.y - __bfloat162float(h1));
    d.x = __float2bfloat16(w.z - __bfloat162float(h2));
    d.y = __float2bfloat16(w.w - __bfloat162float(h3));
    *(__nv_bfloat162*)(g_whi + i) = a;
    *(__nv_bfloat162*)(g_whi + i + 2) = b;
    *(__nv_bfloat162*)(g_wlo + i) = c;
    *(__nv_bfloat162*)(g_wlo + i + 2) = d;
}

// ---------------- K0: h0/c0 from condition ----------------
__global__ __launch_bounds__(256) void init_kernel(
    const float* __restrict__ cond, const float* __restrict__ Wh,
    const float* __restrict__ bh,   const float* __restrict__ Wc,
    const float* __restrict__ bc,
    float* __restrict__ hout, float* __restrict__ cout) {
    int j = blockIdx.x * 8 + (threadIdx.x >> 5);
    int lane = threadIdx.x & 31;
    if (blockIdx.x < 8) {
        int idx = blockIdx.x * 256 + threadIdx.x;
        if (idx < TT * BB) g_best[idx] = 0ull;
    }
    const float* cr = cond + (size_t)lane * EE;
    const float* wh = Wh + (size_t)j * EE;
    const float* wc = Wc + (size_t)j * EE;
    float ah = bh[j], ac = bc[j];
#pragma unroll 4
    for (int k = 0; k < EE; k += 4) {
        float4 c4 = *(const float4*)(cr + k);
        float4 h4 = *(const float4*)(wh + k);
        float4 q4 = *(const float4*)(wc + k);
        ah = fmaf(c4.x, h4.x, ah); ah = fmaf(c4.y, h4.y, ah);
        ah = fmaf(c4.z, h4.z, ah); ah = fmaf(c4.w, h4.w, ah);
        ac = fmaf(c4.x, q4.x, ac); ac = fmaf(c4.y, q4.y, ac);
        ac = fmaf(c4.z, q4.z, ac); ac = fmaf(c4.w, q4.w, ac);
    }
    hout[j * BB + lane] = ah;
    cout[j * BB + lane] = ac;
}

// ---------------- K-gather: build xh[k][b] = [embed(tok); h] ----------------
__global__ __launch_bounds__(256) void gather_kernel(
    const float* __restrict__ embed, const float* __restrict__ hin, int t) {
    int idx = blockIdx.x * 256 + threadIdx.x;
    int b = idx & 31;
    int k = idx >> 5;
    float val;
    if (k < EE) {
        int tok = START_TOK;
        if (t > 0) tok = decode_tok(g_best[(t - 1) * BB + b]);
        val = embed[(size_t)tok * EE + k];
    } else {
        val = hin[(k - EE) * BB + b];
    }
    g_xh[k * BB + b] = val;
}

// ---------------- K1a: lstm gate GEMM (split-K 8) ----------------
__global__ __launch_bounds__(256) void lstm_gemm_kernel(
    const float* __restrict__ Wih, const float* __restrict__ Whh) {
    __shared__ __align__(16) float Ws[2][TILEV][WS_STRIDE];
    __shared__ __align__(16) float xs[2][KC][BB];
    int tid = threadIdx.x;
    int rt = tid & 31;
    int bt = tid >> 5;
    int m0 = blockIdx.x * TILEV;
    int seg = blockIdx.y;
    int k0seg = seg * KSEG;

    int srow = tid >> 1;
    int sko = (tid & 1) * 16;
    unsigned wdst0 = (unsigned)__cvta_generic_to_shared(&Ws[0][srow][sko]);
    unsigned wdst1 = (unsigned)__cvta_generic_to_shared(&Ws[1][srow][sko]);
    unsigned xdst0 = (unsigned)__cvta_generic_to_shared(&xs[0][0][0]) + tid * 16;
    unsigned xdst1 = (unsigned)__cvta_generic_to_shared(&xs[1][0][0]) + tid * 16;

    auto do_stage = [&](int buf, int c) {
        int kk = k0seg + c * KC;
        const float* wsrc;
        if (kk < EE) wsrc = Wih + (size_t)(m0 + srow) * EE + kk + sko;
        else         wsrc = Whh + (size_t)(m0 + srow) * HH + (kk - EE) + sko;
        unsigned wd = buf ? wdst1 : wdst0;
#pragma unroll
        for (int ch = 0; ch < 4; ch++)
            cp_async16(wd + ch * 16, wsrc + ch * 4);
        cp_async16(buf ? xdst1 : xdst0, g_xh + (size_t)kk * BB + tid * 4);
        cp_commit();
    };

    do_stage(0, 0);
    do_stage(1, 1);

    unsigned long long acc[4][2];
#pragma unroll
    for (int rj = 0; rj < 4; rj++) { acc[rj][0] = 0ull; acc[rj][1] = 0ull; }

    for (int c = 0; c < NCHUNK_LSTM; c++) {
        if (c == NCHUNK_LSTM - 1)
            asm volatile("cp.async.wait_group 0;" ::: "memory");
        else
            asm volatile("cp.async.wait_group 1;" ::: "memory");
        __syncthreads();
        int buf = c & 1;
#pragma unroll
        for (int k4 = 0; k4 < KC / 4; k4++) {
            unsigned long long h01[4], h23[4];
#pragma unroll
            for (int i = 0; i < 4; i++) {
                float4 h4 = *(const float4*)&xs[buf][k4 * 4 + i][bt * 4];
                h01[i] = pack2(h4.x, h4.y);
                h23[i] = pack2(h4.z, h4.w);
            }
#pragma unroll
            for (int rj = 0; rj < 4; rj++) {
                float4 w4 = *(const float4*)&Ws[buf][rt + 32 * rj][k4 * 4];
                unsigned long long w;
                w = pack2(w4.x, w4.x);
                acc[rj][0] = fma2(w, h01[0], acc[rj][0]);
                acc[rj][1] = fma2(w, h23[0], acc[rj][1]);
                w = pack2(w4.y, w4.y);
                acc[rj][0] = fma2(w, h01[1], acc[rj][0]);
                acc[rj][1] = fma2(w, h23[1], acc[rj][1]);
                w = pack2(w4.z, w4.z);
                acc[rj][0] = fma2(w, h01[2], acc[rj][0]);
                acc[rj][1] = fma2(w, h23[2], acc[rj][1]);
                w = pack2(w4.w, w4.w);
                acc[rj][0] = fma2(w, h01[3], acc[rj][0]);
                acc[rj][1] = fma2(w, h23[3], acc[rj][1]);
            }
        }
        __syncthreads();
        if (c + 2 < NCHUNK_LSTM) do_stage(buf, c + 2);
    }

    float* part = g_gpart + (size_t)seg * 4 * HH * BB;
#pragma unroll
    for (int rj = 0; rj < 4; rj++) {
        int r = m0 + rt + 32 * rj;
        float p[4];
        unpack2(acc[rj][0], p[0], p[1]);
        unpack2(acc[rj][1], p[2], p[3]);
#pragma unroll
        for (int bi = 0; bi < 4; bi++)
            part[(size_t)r * BB + bt * 4 + bi] = p[bi];
    }
}

// ---------------- K1b: combine partials + cell + h bf16 split ---------------
__global__ __launch_bounds__(256) void cell_kernel(
    const float* __restrict__ bih, const float* __restrict__ bhh,
    const float* __restrict__ cin,
    float* __restrict__ hout, float* __restrict__ cout) {
    int idx = blockIdx.x * 256 + threadIdx.x;
    int b = idx & 31;
    int j = idx >> 5;
    float a[4] = {0.f, 0.f, 0.f, 0.f};
#pragma unroll
    for (int seg = 0; seg < SPLITK; seg++) {
        const float* part = g_gpart + (size_t)seg * 4 * HH * BB;
#pragma unroll
        for (int gate = 0; gate < 4; gate++)
            a[gate] += part[(size_t)(gate * HH + j) * BB + b];
    }
#pragma unroll
    for (int gate = 0; gate < 4; gate++) {
        int r = gate * HH + j;
        a[gate] += bih[r] + bhh[r];
    }
    float ig = 1.0f / (1.0f + expf(-a[0]));
    float fg = 1.0f / (1.0f + expf(-a[1]));
    float gg = tanhf(a[2]);
    float og = 1.0f / (1.0f + expf(-a[3]));
    float c = fg * cin[j * BB + b] + ig * gg;
    float h = og * tanhf(c);
    cout[j * BB + b] = c;
    hout[j * BB + b] = h;
    __nv_bfloat16 hi = __float2bfloat16(h);
    g_hbf_hi[b * HH + j] = hi;
    g_hbf_lo[b * HH + j] = __float2bfloat16(h - __bfloat162float(hi));
}

// ---------------- K2: logits via mma.sync bf16 hi/lo, ldmatrix frags -------
// 256 thr, 8 warps. Warp w owns v-rows [v0+w*16, +16) = one m16 tile.
// 3-term split (hi*hi + hi*lo + lo*hi); lo*lo dropped (~2^-18 relative).
__global__ __launch_bounds__(256) void logits_kernel(
    const float* __restrict__ bout, float* __restrict__ stage,
    unsigned long long* __restrict__ best, int t, unsigned key0, unsigned key1) {
    extern __shared__ __align__(16) char dsm[];
    unsigned sb = (unsigned)__cvta_generic_to_shared(dsm);
    int tid = threadIdx.x;
    int l = tid & 31;
    int w = tid >> 5;
    int bid = blockIdx.x;
    if (t & 1) bid = NBLK_LOG - 1 - bid;
    int v0 = bid * 128;

    auto stage_chunk = [&](int c) {
        int s = c & 3;
        int cc2 = (t & 1) ? (NCHUNK - 1 - c) : c;
        int kc = cc2 * LKC;
        int srow = tid >> 1;
        int shalf = (tid & 1) * 32;
        const __nv_bfloat16* shi = g_whi + (size_t)(v0 + srow) * HH + kc + (tid & 1) * 16;
        const __nv_bfloat16* slo = g_wlo + (size_t)(v0 + srow) * HH + kc + (tid & 1) * 16;
        unsigned dhi = sb + SM_WHI + s * 10240 + srow * 80 + shalf;
        unsigned dlo = sb + SM_WLO + s * 10240 + srow * 80 + shalf;
        cp_async16(dhi, shi);
        cp_async16(dhi + 16, shi + 8);
        cp_async16(dlo, slo);
        cp_async16(dlo + 16, slo + 8);
        if (tid < 128) {
            int hr = tid >> 2, hi_ = tid & 3;
            cp_async16(sb + SM_HHI + s * 2560 + hr * 80 + hi_ * 16,
                       g_hbf_hi + hr * HH + kc + hi_ * 8);
            cp_async16(sb + SM_HLO + s * 2560 + hr * 80 + hi_ * 16,
                       g_hbf_lo + hr * HH + kc + hi_ * 8);
        }
        cp_commit();
    };

    stage_chunk(0); stage_chunk(1); stage_chunk(2);

    float acc[4][4];
#pragma unroll
    for (int bt = 0; bt < 4; bt++)
#pragma unroll
        for (int i = 0; i < 4; i++) acc[bt][i] = 0.f;

    // ldmatrix per-lane address offsets (within a stage buffer)
    // A (W tile, rows = v): lanes 0-15 -> rows 0-15 @+0, lanes 16-31 -> +16B
    unsigned aoff = (unsigned)((w * 16 + (l & 15)) * 80 + (l >> 4) * 16);
    // B (h tile, rows = b): lanes 0-7 n0-7 @+0, 8-15 n0-7 @+16,
    //                       16-23 n8-15 @+0, 24-31 n8-15 @+16
    unsigned brow = (unsigned)(((l >> 4) * 8) + (l & 7));
    unsigned bkadd = (unsigned)(((l >> 3) & 1) * 16);
    unsigned boff0 = brow * 80 + bkadd;          // n 0-15
    unsigned boff1 = (brow + 16) * 80 + bkadd;   // n 16-31

    for (int cc = 0; cc < NCHUNK; cc++) {
        if (cc < NCHUNK - 2)
            asm volatile("cp.async.wait_group 2;" ::: "memory");
        else if (cc == NCHUNK - 2)
            asm volatile("cp.async.wait_group 1;" ::: "memory");
        else
            asm volatile("cp.async.wait_group 0;" ::: "memory");
        __syncthreads();
        int s = cc & 3;
        unsigned whib = sb + SM_WHI + s * 10240;
        unsigned wlob = sb + SM_WLO + s * 10240;
        unsigned hhib = sb + SM_HHI + s * 2560;
        unsigned hlob = sb + SM_HLO + s * 2560;
#pragma unroll
        for (int k16 = 0; k16 < 2; k16++) {
            unsigned kb = (unsigned)(k16 * 32);
            unsigned ahi[4], alo[4], bh0[4], bh1[4], bl0[4], bl1[4];
            ldsm_x4(whib + aoff + kb, ahi);
            ldsm_x4(wlob + aoff + kb, alo);
            ldsm_x4(hhib + boff0 + kb, bh0);
            ldsm_x4(hhib + boff1 + kb, bh1);
            ldsm_x4(hlob + boff0 + kb, bl0);
            ldsm_x4(hlob + boff1 + kb, bl1);
            // bt0: n0-7 (bh0[0..1]); bt1: n8-15 (bh0[2..3]);
            // bt2: n16-23 (bh1[0..1]); bt3: n24-31 (bh1[2..3])
            MMA_BF16(acc[0], ahi, bh0 + 0);
            MMA_BF16(acc[0], ahi, bl0 + 0);
            MMA_BF16(acc[0], alo, bh0 + 0);
            MMA_BF16(acc[1], ahi, bh0 + 2);
            MMA_BF16(acc[1], ahi, bl0 + 2);
            MMA_BF16(acc[1], alo, bh0 + 2);
            MMA_BF16(acc[2], ahi, bh1 + 0);
            MMA_BF16(acc[2], ahi, bl1 + 0);
            MMA_BF16(acc[2], alo, bh1 + 0);
            MMA_BF16(acc[3], ahi, bh1 + 2);
            MMA_BF16(acc[3], ahi, bl1 + 2);
            MMA_BF16(acc[3], alo, bh1 + 2);
        }
        __syncthreads();
        if (cc + 3 < NCHUNK) stage_chunk(cc + 3);
    }

    // epilogue: bias, streaming stage store, gumbel, argmax
    auto gkey = [&](float logit, int b, int v) -> unsigned long long {
        unsigned o0, o1;
        threefry2x32_dev(key0, key1, 0u, (unsigned)(b * VV + v), o0, o1);
        unsigned bits = o0 ^ o1;
        float u = __uint_as_float(0x3f800000u | (bits >> 9)) - 1.0f;
        u = fmaxf(u + F32_TINY, F32_TINY);
        float g = -logf(-logf(u));
        float val = logit + g;
        return ((unsigned long long)ford(val) << 32) |
               (unsigned long long)(0xFFFFFFFFu - (unsigned)v);
    };

    unsigned long long bk[8];
#pragma unroll
    for (int i = 0; i < 8; i++) bk[i] = 0ull;

    {
        int vlo = v0 + w * 16 + (l >> 2);
        int vhi = vlo + 8;
        float bolo = bout[vlo];
        float bohi = bout[vhi];
#pragma unroll
        for (int bt = 0; bt < 4; bt++) {
            int be = bt * 8 + (l & 3) * 2;
            int bo = be + 1;
            float x0 = acc[bt][0] + bolo;
            float x1 = acc[bt][1] + bolo;
            float x2 = acc[bt][2] + bohi;
            float x3 = acc[bt][3] + bohi;
            stcs(&stage[((size_t)be * TT + t) * VV + vlo], x0);
            stcs(&stage[((size_t)bo * TT + t) * VV + vlo], x1);
            stcs(&stage[((size_t)be * TT + t) * VV + vhi], x2);
            stcs(&stage[((size_t)bo * TT + t) * VV + vhi], x3);
            bk[bt * 2]     = u64max(bk[bt * 2],     u64max(gkey(x0, be, vlo), gkey(x2, be, vhi)));
            bk[bt * 2 + 1] = u64max(bk[bt * 2 + 1], u64max(gkey(x1, bo, vlo), gkey(x3, bo, vhi)));
        }
    }
#pragma unroll
    for (int off = 4; off < 32; off <<= 1)
#pragma unroll
        for (int i = 0; i < 8; i++)
            bk[i] = u64max(bk[i], __shfl_xor_sync(0xffffffffu, bk[i], off));

    unsigned long long* parts = (unsigned long long*)(dsm + SM_PARTS);
    if (l < 4) {
#pragma unroll
        for (int bt = 0; bt < 4; bt++) {
            parts[w * 32 + bt * 8 + l * 2]     = bk[bt * 2];
            parts[w * 32 + bt * 8 + l * 2 + 1] = bk[bt * 2 + 1];
        }
    }
    __syncthreads();
    if (tid < 32) {
        unsigned long long m = 0ull;
#pragma unroll
        for (int wi = 0; wi < 8; wi++) m = u64max(m, parts[wi * 32 + tid]);
        atomicMax(&best[t * BB + tid], m);
    }
}

// ---------------- final: captions ----------------
__global__ void caption_kernel(float* __restrict__ cap_f, int* __restrict__ cap_i) {
    int idx = blockIdx.x * 256 + threadIdx.x;
    int tt = idx & 63;
    int b = idx >> 6;
    int v = decode_tok(g_best[tt * BB + b]);
    if (cap_f) cap_f[b * TT + tt] = (float)v;
    if (cap_i) cap_i[b * TT + tt] = v;
}

// ---------------- final: transpose [b][t][v] -> [b][v][t] ----------------
__global__ __launch_bounds__(256) void transpose_kernel(
    const float* __restrict__ stage, float* __restrict__ out) {
    __shared__ float tile[128][65];
    int b = blockIdx.x / 250;
    int vc = blockIdx.x % 250;
    int v0 = vc * 128;
    const float* src = stage + (size_t)b * TT * VV + v0;
#pragma unroll
    for (int l = 0; l < 32; l++) {
        int e = threadIdx.x + l * 256;
        int tt = e >> 7;
        int vi = e & 127;
        tile[vi][tt] = src[(size_t)tt * VV + vi];
    }
    __syncthreads();
    float* dst = out + ((size_t)b * VV + v0) * TT;
#pragma unroll
    for (int l = 0; l < 32; l++) {
        int e = threadIdx.x + l * 256;
        int vi = e >> 6;
        int tt = e & 63;
        dst[(size_t)vi * TT + tt] = tile[vi][tt];
    }
}

// ---------------- host threefry ----------------
static void host_threefry(unsigned k0, unsigned k1, unsigned x0, unsigned x1,
                          unsigned& o0, unsigned& o1) {
    unsigned ks2 = k0 ^ k1 ^ 0x1BD11BDAu;
    x0 += k0; x1 += k1;
#define HTF_RND(r) { x0 += x1; x1 = (x1 << r) | (x1 >> (32 - r)); x1 ^= x0; }
    HTF_RND(13) HTF_RND(15) HTF_RND(26) HTF_RND(6)  x0 += k1;  x1 += ks2 + 1u;
    HTF_RND(17) HTF_RND(29) HTF_RND(16) HTF_RND(24) x0 += ks2; x1 += k0 + 2u;
    HTF_RND(13) HTF_RND(15) HTF_RND(26) HTF_RND(6)  x0 += k0;  x1 += k1 + 3u;
    HTF_RND(17) HTF_RND(29) HTF_RND(16) HTF_RND(24) x0 += k1;  x1 += ks2 + 4u;
    HTF_RND(13) HTF_RND(15) HTF_RND(26) HTF_RND(6)  x0 += ks2; x1 += k0 + 5u;
#undef HTF_RND
    o0 = x0; o1 = x1;
}

extern "C" void kernel_launch(void* const* d_in, const int* in_sizes, int n_in,
                              void* d_out, int out_size) {
    const float* condition = (const float*)d_in[0];
    const float* Wh    = (const float*)d_in[1];
    const float* bh    = (const float*)d_in[2];
    const float* Wc    = (const float*)d_in[3];
    const float* bc    = (const float*)d_in[4];
    const float* embed = (const float*)d_in[5];
    const float* Wih   = (const float*)d_in[6];
    const float* bih   = (const float*)d_in[7];
    const float* Whh   = (const float*)d_in[8];
    const float* bhh   = (const float*)d_in[9];
    const float* Wout  = (const float*)d_in[10];
    const float* bout  = (const float*)d_in[11];

    float *hA, *hB, *cA, *cB, *stage;
    unsigned long long* best;
    cudaGetSymbolAddress((void**)&hA, g_hA);
    cudaGetSymbolAddress((void**)&hB, g_hB);
    cudaGetSymbolAddress((void**)&cA, g_cA);
    cudaGetSymbolAddress((void**)&cB, g_cB);
    cudaGetSymbolAddress((void**)&stage, g_stage);
    cudaGetSymbolAddress((void**)&best, g_best);

    const long long n_cap = (long long)BB * TT;
    const long long n_log = (long long)BB * VV * TT;
    float* cap_f = nullptr;
    int*   cap_i = nullptr;
    float* log_out = nullptr;
    long long osz = (long long)out_size;
    if (osz == n_cap + n_log) {
        cap_f = (float*)d_out;
        log_out = (float*)d_out + n_cap;
    } else if (osz == n_log) {
        log_out = (float*)d_out;
    } else if (osz == n_cap) {
        cap_i = (int*)d_out;
    } else {
        cap_f = (float*)d_out;
        log_out = (float*)d_out + n_cap;
    }

    cudaFuncSetAttribute(logits_kernel,
                         cudaFuncAttributeMaxDynamicSharedMemorySize, SMEM_LOG);

    convert_kernel<<<VV * HH / 1024, 256>>>(Wout);
    init_kernel<<<128, 256>>>(condition, Wh, bh, Wc, bc, hA, cA);

    float *hcur = hA, *hnxt = hB, *ccur = cA, *cnxt = cB;
    for (int t = 0; t < TT; t++) {
        gather_kernel<<<192, 256>>>(embed, hcur, t);
        dim3 ggrid(HH * 4 / TILEV, SPLITK);
        lstm_gemm_kernel<<<ggrid, 256>>>(Wih, Whh);
        cell_kernel<<<128, 256>>>(bih, bhh, ccur, hnxt, cnxt);
        unsigned o0, o1;
        host_threefry(0u, 42u, 0u, (unsigned)t, o0, o1);
        logits_kernel<<<NBLK_LOG, 256, SMEM_LOG>>>(bout, stage, best, t, o0, o1);
        float* tmp;
        tmp = hcur; hcur = hnxt; hnxt = tmp;
        tmp = ccur; ccur = cnxt; cnxt = tmp;
    }
    caption_kernel<<<8, 256>>>(cap_f, cap_i);
    if (log_out) transpose_kernel<<<8000, 256>>>(stage, log_out);
}

// round 15
// speedup vs baseline: 2.1440x; 1.1198x over previous
#include <cuda_runtime.h>
#include <cuda_bf16.h>
#include <math.h>

#define BB 32
#define EE 512
#define HH 1024
#define VV 32000
#define TT 64
#define START_TOK 1
#define F32_TINY 1.17549435e-38f
#define KTOT 1536
#define SPLITK 8
#define KSEG (KTOT / SPLITK)     // 192
#define LKC 32
#define NCHUNK_L (KSEG / LKC)    // 6
#define NCHUNK (HH / LKC)        // 32
#define NBLK_LOG 250
#define MROWS 4096
// shared smem map for both mma kernels
#define SM_WHI 0                 // 4 stages x 128 rows x 80B
#define SM_WLO 40960
#define SM_HHI 81920             // 4 x 32 x 80B
#define SM_HLO 92160
#define SM_PARTS 102400
#define SMEM_MMA 104448

// ---------------- device scratch ----------------
__device__ __align__(16) float g_c[HH * BB];     // cell state [j][b]
__device__ __align__(16) float g_gpart[SPLITK * MROWS * BB];
__device__ unsigned long long g_best[TT * BB];
__device__ __align__(16) float g_stage[(size_t)BB * TT * VV]; // [b][t][v]
__device__ __align__(16) __nv_bfloat16 g_whi[(size_t)VV * HH]; // Wout hi [v][k]
__device__ __align__(16) __nv_bfloat16 g_wlo[(size_t)VV * HH];
__device__ __align__(16) __nv_bfloat16 g_wl_hi[(size_t)MROWS * KTOT]; // [Wih|Whh]
__device__ __align__(16) __nv_bfloat16 g_wl_lo[(size_t)MROWS * KTOT];
__device__ __align__(16) __nv_bfloat16 g_xh_hi[BB * KTOT];   // [b][k]: x|h
__device__ __align__(16) __nv_bfloat16 g_xh_lo[BB * KTOT];

// ---------------- threefry2x32 (JAX-compatible) ----------------
__device__ __forceinline__ void threefry2x32_dev(unsigned k0, unsigned k1,
                                                 unsigned x0, unsigned x1,
                                                 unsigned& o0, unsigned& o1) {
    unsigned ks2 = k0 ^ k1 ^ 0x1BD11BDAu;
    x0 += k0; x1 += k1;
#define TF_RND(r) { x0 += x1; x1 = __funnelshift_l(x1, x1, r); x1 ^= x0; }
    TF_RND(13) TF_RND(15) TF_RND(26) TF_RND(6)  x0 += k1;  x1 += ks2 + 1u;
    TF_RND(17) TF_RND(29) TF_RND(16) TF_RND(24) x0 += ks2; x1 += k0 + 2u;
    TF_RND(13) TF_RND(15) TF_RND(26) TF_RND(6)  x0 += k0;  x1 += k1 + 3u;
    TF_RND(17) TF_RND(29) TF_RND(16) TF_RND(24) x0 += k1;  x1 += ks2 + 4u;
    TF_RND(13) TF_RND(15) TF_RND(26) TF_RND(6)  x0 += ks2; x1 += k0 + 5u;
#undef TF_RND
    o0 = x0; o1 = x1;
}

__device__ __forceinline__ unsigned ford(float f) {
    unsigned u = __float_as_uint(f);
    return (u & 0x80000000u) ? ~u : (u | 0x80000000u);
}
__device__ __forceinline__ unsigned long long u64max(unsigned long long a,
                                                     unsigned long long b) {
    return a > b ? a : b;
}
__device__ __forceinline__ int decode_tok(unsigned long long key) {
    return (int)(0xFFFFFFFFu - (unsigned)(key & 0xFFFFFFFFull));
}

// ---------------- cp.async / ldsm / streaming-store helpers ----------------
__device__ __forceinline__ void cp_async16(unsigned dst, const void* src) {
    asm volatile("cp.async.cg.shared.global [%0], [%1], 16;"
                 :: "r"(dst), "l"(src) : "memory");
}
__device__ __forceinline__ void cp_commit() {
    asm volatile("cp.async.commit_group;" ::: "memory");
}
__device__ __forceinline__ void ldsm_x4(unsigned addr, unsigned* r) {
    asm volatile("ldmatrix.sync.aligned.m8n8.x4.shared.b16 {%0,%1,%2,%3}, [%4];"
                 : "=r"(r[0]), "=r"(r[1]), "=r"(r[2]), "=r"(r[3]) : "r"(addr));
}
__device__ __forceinline__ void stcs(float* p, float v) {
    asm volatile("st.global.cs.f32 [%0], %1;" :: "l"(p), "f"(v) : "memory");
}
#define MMA_BF16(c, a, b) \
    asm volatile("mma.sync.aligned.m16n8k16.row.col.f32.bf16.bf16.f32 " \
        "{%0,%1,%2,%3}, {%4,%5,%6,%7}, {%8,%9}, {%0,%1,%2,%3};" \
        : "+f"((c)[0]), "+f"((c)[1]), "+f"((c)[2]), "+f"((c)[3]) \
        : "r"((a)[0]), "r"((a)[1]), "r"((a)[2]), "r"((a)[3]), \
          "r"((b)[0]), "r"((b)[1]))

// ---------------- converts ----------------
__global__ __launch_bounds__(256) void convert_kernel(const float* __restrict__ W) {
    size_t i = ((size_t)blockIdx.x * 256 + threadIdx.x) * 4;
    float4 w = *(const float4*)(W + i);
    __nv_bfloat16 h0 = __float2bfloat16(w.x);
    __nv_bfloat16 h1 = __float2bfloat16(w.y);
    __nv_bfloat16 h2 = __float2bfloat16(w.z);
    __nv_bfloat16 h3 = __float2bfloat16(w.w);
    __nv_bfloat162 a, b, c, d;
    a.x = h0; a.y = h1; b.x = h2; b.y = h3;
    c.x = __float2bfloat16(w.x - __bfloat162float(h0));
    c.y = __float2bfloat16(w.y - __bfloat162float(h1));
    d.x = __float2bfloat16(w.z - __bfloat162float(h2));
    d.y = __float2bfloat16(w.w - __bfloat162float(h3));
    *(__nv_bfloat162*)(g_whi + i) = a;
    *(__nv_bfloat162*)(g_whi + i + 2) = b;
    *(__nv_bfloat162*)(g_wlo + i) = c;
    *(__nv_bfloat162*)(g_wlo + i + 2) = d;
}

// fuse Wih/Whh into gate-major [4096][1536] bf16 hi/lo
__global__ __launch_bounds__(256) void convert_lstm_kernel(
    const float* __restrict__ src, int srcw, int dstoff) {
    size_t i = ((size_t)blockIdx.x * 256 + threadIdx.x) * 4;
    int r = (int)(i / srcw);
    int k = (int)(i % srcw);
    float4 w = *(const float4*)(src + i);
    size_t o = (size_t)r * KTOT + dstoff + k;
    __nv_bfloat16 h0 = __float2bfloat16(w.x);
    __nv_bfloat16 h1 = __float2bfloat16(w.y);
    __nv_bfloat16 h2 = __float2bfloat16(w.z);
    __nv_bfloat16 h3 = __float2bfloat16(w.w);
    __nv_bfloat162 a, b, c, d;
    a.x = h0; a.y = h1; b.x = h2; b.y = h3;
    c.x = __float2bfloat16(w.x - __bfloat162float(h0));
    c.y = __float2bfloat16(w.y - __bfloat162float(h1));
    d.x = __float2bfloat16(w.z - __bfloat162float(h2));
    d.y = __float2bfloat16(w.w - __bfloat162float(h3));
    *(__nv_bfloat162*)(g_wl_hi + o) = a;
    *(__nv_bfloat162*)(g_wl_hi + o + 2) = b;
    *(__nv_bfloat162*)(g_wl_lo + o) = c;
    *(__nv_bfloat162*)(g_wl_lo + o + 2) = d;
}

// ---------------- K0: h0/c0 from condition ----------------
__global__ __launch_bounds__(256) void init_kernel(
    const float* __restrict__ cond, const float* __restrict__ Wh,
    const float* __restrict__ bh,   const float* __restrict__ Wc,
    const float* __restrict__ bc) {
    int j = blockIdx.x * 8 + (threadIdx.x >> 5);
    int lane = threadIdx.x & 31;
    if (blockIdx.x < 8) {
        int idx = blockIdx.x * 256 + threadIdx.x;
        if (idx < TT * BB) g_best[idx] = 0ull;
    }
    const float* cr = cond + (size_t)lane * EE;
    const float* wh = Wh + (size_t)j * EE;
    const float* wc = Wc + (size_t)j * EE;
    float ah = bh[j], ac = bc[j];
#pragma unroll 4
    for (int k = 0; k < EE; k += 4) {
        float4 c4 = *(const float4*)(cr + k);
        float4 h4 = *(const float4*)(wh + k);
        float4 q4 = *(const float4*)(wc + k);
        ah = fmaf(c4.x, h4.x, ah); ah = fmaf(c4.y, h4.y, ah);
        ah = fmaf(c4.z, h4.z, ah); ah = fmaf(c4.w, h4.w, ah);
        ac = fmaf(c4.x, q4.x, ac); ac = fmaf(c4.y, q4.y, ac);
        ac = fmaf(c4.z, q4.z, ac); ac = fmaf(c4.w, q4.w, ac);
    }
    g_c[j * BB + lane] = ac;
    __nv_bfloat16 hi = __float2bfloat16(ah);
    g_xh_hi[lane * KTOT + EE + j] = hi;
    g_xh_lo[lane * KTOT + EE + j] = __float2bfloat16(ah - __bfloat162float(hi));
}

// ---------------- K-gather: embed(tok) -> xh bf16 hi/lo ----------------
__global__ __launch_bounds__(256) void gather_kernel(
    const float* __restrict__ embed, int t) {
    int idx = blockIdx.x * 256 + threadIdx.x;  // 0..16383
    int b = idx & 31;
    int k = idx >> 5;
    int tok = START_TOK;
    if (t > 0) tok = decode_tok(g_best[(t - 1) * BB + b]);
    float val = embed[(size_t)tok * EE + k];
    __nv_bfloat16 hi = __float2bfloat16(val);
    g_xh_hi[b * KTOT + k] = hi;
    g_xh_lo[b * KTOT + k] = __float2bfloat16(val - __bfloat162float(hi));
}

// ---------------- K1a: lstm gate GEMM via mma.sync bf16 hi/lo --------------
// grid (32, SPLITK). Block: 128 gate-major rows; 256 thr, 8 warps (m16/warp).
__global__ __launch_bounds__(256) void lstm_mma_kernel() {
    extern __shared__ __align__(16) char dsm[];
    unsigned sb = (unsigned)__cvta_generic_to_shared(dsm);
    int tid = threadIdx.x;
    int l = tid & 31;
    int w = tid >> 5;
    int m0 = blockIdx.x * 128;
    int seg = blockIdx.y;
    int k0seg = seg * KSEG;

    auto stage_chunk = [&](int c) {
        int s = c & 3;
        int kc = k0seg + c * LKC;
        int srow = tid >> 1;
        int shalf = (tid & 1) * 32;
        const __nv_bfloat16* shi = g_wl_hi + (size_t)(m0 + srow) * KTOT + kc + (tid & 1) * 16;
        const __nv_bfloat16* slo = g_wl_lo + (size_t)(m0 + srow) * KTOT + kc + (tid & 1) * 16;
        unsigned dhi = sb + SM_WHI + s * 10240 + srow * 80 + shalf;
        unsigned dlo = sb + SM_WLO + s * 10240 + srow * 80 + shalf;
        cp_async16(dhi, shi);
        cp_async16(dhi + 16, shi + 8);
        cp_async16(dlo, slo);
        cp_async16(dlo + 16, slo + 8);
        if (tid < 128) {
            int hr = tid >> 2, hi_ = tid & 3;
            cp_async16(sb + SM_HHI + s * 2560 + hr * 80 + hi_ * 16,
                       g_xh_hi + (size_t)hr * KTOT + kc + hi_ * 8);
            cp_async16(sb + SM_HLO + s * 2560 + hr * 80 + hi_ * 16,
                       g_xh_lo + (size_t)hr * KTOT + kc + hi_ * 8);
        }
        cp_commit();
    };

    stage_chunk(0); stage_chunk(1); stage_chunk(2);

    float acc[4][4];
#pragma unroll
    for (int bt = 0; bt < 4; bt++)
#pragma unroll
        for (int i = 0; i < 4; i++) acc[bt][i] = 0.f;

    unsigned aoff = (unsigned)((w * 16 + (l & 15)) * 80 + (l >> 4) * 16);
    unsigned brow = (unsigned)(((l >> 4) * 8) + (l & 7));
    unsigned bkadd = (unsigned)(((l >> 3) & 1) * 16);
    unsigned boff0 = brow * 80 + bkadd;
    unsigned boff1 = (brow + 16) * 80 + bkadd;

    for (int cc = 0; cc < NCHUNK_L; cc++) {
        if (cc < NCHUNK_L - 2)
            asm volatile("cp.async.wait_group 2;" ::: "memory");
        else if (cc == NCHUNK_L - 2)
            asm volatile("cp.async.wait_group 1;" ::: "memory");
        else
            asm volatile("cp.async.wait_group 0;" ::: "memory");
        __syncthreads();
        int s = cc & 3;
        unsigned whib = sb + SM_WHI + s * 10240;
        unsigned wlob = sb + SM_WLO + s * 10240;
        unsigned hhib = sb + SM_HHI + s * 2560;
        unsigned hlob = sb + SM_HLO + s * 2560;
#pragma unroll
        for (int k16 = 0; k16 < 2; k16++) {
            unsigned kb = (unsigned)(k16 * 32);
            unsigned ahi[4], alo[4], bh0[4], bh1[4], bl0[4], bl1[4];
            ldsm_x4(whib + aoff + kb, ahi);
            ldsm_x4(wlob + aoff + kb, alo);
            ldsm_x4(hhib + boff0 + kb, bh0);
            ldsm_x4(hhib + boff1 + kb, bh1);
            ldsm_x4(hlob + boff0 + kb, bl0);
            ldsm_x4(hlob + boff1 + kb, bl1);
            MMA_BF16(acc[0], ahi, bh0 + 0);
            MMA_BF16(acc[0], ahi, bl0 + 0);
            MMA_BF16(acc[0], alo, bh0 + 0);
            MMA_BF16(acc[1], ahi, bh0 + 2);
            MMA_BF16(acc[1], ahi, bl0 + 2);
            MMA_BF16(acc[1], alo, bh0 + 2);
            MMA_BF16(acc[2], ahi, bh1 + 0);
            MMA_BF16(acc[2], ahi, bl1 + 0);
            MMA_BF16(acc[2], alo, bh1 + 0);
            MMA_BF16(acc[3], ahi, bh1 + 2);
            MMA_BF16(acc[3], ahi, bl1 + 2);
            MMA_BF16(acc[3], alo, bh1 + 2);
        }
        __syncthreads();
        if (cc + 3 < NCHUNK_L) stage_chunk(cc + 3);
    }

    // scatter partials to g_gpart[seg][r][b]
    float* part = g_gpart + (size_t)seg * MROWS * BB;
    int rlo = m0 + w * 16 + (l >> 2);
    int rhi = rlo + 8;
#pragma unroll
    for (int bt = 0; bt < 4; bt++) {
        int be = bt * 8 + (l & 3) * 2;
        int bo = be + 1;
        part[rlo * BB + be] = acc[bt][0];
        part[rlo * BB + bo] = acc[bt][1];
        part[rhi * BB + be] = acc[bt][2];
        part[rhi * BB + bo] = acc[bt][3];
    }
}

// ---------------- K1b: combine partials + cell + h bf16 split ---------------
__global__ __launch_bounds__(256) void cell_kernel(
    const float* __restrict__ bih, const float* __restrict__ bhh) {
    int idx = blockIdx.x * 256 + threadIdx.x;
    int b = idx & 31;
    int j = idx >> 5;
    float a[4] = {0.f, 0.f, 0.f, 0.f};
#pragma unroll
    for (int seg = 0; seg < SPLITK; seg++) {
        const float* part = g_gpart + (size_t)seg * MROWS * BB;
#pragma unroll
        for (int gate = 0; gate < 4; gate++)
            a[gate] += part[(size_t)(gate * HH + j) * BB + b];
    }
#pragma unroll
    for (int gate = 0; gate < 4; gate++) {
        int r = gate * HH + j;
        a[gate] += bih[r] + bhh[r];
    }
    float ig = 1.0f / (1.0f + expf(-a[0]));
    float fg = 1.0f / (1.0f + expf(-a[1]));
    float gg = tanhf(a[2]);
    float og = 1.0f / (1.0f + expf(-a[3]));
    float c = fg * g_c[j * BB + b] + ig * gg;
    float h = og * tanhf(c);
    g_c[j * BB + b] = c;
    __nv_bfloat16 hi = __float2bfloat16(h);
    g_xh_hi[b * KTOT + EE + j] = hi;
    g_xh_lo[b * KTOT + EE + j] = __float2bfloat16(h - __bfloat162float(hi));
}

// ---------------- K2: logits via mma.sync bf16 hi/lo, ldmatrix frags -------
__global__ __launch_bounds__(256) void logits_kernel(
    const float* __restrict__ bout, float* __restrict__ stage,
    unsigned long long* __restrict__ best, int t, unsigned key0, unsigned key1) {
    extern __shared__ __align__(16) char dsm[];
    unsigned sb = (unsigned)__cvta_generic_to_shared(dsm);
    int tid = threadIdx.x;
    int l = tid & 31;
    int w = tid >> 5;
    int bid = blockIdx.x;
    if (t & 1) bid = NBLK_LOG - 1 - bid;
    int v0 = bid * 128;

    auto stage_chunk = [&](int c) {
        int s = c & 3;
        int cc2 = (t & 1) ? (NCHUNK - 1 - c) : c;
        int kc = cc2 * LKC;
        int srow = tid >> 1;
        int shalf = (tid & 1) * 32;
        const __nv_bfloat16* shi = g_whi + (size_t)(v0 + srow) * HH + kc + (tid & 1) * 16;
        const __nv_bfloat16* slo = g_wlo + (size_t)(v0 + srow) * HH + kc + (tid & 1) * 16;
        unsigned dhi = sb + SM_WHI + s * 10240 + srow * 80 + shalf;
        unsigned dlo = sb + SM_WLO + s * 10240 + srow * 80 + shalf;
        cp_async16(dhi, shi);
        cp_async16(dhi + 16, shi + 8);
        cp_async16(dlo, slo);
        cp_async16(dlo + 16, slo + 8);
        if (tid < 128) {
            int hr = tid >> 2, hi_ = tid & 3;
            cp_async16(sb + SM_HHI + s * 2560 + hr * 80 + hi_ * 16,
                       g_xh_hi + (size_t)hr * KTOT + EE + kc + hi_ * 8);
            cp_async16(sb + SM_HLO + s * 2560 + hr * 80 + hi_ * 16,
                       g_xh_lo + (size_t)hr * KTOT + EE + kc + hi_ * 8);
        }
        cp_commit();
    };

    stage_chunk(0); stage_chunk(1); stage_chunk(2);

    float acc[4][4];
#pragma unroll
    for (int bt = 0; bt < 4; bt++)
#pragma unroll
        for (int i = 0; i < 4; i++) acc[bt][i] = 0.f;

    unsigned aoff = (unsigned)((w * 16 + (l & 15)) * 80 + (l >> 4) * 16);
    unsigned brow = (unsigned)(((l >> 4) * 8) + (l & 7));
    unsigned bkadd = (unsigned)(((l >> 3) & 1) * 16);
    unsigned boff0 = brow * 80 + bkadd;
    unsigned boff1 = (brow + 16) * 80 + bkadd;

    for (int cc = 0; cc < NCHUNK; cc++) {
        if (cc < NCHUNK - 2)
            asm volatile("cp.async.wait_group 2;" ::: "memory");
        else if (cc == NCHUNK - 2)
            asm volatile("cp.async.wait_group 1;" ::: "memory");
        else
            asm volatile("cp.async.wait_group 0;" ::: "memory");
        __syncthreads();
        int s = cc & 3;
        unsigned whib = sb + SM_WHI + s * 10240;
        unsigned wlob = sb + SM_WLO + s * 10240;
        unsigned hhib = sb + SM_HHI + s * 2560;
        unsigned hlob = sb + SM_HLO + s * 2560;
#pragma unroll
        for (int k16 = 0; k16 < 2; k16++) {
            unsigned kb = (unsigned)(k16 * 32);
            unsigned ahi[4], alo[4], bh0[4], bh1[4], bl0[4], bl1[4];
            ldsm_x4(whib + aoff + kb, ahi);
            ldsm_x4(wlob + aoff + kb, alo);
            ldsm_x4(hhib + boff0 + kb, bh0);
            ldsm_x4(hhib + boff1 + kb, bh1);
            ldsm_x4(hlob + boff0 + kb, bl0);
            ldsm_x4(hlob + boff1 + kb, bl1);
            MMA_BF16(acc[0], ahi, bh0 + 0);
            MMA_BF16(acc[0], ahi, bl0 + 0);
            MMA_BF16(acc[0], alo, bh0 + 0);
            MMA_BF16(acc[1], ahi, bh0 + 2);
            MMA_BF16(acc[1], ahi, bl0 + 2);
            MMA_BF16(acc[1], alo, bh0 + 2);
            MMA_BF16(acc[2], ahi, bh1 + 0);
            MMA_BF16(acc[2], ahi, bl1 + 0);
            MMA_BF16(acc[2], alo, bh1 + 0);
            MMA_BF16(acc[3], ahi, bh1 + 2);
            MMA_BF16(acc[3], ahi, bl1 + 2);
            MMA_BF16(acc[3], alo, bh1 + 2);
        }
        __syncthreads();
        if (cc + 3 < NCHUNK) stage_chunk(cc + 3);
    }

    auto gkey = [&](float logit, int b, int v) -> unsigned long long {
        unsigned o0, o1;
        threefry2x32_dev(key0, key1, 0u, (unsigned)(b * VV + v), o0, o1);
        unsigned bits = o0 ^ o1;
        float u = __uint_as_float(0x3f800000u | (bits >> 9)) - 1.0f;
        u = fmaxf(u + F32_TINY, F32_TINY);
        float g = -logf(-logf(u));
        float val = logit + g;
        return ((unsigned long long)ford(val) << 32) |
               (unsigned long long)(0xFFFFFFFFu - (unsigned)v);
    };

    unsigned long long bk[8];
#pragma unroll
    for (int i = 0; i < 8; i++) bk[i] = 0ull;

    {
        int vlo = v0 + w * 16 + (l >> 2);
        int vhi = vlo + 8;
        float bolo = bout[vlo];
        float bohi = bout[vhi];
#pragma unroll
        for (int bt = 0; bt < 4; bt++) {
            int be = bt * 8 + (l & 3) * 2;
            int bo = be + 1;
            float x0 = acc[bt][0] + bolo;
            float x1 = acc[bt][1] + bolo;
            float x2 = acc[bt][2] + bohi;
            float x3 = acc[bt][3] + bohi;
            stcs(&stage[((size_t)be * TT + t) * VV + vlo], x0);
            stcs(&stage[((size_t)bo * TT + t) * VV + vlo], x1);
            stcs(&stage[((size_t)be * TT + t) * VV + vhi], x2);
            stcs(&stage[((size_t)bo * TT + t) * VV + vhi], x3);
            bk[bt * 2]     = u64max(bk[bt * 2],     u64max(gkey(x0, be, vlo), gkey(x2, be, vhi)));
            bk[bt * 2 + 1] = u64max(bk[bt * 2 + 1], u64max(gkey(x1, bo, vlo), gkey(x3, bo, vhi)));
        }
    }
#pragma unroll
    for (int off = 4; off < 32; off <<= 1)
#pragma unroll
        for (int i = 0; i < 8; i++)
            bk[i] = u64max(bk[i], __shfl_xor_sync(0xffffffffu, bk[i], off));

    unsigned long long* parts = (unsigned long long*)(dsm + SM_PARTS);
    if (l < 4) {
#pragma unroll
        for (int bt = 0; bt < 4; bt++) {
            parts[w * 32 + bt * 8 + l * 2]     = bk[bt * 2];
            parts[w * 32 + bt * 8 + l * 2 + 1] = bk[bt * 2 + 1];
        }
    }
    __syncthreads();
    if (tid < 32) {
        unsigned long long m = 0ull;
#pragma unroll
        for (int wi = 0; wi < 8; wi++) m = u64max(m, parts[wi * 32 + tid]);
        atomicMax(&best[t * BB + tid], m);
    }
}

// ---------------- final: captions ----------------
__global__ void caption_kernel(float* __restrict__ cap_f, int* __restrict__ cap_i) {
    int idx = blockIdx.x * 256 + threadIdx.x;
    int tt = idx & 63;
    int b = idx >> 6;
    int v = decode_tok(g_best[tt * BB + b]);
    if (cap_f) cap_f[b * TT + tt] = (float)v;
    if (cap_i) cap_i[b * TT + tt] = v;
}

// ---------------- final: transpose [b][t][v] -> [b][v][t] ----------------
__global__ __launch_bounds__(256) void transpose_kernel(
    const float* __restrict__ stage, float* __restrict__ out) {
    __shared__ float tile[128][65];
    int b = blockIdx.x / 250;
    int vc = blockIdx.x % 250;
    int v0 = vc * 128;
    const float* src = stage + (size_t)b * TT * VV + v0;
#pragma unroll
    for (int l = 0; l < 32; l++) {
        int e = threadIdx.x + l * 256;
        int tt = e >> 7;
        int vi = e & 127;
        tile[vi][tt] = src[(size_t)tt * VV + vi];
    }
    __syncthreads();
    float* dst = out + ((size_t)b * VV + v0) * TT;
#pragma unroll
    for (int l = 0; l < 32; l++) {
        int e = threadIdx.x + l * 256;
        int vi = e >> 6;
        int tt = e & 63;
        dst[(size_t)vi * TT + tt] = tile[vi][tt];
    }
}

// ---------------- host threefry ----------------
static void host_threefry(unsigned k0, unsigned k1, unsigned x0, unsigned x1,
                          unsigned& o0, unsigned& o1) {
    unsigned ks2 = k0 ^ k1 ^ 0x1BD11BDAu;
    x0 += k0; x1 += k1;
#define HTF_RND(r) { x0 += x1; x1 = (x1 << r) | (x1 >> (32 - r)); x1 ^= x0; }
    HTF_RND(13) HTF_RND(15) HTF_RND(26) HTF_RND(6)  x0 += k1;  x1 += ks2 + 1u;
    HTF_RND(17) HTF_RND(29) HTF_RND(16) HTF_RND(24) x0 += ks2; x1 += k0 + 2u;
    HTF_RND(13) HTF_RND(15) HTF_RND(26) HTF_RND(6)  x0 += k0;  x1 += k1 + 3u;
    HTF_RND(17) HTF_RND(29) HTF_RND(16) HTF_RND(24) x0 += k1;  x1 += ks2 + 4u;
    HTF_RND(13) HTF_RND(15) HTF_RND(26) HTF_RND(6)  x0 += ks2; x1 += k0 + 5u;
#undef HTF_RND
    o0 = x0; o1 = x1;
}

extern "C" void kernel_launch(void* const* d_in, const int* in_sizes, int n_in,
                              void* d_out, int out_size) {
    const float* condition = (const float*)d_in[0];
    const float* Wh    = (const float*)d_in[1];
    const float* bh    = (const float*)d_in[2];
    const float* Wc    = (const float*)d_in[3];
    const float* bc    = (const float*)d_in[4];
    const float* embed = (const float*)d_in[5];
    const float* Wih   = (const float*)d_in[6];
    const float* bih   = (const float*)d_in[7];
    const float* Whh   = (const float*)d_in[8];
    const float* bhh   = (const float*)d_in[9];
    const float* Wout  = (const float*)d_in[10];
    const float* bout  = (const float*)d_in[11];

    float* stage;
    unsigned long long* best;
    cudaGetSymbolAddress((void**)&stage, g_stage);
    cudaGetSymbolAddress((void**)&best, g_best);

    const long long n_cap = (long long)BB * TT;
    const long long n_log = (long long)BB * VV * TT;
    float* cap_f = nullptr;
    int*   cap_i = nullptr;
    float* log_out = nullptr;
    long long osz = (long long)out_size;
    if (osz == n_cap + n_log) {
        cap_f = (float*)d_out;
        log_out = (float*)d_out + n_cap;
    } else if (osz == n_log) {
        log_out = (float*)d_out;
    } else if (osz == n_cap) {
        cap_i = (int*)d_out;
    } else {
        cap_f = (float*)d_out;
        log_out = (float*)d_out + n_cap;
    }

    cudaFuncSetAttribute(logits_kernel,
                         cudaFuncAttributeMaxDynamicSharedMemorySize, SMEM_MMA);
    cudaFuncSetAttribute(lstm_mma_kernel,
                         cudaFuncAttributeMaxDynamicSharedMemorySize, SMEM_MMA);

    convert_kernel<<<VV * HH / 1024, 256>>>(Wout);
    convert_lstm_kernel<<<MROWS * EE / 1024, 256>>>(Wih, EE, 0);
    convert_lstm_kernel<<<MROWS * HH / 1024, 256>>>(Whh, HH, EE);
    init_kernel<<<128, 256>>>(condition, Wh, bh, Wc, bc);

    for (int t = 0; t < TT; t++) {
        gather_kernel<<<64, 256>>>(embed, t);
        dim3 ggrid(MROWS / 128, SPLITK);
        lstm_mma_kernel<<<ggrid, 256, SMEM_MMA>>>();
        cell_kernel<<<128, 256>>>(bih, bhh);
        unsigned o0, o1;
        host_threefry(0u, 42u, 0u, (unsigned)t, o0, o1);
        logits_kernel<<<NBLK_LOG, 256, SMEM_MMA>>>(bout, stage, best, t, o0, o1);
    }
    caption_kernel<<<8, 256>>>(cap_f, cap_i);
    if (log_out) transpose_kernel<<<8000, 256>>>(stage, log_out);
}